// round 10
// baseline (speedup 1.0000x reference)
#include <cuda_runtime.h>
#include <cuda_bf16.h>
#include <cstdint>

#define EPS 1e-5f

// ---------------- scratch (static __device__ — no allocation) ----------------
// conv2..6 weights, bf16-split u2 layout: [b][chunk(CINPAD/16)][tap(25)][kpair(8)][COUT]
__device__ uint2 g_k2[16 * 1 * 25 * 8 * 16];
__device__ uint2 g_k3[16 * 1 * 25 * 8 * 32];
__device__ uint2 g_k4[16 * 2 * 25 * 8 * 32];
__device__ uint2 g_k5[16 * 2 * 25 * 8 * 64];
__device__ uint2 g_k6[16 * 4 * 25 * 8 * 64];
// conv1 k8 weights: [b][tap][cout][pass(2)] of uint4 (4 u32 = k-pairs per tg)
__device__ uint4 g_c1[16 * 25 * 16 * 2];
__device__ float g_k7[16 * 4 * 64];

__device__ float g_t1[16 * 16 * 256 * 256];
__device__ float g_t2[16 * 16 * 256 * 256];
__device__ float g_t3[16 * 16 * 128 * 128];
__device__ float g_t4[16 * 32 * 128 * 128];
__device__ float g_t5[16 * 32 * 128 * 128];
__device__ float g_t6[16 * 64 * 128 * 128];
__device__ float g_t7[16 * 64 * 128 * 128];
__device__ float g_t8[16 * 4 * 128 * 128];

__device__ float g_aff[7 * 16 * 64 * 2];  // BN affine [layer][b*C+c][2]
__device__ float g_st[6 * 16 * 64 * 2];   // fused stats [layer][b][64][2] (sum, sumsq)

// ---------------- helpers ----------------
__device__ __forceinline__ uint32_t packbf(float a, float b) {
    __nv_bfloat162 h;
    h.x = __float2bfloat16(a);
    h.y = __float2bfloat16(b);
    return *reinterpret_cast<uint32_t*>(&h);
}

__device__ __forceinline__ uint2 bsplit2(float v0, float v1) {
    __nv_bfloat16 h0 = __float2bfloat16(v0);
    __nv_bfloat16 h1 = __float2bfloat16(v1);
    float l0 = v0 - __bfloat162float(h0);
    float l1 = v1 - __bfloat162float(h1);
    uint2 u;
    u.x = packbf(v0, v1);  // hi parts (packbf rounds to nearest = hi)
    u.y = packbf(l0, l1);
    return u;
}

__device__ __forceinline__ void mma_bf16(float c[4], uint32_t a0, uint32_t a1, uint32_t a2,
                                         uint32_t a3, uint32_t b0, uint32_t b1) {
    asm volatile(
        "mma.sync.aligned.m16n8k16.row.col.f32.bf16.bf16.f32 "
        "{%0,%1,%2,%3},{%4,%5,%6,%7},{%8,%9},{%0,%1,%2,%3};"
        : "+f"(c[0]), "+f"(c[1]), "+f"(c[2]), "+f"(c[3])
        : "r"(a0), "r"(a1), "r"(a2), "r"(a3), "r"(b0), "r"(b1));
}

__device__ __forceinline__ void mma_bf16_k8(float c[4], uint32_t a0, uint32_t a1, uint32_t b0) {
    asm volatile(
        "mma.sync.aligned.m16n8k8.row.col.f32.bf16.bf16.f32 "
        "{%0,%1,%2,%3},{%4,%5},{%6},{%0,%1,%2,%3};"
        : "+f"(c[0]), "+f"(c[1]), "+f"(c[2]), "+f"(c[3])
        : "r"(a0), "r"(a1), "r"(b0));
}

// ---------------- weight generation (merged: 2 launches) ----------------
__device__ __forceinline__ void gen_one(const float* __restrict__ w, const float* __restrict__ bias,
                                        const int* __restrict__ action, uint2* __restrict__ out,
                                        int CIN, int NCH, int COUT, int i) {
    int co = i % COUT;
    int r = i / COUT;
    int kp = r % 8;
    r /= 8;
    int tap = r % 25;
    r /= 25;
    int chv = r % NCH;
    int b = r / NCH;
    int a = action[b];
    int ci0 = chv * 16 + kp * 2;
    float v0 = 0.f, v1 = 0.f;
    if (ci0 < CIN) {
        int o = (co * CIN + ci0) * 25 + tap;
        v0 = w[o * 6 + a] + bias[o];
    }
    if (ci0 + 1 < CIN) {
        int o = (co * CIN + ci0 + 1) * 25 + tap;
        v1 = w[o * 6 + a] + bias[o];
    }
    out[i] = bsplit2(v0, v1);
}

__global__ void genA_kernel(const float* w2, const float* b2, const float* w3, const float* b3,
                            const float* w4, const float* b4, const float* w5, const float* b5,
                            const int* __restrict__ action, uint2* k2, uint2* k3, uint2* k4,
                            uint2* k5, float* st) {
    int i = blockIdx.x * 256 + threadIdx.x;
    if (i < 6 * 16 * 64 * 2) st[i] = 0.f;
    if (i < 51200) gen_one(w2, b2, action, k2, 16, 1, 16, i);
    else if (i < 153600) gen_one(w3, b3, action, k3, 16, 1, 32, i - 51200);
    else if (i < 358400) gen_one(w4, b4, action, k4, 32, 2, 32, i - 153600);
    else if (i < 768000) gen_one(w5, b5, action, k5, 32, 2, 64, i - 358400);
}

__global__ void genB_kernel(const float* w6, const float* b6, const float* w1, const float* b1,
                            const float* w7, const float* b7, const int* __restrict__ action,
                            uint2* k6, uint4* c1, float* k7) {
    int i = blockIdx.x * 256 + threadIdx.x;
    if (i < 819200) {
        gen_one(w6, b6, action, k6, 64, 4, 64, i);
    } else if (i < 819200 + 12800) {
        int j = i - 819200;  // [b][tap][co][pass]
        int pass = j & 1;
        int r = j >> 1;
        int co = r & 15;
        r >>= 4;
        int tap = r % 25;
        int b = r / 25;
        int a = action[b];
        float h[4], l[4];
#pragma unroll
        for (int ci = 0; ci < 4; ci++) {
            int o = (co * 4 + ci) * 25 + tap;
            float v = w1[o * 6 + a] + b1[o];
            __nv_bfloat16 hb = __float2bfloat16(v);
            h[ci] = v;  // packbf rounds
            l[ci] = v - __bfloat162float(hb);
        }
        uint4 u;
        if (pass == 0) {
            u.x = packbf(h[0], h[1]);
            u.y = packbf(h[2], h[3]);
            u.z = u.x;
            u.w = u.y;
        } else {
            u.x = packbf(l[0], l[1]);
            u.y = packbf(l[2], l[3]);
            u.z = 0;
            u.w = 0;
        }
        c1[j] = u;
    } else if (i < 819200 + 12800 + 4096) {
        int j = i - 819200 - 12800;
        int b = j / 256, o = j - b * 256;
        k7[j] = w7[o * 6 + action[b]] + b7[o];
    }
}

// ---------------- bn0 stats (input x only) ----------------
template <int N>
__global__ void stats_kernel(const float* __restrict__ in, const float* __restrict__ s,
                             const float* __restrict__ bb, float* __restrict__ aff, int C) {
    int bc = blockIdx.x;
    const float* p = in + (size_t)bc * N;
    float sum = 0.f, sq = 0.f;
    for (int i = threadIdx.x; i < N; i += 256) {
        float v = p[i];
        sum += v;
        sq += v * v;
    }
    __shared__ float ssum[256], ssq[256];
    ssum[threadIdx.x] = sum;
    ssq[threadIdx.x] = sq;
    __syncthreads();
    for (int st = 128; st > 0; st >>= 1) {
        if (threadIdx.x < st) {
            ssum[threadIdx.x] += ssum[threadIdx.x + st];
            ssq[threadIdx.x] += ssq[threadIdx.x + st];
        }
        __syncthreads();
    }
    if (threadIdx.x == 0) {
        int c = bc % C;
        float mean = ssum[0] / (float)N;
        float var = ssq[0] / (float)N - mean * mean;
        float sc = rsqrtf(var + EPS) * s[c];
        aff[2 * bc] = sc;
        aff[2 * bc + 1] = bb[c] - mean * sc;
    }
}

// ---------------- finalize fused stats -> affine ----------------
__global__ void fin_kernel(const float* __restrict__ st, const float* __restrict__ s,
                           const float* __restrict__ bb, float* __restrict__ aff, int C,
                           float invN) {
    int i = threadIdx.x;
    if (i >= C * 16) return;
    int b = i / C, c = i - b * C;
    float sum = st[(b * 64 + c) * 2];
    float sq = st[(b * 64 + c) * 2 + 1];
    float mean = sum * invN;
    float var = sq * invN - mean * mean;
    float sc = rsqrtf(var + EPS) * s[c];
    aff[2 * (b * C + c)] = sc;
    aff[2 * (b * C + c) + 1] = bb[c] - mean * sc;
}

// ---------------- conv1: CIN=4, k8 two-pass (A=[4hi|4lo]) ----------------
__global__ __launch_bounds__(256) void conv1_k8_kernel(const float* __restrict__ in,
                                                       const float* __restrict__ aff,
                                                       const uint4* __restrict__ wts,
                                                       float* __restrict__ out,
                                                       float* __restrict__ st) {
    const int H = 256, PX = 40, R = 4;
    __shared__ uint4 patch[16 * 40];
    __shared__ uint4 wt[25 * 16 * 2];

    int tid = threadIdx.x, wid = tid >> 5, lane = tid & 31;
    int tg = lane & 3, gid = lane >> 2;
    int bx0 = blockIdx.x * 32, by0 = blockIdx.y * 8, b = blockIdx.z;

    const float* inb = in + (size_t)b * 4 * H * H;
    float s0 = aff[b * 8], bi0 = aff[b * 8 + 1];
    float s1 = aff[b * 8 + 2], bi1 = aff[b * 8 + 3];
    float s2 = aff[b * 8 + 4], bi2 = aff[b * 8 + 5];
    float s3 = aff[b * 8 + 6], bi3 = aff[b * 8 + 7];

    for (int idx = tid; idx < 16 * 40; idx += 256) {
        int py = idx / 40, px = idx - py * 40;
        int gy = by0 - R + py, gx = bx0 - R + px;
        float v0 = 0.f, v1 = 0.f, v2 = 0.f, v3 = 0.f;
        if ((unsigned)gy < 256u && (unsigned)gx < 256u) {
            size_t p0 = (size_t)gy * 256 + gx;
            v0 = fmaf(inb[p0], s0, bi0);
            v1 = fmaf(inb[p0 + 65536], s1, bi1);
            v2 = fmaf(inb[p0 + 131072], s2, bi2);
            v3 = fmaf(inb[p0 + 196608], s3, bi3);
        }
        __nv_bfloat16 h0 = __float2bfloat16(v0), h1 = __float2bfloat16(v1);
        __nv_bfloat16 h2 = __float2bfloat16(v2), h3 = __float2bfloat16(v3);
        uint4 u;
        u.x = packbf(v0, v1);
        u.y = packbf(v2, v3);
        u.z = packbf(v0 - __bfloat162float(h0), v1 - __bfloat162float(h1));
        u.w = packbf(v2 - __bfloat162float(h2), v3 - __bfloat162float(h3));
        patch[idx] = u;
    }
    const uint4* wb = wts + (size_t)b * 800;
    for (int idx = tid; idx < 800; idx += 256) wt[idx] = wb[idx];
    __syncthreads();

    float acc[2][2][4];
#pragma unroll
    for (int mt = 0; mt < 2; mt++)
#pragma unroll
        for (int nt = 0; nt < 2; nt++)
#pragma unroll
            for (int k = 0; k < 4; k++) acc[mt][nt][k] = 0.f;

    const uint32_t* pu = reinterpret_cast<const uint32_t*>(patch);
    const uint32_t* wu = reinterpret_cast<const uint32_t*>(wt);

#pragma unroll
    for (int ky = 0; ky < 5; ky++) {
#pragma unroll
        for (int kx = 0; kx < 5; kx++) {
            int tap = ky * 5 + kx;
            uint32_t breg[2][2];
#pragma unroll
            for (int nt = 0; nt < 2; nt++)
#pragma unroll
                for (int ps = 0; ps < 2; ps++)
                    breg[nt][ps] = wu[(((tap * 16 + nt * 8 + gid) * 2) + ps) * 4 + tg];
#pragma unroll
            for (int mt = 0; mt < 2; mt++) {
                int p = (wid + ky * 2) * 40 + mt * 16 + gid + kx * 2;
                uint32_t a0 = pu[p * 4 + tg];
                uint32_t a1 = pu[(p + 8) * 4 + tg];
#pragma unroll
                for (int nt = 0; nt < 2; nt++) {
                    mma_bf16_k8(acc[mt][nt], a0, a1, breg[nt][0]);
                    mma_bf16_k8(acc[mt][nt], a0, a1, breg[nt][1]);
                }
            }
        }
    }

    // store + fused bn1 stats
    int gy = by0 + wid;
#pragma unroll
    for (int mt = 0; mt < 2; mt++) {
        int gx = bx0 + mt * 16 + gid;
#pragma unroll
        for (int nt = 0; nt < 2; nt++) {
            int co = nt * 8 + 2 * tg;
            float* o = out + ((size_t)(b * 16 + co) * H + gy) * H;
            o[gx] = acc[mt][nt][0];
            o[(size_t)H * H + gx] = acc[mt][nt][1];
            o[gx + 8] = acc[mt][nt][2];
            o[(size_t)H * H + gx + 8] = acc[mt][nt][3];
        }
    }
#pragma unroll
    for (int nt = 0; nt < 2; nt++) {
        float sA = 0.f, qA = 0.f, sB = 0.f, qB = 0.f;
#pragma unroll
        for (int mt = 0; mt < 2; mt++) {
            float a = acc[mt][nt][0], c2 = acc[mt][nt][2];
            float bb_ = acc[mt][nt][1], d = acc[mt][nt][3];
            sA += a + c2;
            qA += a * a + c2 * c2;
            sB += bb_ + d;
            qB += bb_ * bb_ + d * d;
        }
#pragma unroll
        for (int m = 4; m < 32; m <<= 1) {
            sA += __shfl_xor_sync(0xffffffffu, sA, m);
            qA += __shfl_xor_sync(0xffffffffu, qA, m);
            sB += __shfl_xor_sync(0xffffffffu, sB, m);
            qB += __shfl_xor_sync(0xffffffffu, qB, m);
        }
        if (lane < 4) {
            int cA = nt * 8 + 2 * lane;
            atomicAdd(st + (b * 64 + cA) * 2, sA);
            atomicAdd(st + (b * 64 + cA) * 2 + 1, qA);
            atomicAdd(st + (b * 64 + cA + 1) * 2, sB);
            atomicAdd(st + (b * 64 + cA + 1) * 2 + 1, qB);
        }
    }
}

// ---------------- bf16x3 tensor-core 5x5 conv (conv2..6) ----------------
template <int CIN, int COUT, int COUT_B, int H, int DIL, int TH, bool AFF, bool RELU>
__global__ __launch_bounds__(256, 2) void conv5_bf16_kernel(const float* __restrict__ in,
                                                            const float* __restrict__ aff,
                                                            const uint2* __restrict__ wts,
                                                            float* __restrict__ out,
                                                            float* __restrict__ st) {
    constexpr int R = 2 * DIL;
    constexpr int PX = 32 + 2 * R;
    constexpr int PY = TH + 2 * R;
    constexpr int PLANE0 = PX * PY;
    constexpr int PS = PLANE0 + ((4 - PLANE0 % 16) + 16) % 16;
    constexpr int WS = COUT_B + 4;
    constexpr int NT = COUT_B / 8;
    constexpr int MT = (TH / 8) * 2;
    constexpr int RPW = TH / 8;
    constexpr int CGRP = COUT / COUT_B;
    constexpr int CINPAD = (CIN + 15) & ~15;
    constexpr int NCH = CINPAD / 16;

    extern __shared__ uint2 sm[];
    uint2* wtile = sm;
    uint2* patch = sm + 25 * 8 * WS;

    int tid = threadIdx.x, wid = tid >> 5, lane = tid & 31;
    int tg = lane & 3, gid = lane >> 2;
    int bx0 = blockIdx.x * 32;
    int ytile = blockIdx.y / CGRP;
    int cg = blockIdx.y % CGRP;
    int by0 = ytile * TH;
    int b = blockIdx.z;
    int co0 = cg * COUT_B;

    const float* inb = in + (size_t)b * CIN * H * H;
    const float* affb = aff + b * CIN * 2;
    const uint2* wb = wts + ((size_t)b * NCH * 25 * 8) * COUT + co0;

    float acc[MT][NT][4];
#pragma unroll
    for (int mt = 0; mt < MT; mt++)
#pragma unroll
        for (int nt = 0; nt < NT; nt++)
#pragma unroll
            for (int k = 0; k < 4; k++) acc[mt][nt][k] = 0.f;

    int baseA[MT];
#pragma unroll
    for (int mt = 0; mt < MT; mt++) {
        int rofs = (MT == 4) ? (mt >> 1) : 0;
        int pxo = ((MT == 4) ? (mt & 1) : mt) * 16;
        baseA[mt] = tg * PS + (wid * RPW + rofs) * PX + pxo + gid;
    }

    for (int ch = 0; ch < NCH; ch++) {
        __syncthreads();
        for (int idx = tid; idx < 8 * PLANE0; idx += 256) {
            int p = idx / PLANE0;
            int rem = idx - p * PLANE0;
            int py = rem / PX, px = rem - py * PX;
            int gy = by0 - R + py, gx = bx0 - R + px;
            int c0 = ch * 16 + 2 * p;
            float v0 = 0.f, v1 = 0.f;
            if ((unsigned)gy < (unsigned)H && (unsigned)gx < (unsigned)H) {
                if (c0 < CIN) {
                    v0 = inb[((size_t)c0 * H + gy) * H + gx];
                    if (AFF) {
                        v0 = fmaf(v0, __ldg(affb + 2 * c0), __ldg(affb + 2 * c0 + 1));
                        if (RELU) v0 = fmaxf(v0, 0.f);
                    }
                }
                if (c0 + 1 < CIN) {
                    v1 = inb[((size_t)(c0 + 1) * H + gy) * H + gx];
                    if (AFF) {
                        v1 = fmaf(v1, __ldg(affb + 2 * c0 + 2), __ldg(affb + 2 * c0 + 3));
                        if (RELU) v1 = fmaxf(v1, 0.f);
                    }
                }
            }
            patch[p * PS + py * PX + px] = bsplit2(v0, v1);
        }
        const uint2* wc = wb + (size_t)ch * 25 * 8 * COUT;
        for (int idx = tid; idx < 25 * 8 * COUT_B; idx += 256) {
            int t8 = idx / COUT_B;
            int co = idx - t8 * COUT_B;
            wtile[t8 * WS + co] = wc[(size_t)t8 * COUT + co];
        }
        __syncthreads();

#pragma unroll
        for (int ky = 0; ky < 5; ky++) {
#pragma unroll
            for (int kx = 0; kx < 5; kx++) {
                const uint2* wt = wtile + (ky * 5 + kx) * 8 * WS;
                uint2 Bf[NT][2];
#pragma unroll
                for (int nt = 0; nt < NT; nt++) {
                    Bf[nt][0] = wt[tg * WS + nt * 8 + gid];
                    Bf[nt][1] = wt[(tg + 4) * WS + nt * 8 + gid];
                }
#pragma unroll
                for (int mt = 0; mt < MT; mt++) {
                    int ao = baseA[mt] + ky * DIL * PX + kx * DIL;
                    uint2 A0 = patch[ao];
                    uint2 A1 = patch[ao + 8];
                    uint2 A2 = patch[ao + 4 * PS];
                    uint2 A3 = patch[ao + 4 * PS + 8];
#pragma unroll
                    for (int nt = 0; nt < NT; nt++) {
                        mma_bf16(acc[mt][nt], A0.x, A1.x, A2.x, A3.x, Bf[nt][0].x, Bf[nt][1].x);
                        mma_bf16(acc[mt][nt], A0.x, A1.x, A2.x, A3.x, Bf[nt][0].y, Bf[nt][1].y);
                        mma_bf16(acc[mt][nt], A0.y, A1.y, A2.y, A3.y, Bf[nt][0].x, Bf[nt][1].x);
                    }
                }
            }
        }
    }

    // ---- store + fused BN stats ----
#pragma unroll
    for (int mt = 0; mt < MT; mt++) {
        int rofs = (MT == 4) ? (mt >> 1) : 0;
        int pxo = ((MT == 4) ? (mt & 1) : mt) * 16;
        int gy = by0 + wid * RPW + rofs;
        int gx = bx0 + pxo + gid;
#pragma unroll
        for (int nt = 0; nt < NT; nt++) {
            int co = co0 + nt * 8 + 2 * tg;
            float* o = out + ((size_t)(b * COUT + co) * H + gy) * H;
            o[gx] = acc[mt][nt][0];
            o[(size_t)H * H + gx] = acc[mt][nt][1];
            o[gx + 8] = acc[mt][nt][2];
            o[(size_t)H * H + gx + 8] = acc[mt][nt][3];
        }
    }
#pragma unroll
    for (int nt = 0; nt < NT; nt++) {
        float sA = 0.f, qA = 0.f, sB = 0.f, qB = 0.f;
#pragma unroll
        for (int mt = 0; mt < MT; mt++) {
            float a = acc[mt][nt][0], c2 = acc[mt][nt][2];
            float bb_ = acc[mt][nt][1], d = acc[mt][nt][3];
            sA += a + c2;
            qA += a * a + c2 * c2;
            sB += bb_ + d;
            qB += bb_ * bb_ + d * d;
        }
#pragma unroll
        for (int m = 4; m < 32; m <<= 1) {
            sA += __shfl_xor_sync(0xffffffffu, sA, m);
            qA += __shfl_xor_sync(0xffffffffu, qA, m);
            sB += __shfl_xor_sync(0xffffffffu, sB, m);
            qB += __shfl_xor_sync(0xffffffffu, qB, m);
        }
        if (lane < 4) {
            int cA = co0 + nt * 8 + 2 * lane;
            atomicAdd(st + (b * 64 + cA) * 2, sA);
            atomicAdd(st + (b * 64 + cA) * 2 + 1, qA);
            atomicAdd(st + (b * 64 + cA + 1) * 2, sB);
            atomicAdd(st + (b * 64 + cA + 1) * 2 + 1, qB);
        }
    }
}

// ---------------- pointwise kernels ----------------
__global__ void avgpool_kernel(const float* __restrict__ in, const float* __restrict__ aff,
                               float* __restrict__ out) {
    int idx = blockIdx.x * 256 + threadIdx.x;
    if (idx >= 16 * 16 * 128 * 128) return;
    int x = idx & 127;
    int y = (idx >> 7) & 127;
    int bc = idx >> 14;
    const float* p = in + ((size_t)bc * 256 + 2 * y) * 256 + 2 * x;
    float sc = aff[2 * bc], bi = aff[2 * bc + 1];
    float s = p[0] + p[1] + p[256] + p[257];
    out[idx] = fmaf(s * 0.25f, sc, bi);
}

__global__ __launch_bounds__(256) void conv1x1_kernel(const float* __restrict__ in,
                                                      const float* __restrict__ aff,
                                                      const float* __restrict__ wts,
                                                      float* __restrict__ out) {
    int b = blockIdx.y;
    int p = blockIdx.x * 256 + threadIdx.x;
    __shared__ float wsh[4][64];
    __shared__ float sc[64], bi[64];
    int tid = threadIdx.x;
    wsh[tid >> 6][tid & 63] = wts[b * 256 + tid];
    if (tid < 64) {
        sc[tid] = aff[(b * 64 + tid) * 2];
        bi[tid] = aff[(b * 64 + tid) * 2 + 1];
    }
    __syncthreads();
    float acc[4] = {0.f, 0.f, 0.f, 0.f};
    const float* pin = in + (size_t)b * 64 * 16384 + p;
#pragma unroll 8
    for (int ci = 0; ci < 64; ci++) {
        float v = fmaf(pin[(size_t)ci * 16384], sc[ci], bi[ci]);
#pragma unroll
        for (int co = 0; co < 4; co++) acc[co] = fmaf(v, wsh[co][ci], acc[co]);
    }
#pragma unroll
    for (int co = 0; co < 4; co++) out[((size_t)b * 4 + co) * 16384 + p] = acc[co];
}

__global__ void up_add_kernel(const float* __restrict__ in, const float* __restrict__ x,
                              float* __restrict__ out) {
    int idx = blockIdx.x * 256 + threadIdx.x;
    if (idx >= 16 * 4 * 256 * 256) return;
    int ox = idx & 255;
    int oy = (idx >> 8) & 255;
    int bc = idx >> 16;
    const float r = (float)(127.0 / 255.0);
    float px = ox * r, py = oy * r;
    int x0 = (int)px, y0 = (int)py;
    float fx = px - x0, fy = py - y0;
    int x1 = min(x0 + 1, 127), y1 = min(y0 + 1, 127);
    const float* p = in + (size_t)bc * 16384;
    float v00 = p[y0 * 128 + x0], v01 = p[y0 * 128 + x1];
    float v10 = p[y1 * 128 + x0], v11 = p[y1 * 128 + x1];
    float v0 = v00 * (1.f - fx) + v01 * fx;
    float v1 = v10 * (1.f - fx) + v11 * fx;
    out[idx] = v0 * (1.f - fy) + v1 * fy + x[idx];
}

// ---------------- host-side smem size mirror ----------------
static int smem_bytes(int COUT_B, int DIL, int TH) {
    int R = 2 * DIL;
    int PX = 32 + 2 * R, PY = TH + 2 * R;
    int PLANE0 = PX * PY;
    int PS = PLANE0 + ((4 - PLANE0 % 16) + 16) % 16;
    return (25 * 8 * (COUT_B + 4) + 8 * PS) * 8;
}

// ---------------- launch ----------------
extern "C" void kernel_launch(void* const* d_in, const int* in_sizes, int n_in,
                              void* d_out, int out_size) {
    const float* x = (const float*)d_in[0];
    const int* action = (const int*)d_in[1];
    const float* w[7];
    const float* wb[7];
    for (int i = 0; i < 7; i++) {
        w[i] = (const float*)d_in[2 + 2 * i];
        wb[i] = (const float*)d_in[3 + 2 * i];
    }
    const float* bns[7];
    const float* bnb[7];
    for (int i = 0; i < 7; i++) {
        bns[i] = (const float*)d_in[16 + 2 * i];
        bnb[i] = (const float*)d_in[17 + 2 * i];
    }

    uint2 *k2, *k3, *k4, *k5, *k6;
    uint4* c1;
    float* k7;
    float *t1, *t2, *t3, *t4, *t5, *t6, *t7, *t8, *aff, *st;
    cudaGetSymbolAddress((void**)&k2, g_k2);
    cudaGetSymbolAddress((void**)&k3, g_k3);
    cudaGetSymbolAddress((void**)&k4, g_k4);
    cudaGetSymbolAddress((void**)&k5, g_k5);
    cudaGetSymbolAddress((void**)&k6, g_k6);
    cudaGetSymbolAddress((void**)&c1, g_c1);
    cudaGetSymbolAddress((void**)&k7, g_k7);
    cudaGetSymbolAddress((void**)&t1, g_t1);
    cudaGetSymbolAddress((void**)&t2, g_t2);
    cudaGetSymbolAddress((void**)&t3, g_t3);
    cudaGetSymbolAddress((void**)&t4, g_t4);
    cudaGetSymbolAddress((void**)&t5, g_t5);
    cudaGetSymbolAddress((void**)&t6, g_t6);
    cudaGetSymbolAddress((void**)&t7, g_t7);
    cudaGetSymbolAddress((void**)&t8, g_t8);
    cudaGetSymbolAddress((void**)&aff, g_aff);
    cudaGetSymbolAddress((void**)&st, g_st);

    const int AOFF = 16 * 64 * 2;
    const int SOFF = 16 * 64 * 2;
    const float iN256 = 1.f / 65536.f, iN128 = 1.f / 16384.f;

    cudaFuncSetAttribute(conv5_bf16_kernel<16, 16, 16, 256, 1, 16, true, true>,
                         cudaFuncAttributeMaxDynamicSharedMemorySize, smem_bytes(16, 1, 16));
    cudaFuncSetAttribute(conv5_bf16_kernel<16, 32, 32, 128, 2, 8, false, false>,
                         cudaFuncAttributeMaxDynamicSharedMemorySize, smem_bytes(32, 2, 8));
    cudaFuncSetAttribute(conv5_bf16_kernel<32, 32, 32, 128, 1, 16, true, true>,
                         cudaFuncAttributeMaxDynamicSharedMemorySize, smem_bytes(32, 1, 16));
    cudaFuncSetAttribute(conv5_bf16_kernel<32, 64, 32, 128, 2, 8, true, false>,
                         cudaFuncAttributeMaxDynamicSharedMemorySize, smem_bytes(32, 2, 8));
    cudaFuncSetAttribute(conv5_bf16_kernel<64, 64, 32, 128, 1, 16, true, true>,
                         cudaFuncAttributeMaxDynamicSharedMemorySize, smem_bytes(32, 1, 16));

    // #1, #2: weight gen (+ zero stats)
    genA_kernel<<<3000, 256>>>(w[1], wb[1], w[2], wb[2], w[3], wb[3], w[4], wb[4], action, k2, k3,
                               k4, k5, st);
    genB_kernel<<<3267, 256>>>(w[5], wb[5], w[0], wb[0], w[6], wb[6], action, k6, c1, k7);
    // #3: bn0 stats on x
    stats_kernel<65536><<<16 * 4, 256>>>(x, bns[0], bnb[0], aff + 0 * AOFF, 4);
    // #4: conv1 (k8) + bn1 stats
    conv1_k8_kernel<<<dim3(8, 32, 16), 256>>>(x, aff + 0 * AOFF, c1, t1, st + 0 * SOFF);
    // #5: fin1
    fin_kernel<<<1, 256>>>(st + 0 * SOFF, bns[1], bnb[1], aff + 1 * AOFF, 16, iN256);
    // #6: conv2 + bn2 stats  (ncu -s 5 captures this)
    conv5_bf16_kernel<16, 16, 16, 256, 1, 16, true, true>
        <<<dim3(8, 16, 16), 256, smem_bytes(16, 1, 16)>>>(t1, aff + 1 * AOFF, k2, t2,
                                                          st + 1 * SOFF);
    fin_kernel<<<1, 256>>>(st + 1 * SOFF, bns[2], bnb[2], aff + 2 * AOFF, 16, iN256);
    avgpool_kernel<<<(16 * 16 * 128 * 128 + 255) / 256, 256>>>(t2, aff + 2 * AOFF, t3);
    conv5_bf16_kernel<16, 32, 32, 128, 2, 8, false, false>
        <<<dim3(4, 16, 16), 256, smem_bytes(32, 2, 8)>>>(t3, aff, k3, t4, st + 2 * SOFF);
    fin_kernel<<<1, 512>>>(st + 2 * SOFF, bns[3], bnb[3], aff + 3 * AOFF, 32, iN128);
    conv5_bf16_kernel<32, 32, 32, 128, 1, 16, true, true>
        <<<dim3(4, 8, 16), 256, smem_bytes(32, 1, 16)>>>(t4, aff + 3 * AOFF, k4, t5,
                                                         st + 3 * SOFF);
    fin_kernel<<<1, 512>>>(st + 3 * SOFF, bns[4], bnb[4], aff + 4 * AOFF, 32, iN128);
    conv5_bf16_kernel<32, 64, 32, 128, 2, 8, true, false>
        <<<dim3(4, 32, 16), 256, smem_bytes(32, 2, 8)>>>(t5, aff + 4 * AOFF, k5, t6,
                                                         st + 4 * SOFF);
    fin_kernel<<<1, 1024>>>(st + 4 * SOFF, bns[5], bnb[5], aff + 5 * AOFF, 64, iN128);
    conv5_bf16_kernel<64, 64, 32, 128, 1, 16, true, true>
        <<<dim3(4, 16, 16), 256, smem_bytes(32, 1, 16)>>>(t6, aff + 5 * AOFF, k6, t7,
                                                          st + 5 * SOFF);
    fin_kernel<<<1, 1024>>>(st + 5 * SOFF, bns[6], bnb[6], aff + 6 * AOFF, 64, iN128);
    conv1x1_kernel<<<dim3(64, 16), 256>>>(t7, aff + 6 * AOFF, k7, t8);
    up_add_kernel<<<(16 * 4 * 256 * 256 + 255) / 256, 256>>>(t8, x, (float*)d_out);
}

// round 12
// speedup vs baseline: 1.1242x; 1.1242x over previous
#include <cuda_runtime.h>
#include <cuda_bf16.h>
#include <cstdint>

#define EPS 1e-5f

// ---------------- scratch (static __device__ — no allocation) ----------------
// conv2..6 weights, bf16-split u2 layout: [b][chunk(CINPAD/16)][tap(25)][kpair(8)][COUT]
__device__ uint2 g_k2[16 * 1 * 25 * 8 * 16];
__device__ uint2 g_k3[16 * 1 * 25 * 8 * 32];
__device__ uint2 g_k4[16 * 2 * 25 * 8 * 32];
__device__ uint2 g_k5[16 * 2 * 25 * 8 * 64];
__device__ uint2 g_k6[16 * 4 * 25 * 8 * 64];
// conv1 k8 weights: [b][tap][cout][pass(2)] of uint4
__device__ uint4 g_c1[16 * 25 * 16 * 2];
__device__ float g_k7[16 * 4 * 64];

__device__ float g_t1[16 * 16 * 256 * 256];
__device__ float g_t2[16 * 16 * 256 * 256];
__device__ float g_t3[16 * 16 * 128 * 128];
__device__ float g_t4[16 * 32 * 128 * 128];
__device__ float g_t5[16 * 32 * 128 * 128];
__device__ float g_t6[16 * 64 * 128 * 128];
__device__ float g_t7[16 * 64 * 128 * 128];
__device__ float g_t8[16 * 4 * 128 * 128];

__device__ float g_aff[7 * 16 * 64 * 2];  // BN affine [layer][b*C+c][2]

// ---------------- helpers ----------------
__device__ __forceinline__ uint32_t packbf(float a, float b) {
    __nv_bfloat162 h;
    h.x = __float2bfloat16(a);
    h.y = __float2bfloat16(b);
    return *reinterpret_cast<uint32_t*>(&h);
}

__device__ __forceinline__ uint2 bsplit2(float v0, float v1) {
    __nv_bfloat16 h0 = __float2bfloat16(v0);
    __nv_bfloat16 h1 = __float2bfloat16(v1);
    float l0 = v0 - __bfloat162float(h0);
    float l1 = v1 - __bfloat162float(h1);
    uint2 u;
    u.x = packbf(v0, v1);
    u.y = packbf(l0, l1);
    return u;
}

__device__ __forceinline__ void mma_bf16(float c[4], uint32_t a0, uint32_t a1, uint32_t a2,
                                         uint32_t a3, uint32_t b0, uint32_t b1) {
    asm volatile(
        "mma.sync.aligned.m16n8k16.row.col.f32.bf16.bf16.f32 "
        "{%0,%1,%2,%3},{%4,%5,%6,%7},{%8,%9},{%0,%1,%2,%3};"
        : "+f"(c[0]), "+f"(c[1]), "+f"(c[2]), "+f"(c[3])
        : "r"(a0), "r"(a1), "r"(a2), "r"(a3), "r"(b0), "r"(b1));
}

__device__ __forceinline__ void mma_bf16_k8(float c[4], uint32_t a0, uint32_t a1, uint32_t b0) {
    asm volatile(
        "mma.sync.aligned.m16n8k8.row.col.f32.bf16.bf16.f32 "
        "{%0,%1,%2,%3},{%4,%5},{%6},{%0,%1,%2,%3};"
        : "+f"(c[0]), "+f"(c[1]), "+f"(c[2]), "+f"(c[3])
        : "r"(a0), "r"(a1), "r"(b0));
}

// ---------------- weight generation (merged: 2 launches) ----------------
__device__ __forceinline__ void gen_one(const float* __restrict__ w, const float* __restrict__ bias,
                                        const int* __restrict__ action, uint2* __restrict__ out,
                                        int CIN, int NCH, int COUT, int i) {
    int co = i % COUT;
    int r = i / COUT;
    int kp = r % 8;
    r /= 8;
    int tap = r % 25;
    r /= 25;
    int chv = r % NCH;
    int b = r / NCH;
    int a = action[b];
    int ci0 = chv * 16 + kp * 2;
    float v0 = 0.f, v1 = 0.f;
    if (ci0 < CIN) {
        int o = (co * CIN + ci0) * 25 + tap;
        v0 = w[o * 6 + a] + bias[o];
    }
    if (ci0 + 1 < CIN) {
        int o = (co * CIN + ci0 + 1) * 25 + tap;
        v1 = w[o * 6 + a] + bias[o];
    }
    out[i] = bsplit2(v0, v1);
}

__global__ void genA_kernel(const float* w2, const float* b2, const float* w3, const float* b3,
                            const float* w4, const float* b4, const float* w5, const float* b5,
                            const int* __restrict__ action, uint2* k2, uint2* k3, uint2* k4,
                            uint2* k5) {
    int i = blockIdx.x * 256 + threadIdx.x;
    if (i < 51200) gen_one(w2, b2, action, k2, 16, 1, 16, i);
    else if (i < 153600) gen_one(w3, b3, action, k3, 16, 1, 32, i - 51200);
    else if (i < 358400) gen_one(w4, b4, action, k4, 32, 2, 32, i - 153600);
    else if (i < 768000) gen_one(w5, b5, action, k5, 32, 2, 64, i - 358400);
}

__global__ void genB_kernel(const float* w6, const float* b6, const float* w1, const float* b1,
                            const float* w7, const float* b7, const int* __restrict__ action,
                            uint2* k6, uint4* c1, float* k7) {
    int i = blockIdx.x * 256 + threadIdx.x;
    if (i < 819200) {
        gen_one(w6, b6, action, k6, 64, 4, 64, i);
    } else if (i < 819200 + 12800) {
        int j = i - 819200;  // [b][tap][co][pass]
        int pass = j & 1;
        int r = j >> 1;
        int co = r & 15;
        r >>= 4;
        int tap = r % 25;
        int b = r / 25;
        int a = action[b];
        float h[4], l[4];
#pragma unroll
        for (int ci = 0; ci < 4; ci++) {
            int o = (co * 4 + ci) * 25 + tap;
            float v = w1[o * 6 + a] + b1[o];
            __nv_bfloat16 hb = __float2bfloat16(v);
            h[ci] = v;
            l[ci] = v - __bfloat162float(hb);
        }
        uint4 u;
        if (pass == 0) {
            u.x = packbf(h[0], h[1]);
            u.y = packbf(h[2], h[3]);
            u.z = u.x;
            u.w = u.y;
        } else {
            u.x = packbf(l[0], l[1]);
            u.y = packbf(l[2], l[3]);
            u.z = 0;
            u.w = 0;
        }
        c1[j] = u;
    } else if (i < 819200 + 12800 + 4096) {
        int j = i - 819200 - 12800;
        int b = j / 256, o = j - b * 256;
        k7[j] = w7[o * 6 + action[b]] + b7[o];
    }
}

// ---------------- per-(b,c) BN stats -> affine ----------------
template <int N>
__global__ void stats_kernel(const float* __restrict__ in, const float* __restrict__ s,
                             const float* __restrict__ bb, float* __restrict__ aff, int C) {
    int bc = blockIdx.x;
    const float* p = in + (size_t)bc * N;
    float sum = 0.f, sq = 0.f;
    for (int i = threadIdx.x; i < N; i += 256) {
        float v = p[i];
        sum += v;
        sq += v * v;
    }
    __shared__ float ssum[256], ssq[256];
    ssum[threadIdx.x] = sum;
    ssq[threadIdx.x] = sq;
    __syncthreads();
    for (int st = 128; st > 0; st >>= 1) {
        if (threadIdx.x < st) {
            ssum[threadIdx.x] += ssum[threadIdx.x + st];
            ssq[threadIdx.x] += ssq[threadIdx.x + st];
        }
        __syncthreads();
    }
    if (threadIdx.x == 0) {
        int c = bc % C;
        float mean = ssum[0] / (float)N;
        float var = ssq[0] / (float)N - mean * mean;
        float sc = rsqrtf(var + EPS) * s[c];
        aff[2 * bc] = sc;
        aff[2 * bc + 1] = bb[c] - mean * sc;
    }
}

// ---------------- conv1: CIN=4, k8 two-pass, 32x32 tile ----------------
__global__ __launch_bounds__(256, 2) void conv1_k8_kernel(const float* __restrict__ in,
                                                          const float* __restrict__ aff,
                                                          const uint4* __restrict__ wts,
                                                          float* __restrict__ out) {
    const int H = 256, R = 4;
    __shared__ uint4 patch[40 * 40];  // 25.6 KB
    __shared__ uint4 wt[25 * 16 * 2];  // 12.8 KB

    int tid = threadIdx.x, wid = tid >> 5, lane = tid & 31;
    int tg = lane & 3, gid = lane >> 2;
    int bx0 = blockIdx.x * 32, by0 = blockIdx.y * 32, b = blockIdx.z;

    const float* inb = in + (size_t)b * 4 * H * H;
    float s0 = aff[b * 8], bi0 = aff[b * 8 + 1];
    float s1 = aff[b * 8 + 2], bi1 = aff[b * 8 + 3];
    float s2 = aff[b * 8 + 4], bi2 = aff[b * 8 + 5];
    float s3 = aff[b * 8 + 6], bi3 = aff[b * 8 + 7];

    for (int idx = tid; idx < 40 * 40; idx += 256) {
        int py = idx / 40, px = idx - py * 40;
        int gy = by0 - R + py, gx = bx0 - R + px;
        float v0 = 0.f, v1 = 0.f, v2 = 0.f, v3 = 0.f;
        if ((unsigned)gy < 256u && (unsigned)gx < 256u) {
            size_t p0 = (size_t)gy * 256 + gx;
            v0 = fmaf(inb[p0], s0, bi0);
            v1 = fmaf(inb[p0 + 65536], s1, bi1);
            v2 = fmaf(inb[p0 + 131072], s2, bi2);
            v3 = fmaf(inb[p0 + 196608], s3, bi3);
        }
        __nv_bfloat16 h0 = __float2bfloat16(v0), h1 = __float2bfloat16(v1);
        __nv_bfloat16 h2 = __float2bfloat16(v2), h3 = __float2bfloat16(v3);
        uint4 u;
        u.x = packbf(v0, v1);
        u.y = packbf(v2, v3);
        u.z = packbf(v0 - __bfloat162float(h0), v1 - __bfloat162float(h1));
        u.w = packbf(v2 - __bfloat162float(h2), v3 - __bfloat162float(h3));
        patch[idx] = u;
    }
    const uint4* wb = wts + (size_t)b * 800;
    for (int idx = tid; idx < 800; idx += 256) wt[idx] = wb[idx];
    __syncthreads();

    float acc[8][2][4];
#pragma unroll
    for (int mt = 0; mt < 8; mt++)
#pragma unroll
        for (int nt = 0; nt < 2; nt++)
#pragma unroll
            for (int k = 0; k < 4; k++) acc[mt][nt][k] = 0.f;

    const uint32_t* pu = reinterpret_cast<const uint32_t*>(patch);
    const uint32_t* wu = reinterpret_cast<const uint32_t*>(wt);

#pragma unroll
    for (int ky = 0; ky < 5; ky++) {
#pragma unroll
        for (int kx = 0; kx < 5; kx++) {
            int tap = ky * 5 + kx;
            uint32_t breg[2][2];
#pragma unroll
            for (int nt = 0; nt < 2; nt++)
#pragma unroll
                for (int ps = 0; ps < 2; ps++)
                    breg[nt][ps] = wu[(((tap * 16 + nt * 8 + gid) * 2) + ps) * 4 + tg];
#pragma unroll
            for (int mt = 0; mt < 8; mt++) {
                int r = mt >> 1, hx = mt & 1;
                int p = (wid * 4 + r + ky * 2) * 40 + hx * 16 + gid + kx * 2;
                uint32_t a0 = pu[p * 4 + tg];
                uint32_t a1 = pu[(p + 8) * 4 + tg];
#pragma unroll
                for (int nt = 0; nt < 2; nt++) {
                    mma_bf16_k8(acc[mt][nt], a0, a1, breg[nt][0]);
                    mma_bf16_k8(acc[mt][nt], a0, a1, breg[nt][1]);
                }
            }
        }
    }

#pragma unroll
    for (int mt = 0; mt < 8; mt++) {
        int r = mt >> 1, hx = mt & 1;
        int gy = by0 + wid * 4 + r;
        int gx = bx0 + hx * 16 + gid;
#pragma unroll
        for (int nt = 0; nt < 2; nt++) {
            int co = nt * 8 + 2 * tg;
            float* o = out + ((size_t)(b * 16 + co) * H + gy) * H;
            o[gx] = acc[mt][nt][0];
            o[(size_t)H * H + gx] = acc[mt][nt][1];
            o[gx + 8] = acc[mt][nt][2];
            o[(size_t)H * H + gx + 8] = acc[mt][nt][3];
        }
    }
}

// ---------------- bf16x3 tensor-core 5x5 conv (conv2..6) ----------------
template <int CIN, int COUT, int COUT_B, int H, int DIL, int TH, bool AFF, bool RELU>
__global__ __launch_bounds__(256, 2) void conv5_bf16_kernel(const float* __restrict__ in,
                                                            const float* __restrict__ aff,
                                                            const uint2* __restrict__ wts,
                                                            float* __restrict__ out) {
    constexpr int R = 2 * DIL;
    constexpr int PX = 32 + 2 * R;
    constexpr int PY = TH + 2 * R;
    constexpr int PLANE0 = PX * PY;
    constexpr int PS = PLANE0 + ((4 - PLANE0 % 16) + 16) % 16;
    constexpr int WS = COUT_B + 4;
    constexpr int NT = COUT_B / 8;
    constexpr int MT = (TH / 8) * 2;
    constexpr int RPW = TH / 8;
    constexpr int CGRP = COUT / COUT_B;
    constexpr int CINPAD = (CIN + 15) & ~15;
    constexpr int NCH = CINPAD / 16;

    extern __shared__ uint2 sm[];
    uint2* wtile = sm;
    uint2* patch = sm + 25 * 8 * WS;

    int tid = threadIdx.x, wid = tid >> 5, lane = tid & 31;
    int tg = lane & 3, gid = lane >> 2;
    int bx0 = blockIdx.x * 32;
    int ytile = blockIdx.y / CGRP;
    int cg = blockIdx.y % CGRP;
    int by0 = ytile * TH;
    int b = blockIdx.z;
    int co0 = cg * COUT_B;

    const float* inb = in + (size_t)b * CIN * H * H;
    const float* affb = aff + b * CIN * 2;
    const uint2* wb = wts + ((size_t)b * NCH * 25 * 8) * COUT + co0;

    float acc[MT][NT][4];
#pragma unroll
    for (int mt = 0; mt < MT; mt++)
#pragma unroll
        for (int nt = 0; nt < NT; nt++)
#pragma unroll
            for (int k = 0; k < 4; k++) acc[mt][nt][k] = 0.f;

    int baseA[MT];
#pragma unroll
    for (int mt = 0; mt < MT; mt++) {
        int rofs = (MT == 4) ? (mt >> 1) : 0;
        int pxo = ((MT == 4) ? (mt & 1) : mt) * 16;
        baseA[mt] = tg * PS + (wid * RPW + rofs) * PX + pxo + gid;
    }

    for (int ch = 0; ch < NCH; ch++) {
        __syncthreads();
        for (int idx = tid; idx < 8 * PLANE0; idx += 256) {
            int p = idx / PLANE0;
            int rem = idx - p * PLANE0;
            int py = rem / PX, px = rem - py * PX;
            int gy = by0 - R + py, gx = bx0 - R + px;
            int c0 = ch * 16 + 2 * p;
            float v0 = 0.f, v1 = 0.f;
            if ((unsigned)gy < (unsigned)H && (unsigned)gx < (unsigned)H) {
                if (c0 < CIN) {
                    v0 = inb[((size_t)c0 * H + gy) * H + gx];
                    if (AFF) {
                        v0 = fmaf(v0, __ldg(affb + 2 * c0), __ldg(affb + 2 * c0 + 1));
                        if (RELU) v0 = fmaxf(v0, 0.f);
                    }
                }
                if (c0 + 1 < CIN) {
                    v1 = inb[((size_t)(c0 + 1) * H + gy) * H + gx];
                    if (AFF) {
                        v1 = fmaf(v1, __ldg(affb + 2 * c0 + 2), __ldg(affb + 2 * c0 + 3));
                        if (RELU) v1 = fmaxf(v1, 0.f);
                    }
                }
            }
            patch[p * PS + py * PX + px] = bsplit2(v0, v1);
        }
        const uint2* wc = wb + (size_t)ch * 25 * 8 * COUT;
        for (int idx = tid; idx < 25 * 8 * COUT_B; idx += 256) {
            int t8 = idx / COUT_B;
            int co = idx - t8 * COUT_B;
            wtile[t8 * WS + co] = wc[(size_t)t8 * COUT + co];
        }
        __syncthreads();

#pragma unroll
        for (int ky = 0; ky < 5; ky++) {
#pragma unroll
            for (int kx = 0; kx < 5; kx++) {
                const uint2* wt = wtile + (ky * 5 + kx) * 8 * WS;
                uint2 Bf[NT][2];
#pragma unroll
                for (int nt = 0; nt < NT; nt++) {
                    Bf[nt][0] = wt[tg * WS + nt * 8 + gid];
                    Bf[nt][1] = wt[(tg + 4) * WS + nt * 8 + gid];
                }
#pragma unroll
                for (int mt = 0; mt < MT; mt++) {
                    int ao = baseA[mt] + ky * DIL * PX + kx * DIL;
                    uint2 A0 = patch[ao];
                    uint2 A1 = patch[ao + 8];
                    uint2 A2 = patch[ao + 4 * PS];
                    uint2 A3 = patch[ao + 4 * PS + 8];
#pragma unroll
                    for (int nt = 0; nt < NT; nt++) {
                        mma_bf16(acc[mt][nt], A0.x, A1.x, A2.x, A3.x, Bf[nt][0].x, Bf[nt][1].x);
                        mma_bf16(acc[mt][nt], A0.x, A1.x, A2.x, A3.x, Bf[nt][0].y, Bf[nt][1].y);
                        mma_bf16(acc[mt][nt], A0.y, A1.y, A2.y, A3.y, Bf[nt][0].x, Bf[nt][1].x);
                    }
                }
            }
        }
    }

#pragma unroll
    for (int mt = 0; mt < MT; mt++) {
        int rofs = (MT == 4) ? (mt >> 1) : 0;
        int pxo = ((MT == 4) ? (mt & 1) : mt) * 16;
        int gy = by0 + wid * RPW + rofs;
        int gx = bx0 + pxo + gid;
#pragma unroll
        for (int nt = 0; nt < NT; nt++) {
            int co = co0 + nt * 8 + 2 * tg;
            float* o = out + ((size_t)(b * COUT + co) * H + gy) * H;
            o[gx] = acc[mt][nt][0];
            o[(size_t)H * H + gx] = acc[mt][nt][1];
            o[gx + 8] = acc[mt][nt][2];
            o[(size_t)H * H + gx + 8] = acc[mt][nt][3];
        }
    }
}

// ---------------- pointwise kernels ----------------
__global__ void avgpool_kernel(const float* __restrict__ in, const float* __restrict__ aff,
                               float* __restrict__ out) {
    int idx = blockIdx.x * 256 + threadIdx.x;
    if (idx >= 16 * 16 * 128 * 128) return;
    int x = idx & 127;
    int y = (idx >> 7) & 127;
    int bc = idx >> 14;
    const float* p = in + ((size_t)bc * 256 + 2 * y) * 256 + 2 * x;
    float sc = aff[2 * bc], bi = aff[2 * bc + 1];
    float s = p[0] + p[1] + p[256] + p[257];
    out[idx] = fmaf(s * 0.25f, sc, bi);
}

__global__ __launch_bounds__(256) void conv1x1_kernel(const float* __restrict__ in,
                                                      const float* __restrict__ aff,
                                                      const float* __restrict__ wts,
                                                      float* __restrict__ out) {
    int b = blockIdx.y;
    int p = blockIdx.x * 256 + threadIdx.x;
    __shared__ float wsh[4][64];
    __shared__ float sc[64], bi[64];
    int tid = threadIdx.x;
    wsh[tid >> 6][tid & 63] = wts[b * 256 + tid];
    if (tid < 64) {
        sc[tid] = aff[(b * 64 + tid) * 2];
        bi[tid] = aff[(b * 64 + tid) * 2 + 1];
    }
    __syncthreads();
    float acc[4] = {0.f, 0.f, 0.f, 0.f};
    const float* pin = in + (size_t)b * 64 * 16384 + p;
#pragma unroll 8
    for (int ci = 0; ci < 64; ci++) {
        float v = fmaf(pin[(size_t)ci * 16384], sc[ci], bi[ci]);
#pragma unroll
        for (int co = 0; co < 4; co++) acc[co] = fmaf(v, wsh[co][ci], acc[co]);
    }
#pragma unroll
    for (int co = 0; co < 4; co++) out[((size_t)b * 4 + co) * 16384 + p] = acc[co];
}

__global__ void up_add_kernel(const float* __restrict__ in, const float* __restrict__ x,
                              float* __restrict__ out) {
    int idx = blockIdx.x * 256 + threadIdx.x;
    if (idx >= 16 * 4 * 256 * 256) return;
    int ox = idx & 255;
    int oy = (idx >> 8) & 255;
    int bc = idx >> 16;
    const float r = (float)(127.0 / 255.0);
    float px = ox * r, py = oy * r;
    int x0 = (int)px, y0 = (int)py;
    float fx = px - x0, fy = py - y0;
    int x1 = min(x0 + 1, 127), y1 = min(y0 + 1, 127);
    const float* p = in + (size_t)bc * 16384;
    float v00 = p[y0 * 128 + x0], v01 = p[y0 * 128 + x1];
    float v10 = p[y1 * 128 + x0], v11 = p[y1 * 128 + x1];
    float v0 = v00 * (1.f - fx) + v01 * fx;
    float v1 = v10 * (1.f - fx) + v11 * fx;
    out[idx] = v0 * (1.f - fy) + v1 * fy + x[idx];
}

// ---------------- host-side smem size mirror ----------------
static int smem_bytes(int COUT_B, int DIL, int TH) {
    int R = 2 * DIL;
    int PX = 32 + 2 * R, PY = TH + 2 * R;
    int PLANE0 = PX * PY;
    int PS = PLANE0 + ((4 - PLANE0 % 16) + 16) % 16;
    return (25 * 8 * (COUT_B + 4) + 8 * PS) * 8;
}

// ---------------- launch ----------------
extern "C" void kernel_launch(void* const* d_in, const int* in_sizes, int n_in,
                              void* d_out, int out_size) {
    const float* x = (const float*)d_in[0];
    const int* action = (const int*)d_in[1];
    const float* w[7];
    const float* wb[7];
    for (int i = 0; i < 7; i++) {
        w[i] = (const float*)d_in[2 + 2 * i];
        wb[i] = (const float*)d_in[3 + 2 * i];
    }
    const float* bns[7];
    const float* bnb[7];
    for (int i = 0; i < 7; i++) {
        bns[i] = (const float*)d_in[16 + 2 * i];
        bnb[i] = (const float*)d_in[17 + 2 * i];
    }

    uint2 *k2, *k3, *k4, *k5, *k6;
    uint4* c1;
    float* k7;
    float *t1, *t2, *t3, *t4, *t5, *t6, *t7, *t8, *aff;
    cudaGetSymbolAddress((void**)&k2, g_k2);
    cudaGetSymbolAddress((void**)&k3, g_k3);
    cudaGetSymbolAddress((void**)&k4, g_k4);
    cudaGetSymbolAddress((void**)&k5, g_k5);
    cudaGetSymbolAddress((void**)&k6, g_k6);
    cudaGetSymbolAddress((void**)&c1, g_c1);
    cudaGetSymbolAddress((void**)&k7, g_k7);
    cudaGetSymbolAddress((void**)&t1, g_t1);
    cudaGetSymbolAddress((void**)&t2, g_t2);
    cudaGetSymbolAddress((void**)&t3, g_t3);
    cudaGetSymbolAddress((void**)&t4, g_t4);
    cudaGetSymbolAddress((void**)&t5, g_t5);
    cudaGetSymbolAddress((void**)&t6, g_t6);
    cudaGetSymbolAddress((void**)&t7, g_t7);
    cudaGetSymbolAddress((void**)&t8, g_t8);
    cudaGetSymbolAddress((void**)&aff, g_aff);

    const int AOFF = 16 * 64 * 2;

    cudaFuncSetAttribute(conv5_bf16_kernel<16, 16, 16, 256, 1, 16, true, true>,
                         cudaFuncAttributeMaxDynamicSharedMemorySize, smem_bytes(16, 1, 16));
    cudaFuncSetAttribute(conv5_bf16_kernel<16, 32, 32, 128, 2, 8, false, false>,
                         cudaFuncAttributeMaxDynamicSharedMemorySize, smem_bytes(32, 2, 8));
    cudaFuncSetAttribute(conv5_bf16_kernel<32, 32, 32, 128, 1, 16, true, true>,
                         cudaFuncAttributeMaxDynamicSharedMemorySize, smem_bytes(32, 1, 16));
    cudaFuncSetAttribute(conv5_bf16_kernel<32, 64, 32, 128, 2, 8, true, false>,
                         cudaFuncAttributeMaxDynamicSharedMemorySize, smem_bytes(32, 2, 8));
    cudaFuncSetAttribute(conv5_bf16_kernel<64, 64, 32, 128, 1, 16, true, true>,
                         cudaFuncAttributeMaxDynamicSharedMemorySize, smem_bytes(32, 1, 16));

    // #1, #2: weight gen
    genA_kernel<<<3000, 256>>>(w[1], wb[1], w[2], wb[2], w[3], wb[3], w[4], wb[4], action, k2, k3,
                               k4, k5);
    genB_kernel<<<3267, 256>>>(w[5], wb[5], w[0], wb[0], w[6], wb[6], action, k6, c1, k7);
    // #3: bn0 stats on x
    stats_kernel<65536><<<16 * 4, 256>>>(x, bns[0], bnb[0], aff + 0 * AOFF, 4);
    // #4: conv1 (k8, 32x32 tile)
    conv1_k8_kernel<<<dim3(8, 8, 16), 256>>>(x, aff + 0 * AOFF, c1, t1);
    // #5: bn1 stats
    stats_kernel<65536><<<16 * 16, 256>>>(t1, bns[1], bnb[1], aff + 1 * AOFF, 16);
    // #6: conv2  (ncu -s 5 captures this)
    conv5_bf16_kernel<16, 16, 16, 256, 1, 16, true, true>
        <<<dim3(8, 16, 16), 256, smem_bytes(16, 1, 16)>>>(t1, aff + 1 * AOFF, k2, t2);
    stats_kernel<65536><<<16 * 16, 256>>>(t2, bns[2], bnb[2], aff + 2 * AOFF, 16);
    avgpool_kernel<<<(16 * 16 * 128 * 128 + 255) / 256, 256>>>(t2, aff + 2 * AOFF, t3);
    conv5_bf16_kernel<16, 32, 32, 128, 2, 8, false, false>
        <<<dim3(4, 16, 16), 256, smem_bytes(32, 2, 8)>>>(t3, aff, k3, t4);
    stats_kernel<16384><<<16 * 32, 256>>>(t4, bns[3], bnb[3], aff + 3 * AOFF, 32);
    conv5_bf16_kernel<32, 32, 32, 128, 1, 16, true, true>
        <<<dim3(4, 8, 16), 256, smem_bytes(32, 1, 16)>>>(t4, aff + 3 * AOFF, k4, t5);
    stats_kernel<16384><<<16 * 32, 256>>>(t5, bns[4], bnb[4], aff + 4 * AOFF, 32);
    conv5_bf16_kernel<32, 64, 32, 128, 2, 8, true, false>
        <<<dim3(4, 32, 16), 256, smem_bytes(32, 2, 8)>>>(t5, aff + 4 * AOFF, k5, t6);
    stats_kernel<16384><<<16 * 64, 256>>>(t6, bns[5], bnb[5], aff + 5 * AOFF, 64);
    conv5_bf16_kernel<64, 64, 32, 128, 1, 16, true, true>
        <<<dim3(4, 16, 16), 256, smem_bytes(32, 1, 16)>>>(t6, aff + 5 * AOFF, k6, t7);
    stats_kernel<16384><<<16 * 64, 256>>>(t7, bns[6], bnb[6], aff + 6 * AOFF, 64);
    conv1x1_kernel<<<dim3(64, 16), 256>>>(t7, aff + 6 * AOFF, k7, t8);
    up_add_kernel<<<(16 * 4 * 256 * 256 + 255) / 256, 256>>>(t8, x, (float*)d_out);
}

// round 13
// speedup vs baseline: 1.1664x; 1.0375x over previous
#include <cuda_runtime.h>
#include <cuda_bf16.h>
#include <cstdint>

#define EPS 1e-5f

// ---------------- scratch (static __device__ — no allocation) ----------------
// conv2..6 weights, bf16-split u2 layout: [b][chunk(CINPAD/16)][tap(25)][kpair(8)][COUT]
__device__ uint2 g_k2[16 * 1 * 25 * 8 * 16];
__device__ uint2 g_k3[16 * 1 * 25 * 8 * 32];
__device__ uint2 g_k4[16 * 2 * 25 * 8 * 32];
__device__ uint2 g_k5[16 * 2 * 25 * 8 * 64];
__device__ uint2 g_k6[16 * 4 * 25 * 8 * 64];
// conv1 k8 weights: [b][tap][cout][pass(2)] of uint4
__device__ uint4 g_c1[16 * 25 * 16 * 2];
__device__ float g_k7[16 * 4 * 64];

__device__ float g_t1[16 * 16 * 256 * 256];
__device__ float g_t2[16 * 16 * 256 * 256];
__device__ float g_t3[16 * 16 * 128 * 128];
__device__ float g_t4[16 * 32 * 128 * 128];
__device__ float g_t5[16 * 32 * 128 * 128];
__device__ float g_t6[16 * 64 * 128 * 128];
__device__ float g_t7[16 * 64 * 128 * 128];
__device__ float g_t8[16 * 4 * 128 * 128];

__device__ float g_aff[7 * 16 * 64 * 2];  // BN affine [layer][b*C+c][2]
__device__ float g_st2[16 * 16 * 2];      // fused bn2 stats (sum, sumsq)

// ---------------- helpers ----------------
__device__ __forceinline__ uint32_t packbf(float a, float b) {
    __nv_bfloat162 h;
    h.x = __float2bfloat16(a);
    h.y = __float2bfloat16(b);
    return *reinterpret_cast<uint32_t*>(&h);
}

__device__ __forceinline__ uint2 bsplit2(float v0, float v1) {
    __nv_bfloat16 h0 = __float2bfloat16(v0);
    __nv_bfloat16 h1 = __float2bfloat16(v1);
    float l0 = v0 - __bfloat162float(h0);
    float l1 = v1 - __bfloat162float(h1);
    uint2 u;
    u.x = packbf(v0, v1);
    u.y = packbf(l0, l1);
    return u;
}

__device__ __forceinline__ void mma_bf16(float c[4], uint32_t a0, uint32_t a1, uint32_t a2,
                                         uint32_t a3, uint32_t b0, uint32_t b1) {
    asm volatile(
        "mma.sync.aligned.m16n8k16.row.col.f32.bf16.bf16.f32 "
        "{%0,%1,%2,%3},{%4,%5,%6,%7},{%8,%9},{%0,%1,%2,%3};"
        : "+f"(c[0]), "+f"(c[1]), "+f"(c[2]), "+f"(c[3])
        : "r"(a0), "r"(a1), "r"(a2), "r"(a3), "r"(b0), "r"(b1));
}

__device__ __forceinline__ void mma_bf16_k8(float c[4], uint32_t a0, uint32_t a1, uint32_t b0) {
    asm volatile(
        "mma.sync.aligned.m16n8k8.row.col.f32.bf16.bf16.f32 "
        "{%0,%1,%2,%3},{%4,%5},{%6},{%0,%1,%2,%3};"
        : "+f"(c[0]), "+f"(c[1]), "+f"(c[2]), "+f"(c[3])
        : "r"(a0), "r"(a1), "r"(b0));
}

// ---------------- weight generation (merged: 2 launches) ----------------
__device__ __forceinline__ void gen_one(const float* __restrict__ w, const float* __restrict__ bias,
                                        const int* __restrict__ action, uint2* __restrict__ out,
                                        int CIN, int NCH, int COUT, int i) {
    int co = i % COUT;
    int r = i / COUT;
    int kp = r % 8;
    r /= 8;
    int tap = r % 25;
    r /= 25;
    int chv = r % NCH;
    int b = r / NCH;
    int a = action[b];
    int ci0 = chv * 16 + kp * 2;
    float v0 = 0.f, v1 = 0.f;
    if (ci0 < CIN) {
        int o = (co * CIN + ci0) * 25 + tap;
        v0 = w[o * 6 + a] + bias[o];
    }
    if (ci0 + 1 < CIN) {
        int o = (co * CIN + ci0 + 1) * 25 + tap;
        v1 = w[o * 6 + a] + bias[o];
    }
    out[i] = bsplit2(v0, v1);
}

__global__ void genA_kernel(const float* w2, const float* b2, const float* w3, const float* b3,
                            const float* w4, const float* b4, const float* w5, const float* b5,
                            const int* __restrict__ action, uint2* k2, uint2* k3, uint2* k4,
                            uint2* k5, float* st2) {
    int i = blockIdx.x * 256 + threadIdx.x;
    if (i < 16 * 16 * 2) st2[i] = 0.f;
    if (i < 51200) gen_one(w2, b2, action, k2, 16, 1, 16, i);
    else if (i < 153600) gen_one(w3, b3, action, k3, 16, 1, 32, i - 51200);
    else if (i < 358400) gen_one(w4, b4, action, k4, 32, 2, 32, i - 153600);
    else if (i < 768000) gen_one(w5, b5, action, k5, 32, 2, 64, i - 358400);
}

__global__ void genB_kernel(const float* w6, const float* b6, const float* w1, const float* b1,
                            const float* w7, const float* b7, const int* __restrict__ action,
                            uint2* k6, uint4* c1, float* k7) {
    int i = blockIdx.x * 256 + threadIdx.x;
    if (i < 819200) {
        gen_one(w6, b6, action, k6, 64, 4, 64, i);
    } else if (i < 819200 + 12800) {
        int j = i - 819200;  // [b][tap][co][pass]
        int pass = j & 1;
        int r = j >> 1;
        int co = r & 15;
        r >>= 4;
        int tap = r % 25;
        int b = r / 25;
        int a = action[b];
        float h[4], l[4];
#pragma unroll
        for (int ci = 0; ci < 4; ci++) {
            int o = (co * 4 + ci) * 25 + tap;
            float v = w1[o * 6 + a] + b1[o];
            __nv_bfloat16 hb = __float2bfloat16(v);
            h[ci] = v;
            l[ci] = v - __bfloat162float(hb);
        }
        uint4 u;
        if (pass == 0) {
            u.x = packbf(h[0], h[1]);
            u.y = packbf(h[2], h[3]);
            u.z = u.x;
            u.w = u.y;
        } else {
            u.x = packbf(l[0], l[1]);
            u.y = packbf(l[2], l[3]);
            u.z = 0;
            u.w = 0;
        }
        c1[j] = u;
    } else if (i < 819200 + 12800 + 4096) {
        int j = i - 819200 - 12800;
        int b = j / 256, o = j - b * 256;
        k7[j] = w7[o * 6 + action[b]] + b7[o];
    }
}

// ---------------- per-(b,c) BN stats -> affine ----------------
template <int N>
__global__ void stats_kernel(const float* __restrict__ in, const float* __restrict__ s,
                             const float* __restrict__ bb, float* __restrict__ aff, int C) {
    int bc = blockIdx.x;
    const float* p = in + (size_t)bc * N;
    float sum = 0.f, sq = 0.f;
    for (int i = threadIdx.x; i < N; i += 256) {
        float v = p[i];
        sum += v;
        sq += v * v;
    }
    __shared__ float ssum[256], ssq[256];
    ssum[threadIdx.x] = sum;
    ssq[threadIdx.x] = sq;
    __syncthreads();
    for (int st = 128; st > 0; st >>= 1) {
        if (threadIdx.x < st) {
            ssum[threadIdx.x] += ssum[threadIdx.x + st];
            ssq[threadIdx.x] += ssq[threadIdx.x + st];
        }
        __syncthreads();
    }
    if (threadIdx.x == 0) {
        int c = bc % C;
        float mean = ssum[0] / (float)N;
        float var = ssq[0] / (float)N - mean * mean;
        float sc = rsqrtf(var + EPS) * s[c];
        aff[2 * bc] = sc;
        aff[2 * bc + 1] = bb[c] - mean * sc;
    }
}

// ---------------- finalize fused stats -> affine (bn2) ----------------
__global__ void fin_kernel(const float* __restrict__ st, const float* __restrict__ s,
                           const float* __restrict__ bb, float* __restrict__ aff, int C,
                           float invN) {
    int i = threadIdx.x;
    if (i >= C * 16) return;
    int b = i / C, c = i - b * C;
    float sum = st[(b * C + c) * 2];
    float sq = st[(b * C + c) * 2 + 1];
    float mean = sum * invN;
    float var = sq * invN - mean * mean;
    float sc = rsqrtf(var + EPS) * s[c];
    aff[2 * (b * C + c)] = sc;
    aff[2 * (b * C + c) + 1] = bb[c] - mean * sc;
}

// ---------------- conv1: CIN=4, k8 two-pass, 32x32 tile ----------------
__global__ __launch_bounds__(256, 2) void conv1_k8_kernel(const float* __restrict__ in,
                                                          const float* __restrict__ aff,
                                                          const uint4* __restrict__ wts,
                                                          float* __restrict__ out) {
    const int H = 256, R = 4;
    __shared__ uint4 patch[40 * 40];
    __shared__ uint4 wt[25 * 16 * 2];

    int tid = threadIdx.x, wid = tid >> 5, lane = tid & 31;
    int tg = lane & 3, gid = lane >> 2;
    int bx0 = blockIdx.x * 32, by0 = blockIdx.y * 32, b = blockIdx.z;

    const float* inb = in + (size_t)b * 4 * H * H;
    float s0 = aff[b * 8], bi0 = aff[b * 8 + 1];
    float s1 = aff[b * 8 + 2], bi1 = aff[b * 8 + 3];
    float s2 = aff[b * 8 + 4], bi2 = aff[b * 8 + 5];
    float s3 = aff[b * 8 + 6], bi3 = aff[b * 8 + 7];

    for (int idx = tid; idx < 40 * 40; idx += 256) {
        int py = idx / 40, px = idx - py * 40;
        int gy = by0 - R + py, gx = bx0 - R + px;
        float v0 = 0.f, v1 = 0.f, v2 = 0.f, v3 = 0.f;
        if ((unsigned)gy < 256u && (unsigned)gx < 256u) {
            size_t p0 = (size_t)gy * 256 + gx;
            v0 = fmaf(inb[p0], s0, bi0);
            v1 = fmaf(inb[p0 + 65536], s1, bi1);
            v2 = fmaf(inb[p0 + 131072], s2, bi2);
            v3 = fmaf(inb[p0 + 196608], s3, bi3);
        }
        __nv_bfloat16 h0 = __float2bfloat16(v0), h1 = __float2bfloat16(v1);
        __nv_bfloat16 h2 = __float2bfloat16(v2), h3 = __float2bfloat16(v3);
        uint4 u;
        u.x = packbf(v0, v1);
        u.y = packbf(v2, v3);
        u.z = packbf(v0 - __bfloat162float(h0), v1 - __bfloat162float(h1));
        u.w = packbf(v2 - __bfloat162float(h2), v3 - __bfloat162float(h3));
        patch[idx] = u;
    }
    const uint4* wb = wts + (size_t)b * 800;
    for (int idx = tid; idx < 800; idx += 256) wt[idx] = wb[idx];
    __syncthreads();

    float acc[8][2][4];
#pragma unroll
    for (int mt = 0; mt < 8; mt++)
#pragma unroll
        for (int nt = 0; nt < 2; nt++)
#pragma unroll
            for (int k = 0; k < 4; k++) acc[mt][nt][k] = 0.f;

    const uint32_t* pu = reinterpret_cast<const uint32_t*>(patch);
    const uint32_t* wu = reinterpret_cast<const uint32_t*>(wt);

#pragma unroll
    for (int ky = 0; ky < 5; ky++) {
#pragma unroll
        for (int kx = 0; kx < 5; kx++) {
            int tap = ky * 5 + kx;
            uint32_t breg[2][2];
#pragma unroll
            for (int nt = 0; nt < 2; nt++)
#pragma unroll
                for (int ps = 0; ps < 2; ps++)
                    breg[nt][ps] = wu[(((tap * 16 + nt * 8 + gid) * 2) + ps) * 4 + tg];
#pragma unroll
            for (int mt = 0; mt < 8; mt++) {
                int r = mt >> 1, hx = mt & 1;
                int p = (wid * 4 + r + ky * 2) * 40 + hx * 16 + gid + kx * 2;
                uint32_t a0 = pu[p * 4 + tg];
                uint32_t a1 = pu[(p + 8) * 4 + tg];
#pragma unroll
                for (int nt = 0; nt < 2; nt++) {
                    mma_bf16_k8(acc[mt][nt], a0, a1, breg[nt][0]);
                    mma_bf16_k8(acc[mt][nt], a0, a1, breg[nt][1]);
                }
            }
        }
    }

#pragma unroll
    for (int mt = 0; mt < 8; mt++) {
        int r = mt >> 1, hx = mt & 1;
        int gy = by0 + wid * 4 + r;
        int gx = bx0 + hx * 16 + gid;
#pragma unroll
        for (int nt = 0; nt < 2; nt++) {
            int co = nt * 8 + 2 * tg;
            float* o = out + ((size_t)(b * 16 + co) * H + gy) * H;
            o[gx] = acc[mt][nt][0];
            o[(size_t)H * H + gx] = acc[mt][nt][1];
            o[gx + 8] = acc[mt][nt][2];
            o[(size_t)H * H + gx + 8] = acc[mt][nt][3];
        }
    }
}

// ---------------- bf16x3 tensor-core 5x5 conv (conv2..4) ----------------
template <int CIN, int COUT, int COUT_B, int H, int DIL, int TH, bool AFF, bool RELU>
__global__ __launch_bounds__(256, 2) void conv5_bf16_kernel(const float* __restrict__ in,
                                                            const float* __restrict__ aff,
                                                            const uint2* __restrict__ wts,
                                                            float* __restrict__ out) {
    constexpr int R = 2 * DIL;
    constexpr int PX = 32 + 2 * R;
    constexpr int PY = TH + 2 * R;
    constexpr int PLANE0 = PX * PY;
    constexpr int PS = PLANE0 + ((4 - PLANE0 % 16) + 16) % 16;
    constexpr int WS = COUT_B + 4;
    constexpr int NT = COUT_B / 8;
    constexpr int MT = (TH / 8) * 2;
    constexpr int RPW = TH / 8;
    constexpr int CGRP = COUT / COUT_B;
    constexpr int CINPAD = (CIN + 15) & ~15;
    constexpr int NCH = CINPAD / 16;

    extern __shared__ uint2 sm[];
    uint2* wtile = sm;
    uint2* patch = sm + 25 * 8 * WS;

    int tid = threadIdx.x, wid = tid >> 5, lane = tid & 31;
    int tg = lane & 3, gid = lane >> 2;
    int bx0 = blockIdx.x * 32;
    int ytile = blockIdx.y / CGRP;
    int cg = blockIdx.y % CGRP;
    int by0 = ytile * TH;
    int b = blockIdx.z;
    int co0 = cg * COUT_B;

    const float* inb = in + (size_t)b * CIN * H * H;
    const float* affb = aff + b * CIN * 2;
    const uint2* wb = wts + ((size_t)b * NCH * 25 * 8) * COUT + co0;

    float acc[MT][NT][4];
#pragma unroll
    for (int mt = 0; mt < MT; mt++)
#pragma unroll
        for (int nt = 0; nt < NT; nt++)
#pragma unroll
            for (int k = 0; k < 4; k++) acc[mt][nt][k] = 0.f;

    int baseA[MT];
#pragma unroll
    for (int mt = 0; mt < MT; mt++) {
        int rofs = (MT == 4) ? (mt >> 1) : 0;
        int pxo = ((MT == 4) ? (mt & 1) : mt) * 16;
        baseA[mt] = tg * PS + (wid * RPW + rofs) * PX + pxo + gid;
    }

    for (int ch = 0; ch < NCH; ch++) {
        __syncthreads();
        for (int idx = tid; idx < 8 * PLANE0; idx += 256) {
            int p = idx / PLANE0;
            int rem = idx - p * PLANE0;
            int py = rem / PX, px = rem - py * PX;
            int gy = by0 - R + py, gx = bx0 - R + px;
            int c0 = ch * 16 + 2 * p;
            float v0 = 0.f, v1 = 0.f;
            if ((unsigned)gy < (unsigned)H && (unsigned)gx < (unsigned)H) {
                if (c0 < CIN) {
                    v0 = inb[((size_t)c0 * H + gy) * H + gx];
                    if (AFF) {
                        v0 = fmaf(v0, __ldg(affb + 2 * c0), __ldg(affb + 2 * c0 + 1));
                        if (RELU) v0 = fmaxf(v0, 0.f);
                    }
                }
                if (c0 + 1 < CIN) {
                    v1 = inb[((size_t)(c0 + 1) * H + gy) * H + gx];
                    if (AFF) {
                        v1 = fmaf(v1, __ldg(affb + 2 * c0 + 2), __ldg(affb + 2 * c0 + 3));
                        if (RELU) v1 = fmaxf(v1, 0.f);
                    }
                }
            }
            patch[p * PS + py * PX + px] = bsplit2(v0, v1);
        }
        const uint2* wc = wb + (size_t)ch * 25 * 8 * COUT;
        for (int idx = tid; idx < 25 * 8 * COUT_B; idx += 256) {
            int t8 = idx / COUT_B;
            int co = idx - t8 * COUT_B;
            wtile[t8 * WS + co] = wc[(size_t)t8 * COUT + co];
        }
        __syncthreads();

#pragma unroll
        for (int ky = 0; ky < 5; ky++) {
#pragma unroll
            for (int kx = 0; kx < 5; kx++) {
                const uint2* wt = wtile + (ky * 5 + kx) * 8 * WS;
                uint2 Bf[NT][2];
#pragma unroll
                for (int nt = 0; nt < NT; nt++) {
                    Bf[nt][0] = wt[tg * WS + nt * 8 + gid];
                    Bf[nt][1] = wt[(tg + 4) * WS + nt * 8 + gid];
                }
#pragma unroll
                for (int mt = 0; mt < MT; mt++) {
                    int ao = baseA[mt] + ky * DIL * PX + kx * DIL;
                    uint2 A0 = patch[ao];
                    uint2 A1 = patch[ao + 8];
                    uint2 A2 = patch[ao + 4 * PS];
                    uint2 A3 = patch[ao + 4 * PS + 8];
#pragma unroll
                    for (int nt = 0; nt < NT; nt++) {
                        mma_bf16(acc[mt][nt], A0.x, A1.x, A2.x, A3.x, Bf[nt][0].x, Bf[nt][1].x);
                        mma_bf16(acc[mt][nt], A0.x, A1.x, A2.x, A3.x, Bf[nt][0].y, Bf[nt][1].y);
                        mma_bf16(acc[mt][nt], A0.y, A1.y, A2.y, A3.y, Bf[nt][0].x, Bf[nt][1].x);
                    }
                }
            }
        }
    }

#pragma unroll
    for (int mt = 0; mt < MT; mt++) {
        int rofs = (MT == 4) ? (mt >> 1) : 0;
        int pxo = ((MT == 4) ? (mt & 1) : mt) * 16;
        int gy = by0 + wid * RPW + rofs;
        int gx = bx0 + pxo + gid;
#pragma unroll
        for (int nt = 0; nt < NT; nt++) {
            int co = co0 + nt * 8 + 2 * tg;
            float* o = out + ((size_t)(b * COUT + co) * H + gy) * H;
            o[gx] = acc[mt][nt][0];
            o[(size_t)H * H + gx] = acc[mt][nt][1];
            o[gx + 8] = acc[mt][nt][2];
            o[(size_t)H * H + gx + 8] = acc[mt][nt][3];
        }
    }
}

// ---------------- wide conv (COUT=64, COUT_B=64, TH=8): conv5, conv6 ----------------
// Per-ky weight staging (21.8KB) keeps smem for 2 CTA/SM; nt-outer loop with A cached.
template <int CIN, int H, int DIL, bool RELU>
__global__ __launch_bounds__(256, 2) void conv5_wide_kernel(const float* __restrict__ in,
                                                            const float* __restrict__ aff,
                                                            const uint2* __restrict__ wts,
                                                            float* __restrict__ out) {
    constexpr int R = 2 * DIL;
    constexpr int PX = 32 + 2 * R;
    constexpr int PY = 8 + 2 * R;
    constexpr int PLANE0 = PX * PY;
    constexpr int PS = PLANE0 + ((4 - PLANE0 % 16) + 16) % 16;
    constexpr int WS = 68;
    constexpr int NCH = CIN / 16;

    extern __shared__ uint2 sm[];
    uint2* wtile = sm;                // [5 kx][8 kp][WS]
    uint2* patch = sm + 5 * 8 * WS;   // [8 pairs][PS]

    int tid = threadIdx.x, wid = tid >> 5, lane = tid & 31;
    int tg = lane & 3, gid = lane >> 2;
    int bx0 = blockIdx.x * 32;
    int by0 = blockIdx.y * 8;
    int b = blockIdx.z;

    const float* inb = in + (size_t)b * CIN * H * H;
    const float* affb = aff + b * CIN * 2;
    const uint2* wb = wts + ((size_t)b * NCH * 25 * 8) * 64;

    float acc[2][8][4];
#pragma unroll
    for (int mt = 0; mt < 2; mt++)
#pragma unroll
        for (int nt = 0; nt < 8; nt++)
#pragma unroll
            for (int k = 0; k < 4; k++) acc[mt][nt][k] = 0.f;

    int baseA0 = tg * PS + wid * PX + gid;

    for (int ch = 0; ch < NCH; ch++) {
        __syncthreads();
        // patch fill (once per chunk — CGRP=1, no duplication)
        for (int idx = tid; idx < 8 * PLANE0; idx += 256) {
            int p = idx / PLANE0;
            int rem = idx - p * PLANE0;
            int py = rem / PX, px = rem - py * PX;
            int gy = by0 - R + py, gx = bx0 - R + px;
            int c0 = ch * 16 + 2 * p;
            float v0 = 0.f, v1 = 0.f;
            if ((unsigned)gy < (unsigned)H && (unsigned)gx < (unsigned)H) {
                v0 = fmaf(inb[((size_t)c0 * H + gy) * H + gx], __ldg(affb + 2 * c0),
                          __ldg(affb + 2 * c0 + 1));
                v1 = fmaf(inb[((size_t)(c0 + 1) * H + gy) * H + gx], __ldg(affb + 2 * c0 + 2),
                          __ldg(affb + 2 * c0 + 3));
                if (RELU) {
                    v0 = fmaxf(v0, 0.f);
                    v1 = fmaxf(v1, 0.f);
                }
            }
            patch[p * PS + py * PX + px] = bsplit2(v0, v1);
        }
        const uint2* wc = wb + (size_t)ch * 25 * 8 * 64;
#pragma unroll 1
        for (int ky = 0; ky < 5; ky++) {
            __syncthreads();
            // stage weights for (ch, ky): 5 kx x 8 kp x 64 co
            for (int idx = tid; idx < 5 * 8 * 64; idx += 256) {
                int kx = idx >> 9;          // /512
                int rem = idx & 511;
                int kp = rem >> 6;
                int co = rem & 63;
                wtile[(kx * 8 + kp) * WS + co] = wc[((ky * 5 + kx) * 8 + kp) * 64 + co];
            }
            __syncthreads();
#pragma unroll
            for (int kx = 0; kx < 5; kx++) {
                uint2 A[2][4];
#pragma unroll
                for (int mt = 0; mt < 2; mt++) {
                    int ao = baseA0 + mt * 16 + ky * DIL * PX + kx * DIL;
                    A[mt][0] = patch[ao];
                    A[mt][1] = patch[ao + 8];
                    A[mt][2] = patch[ao + 4 * PS];
                    A[mt][3] = patch[ao + 4 * PS + 8];
                }
                const uint2* wt = wtile + kx * 8 * WS;
#pragma unroll
                for (int nt = 0; nt < 8; nt++) {
                    uint2 B0 = wt[tg * WS + nt * 8 + gid];
                    uint2 B1 = wt[(tg + 4) * WS + nt * 8 + gid];
#pragma unroll
                    for (int mt = 0; mt < 2; mt++) {
                        mma_bf16(acc[mt][nt], A[mt][0].x, A[mt][1].x, A[mt][2].x, A[mt][3].x,
                                 B0.x, B1.x);
                        mma_bf16(acc[mt][nt], A[mt][0].x, A[mt][1].x, A[mt][2].x, A[mt][3].x,
                                 B0.y, B1.y);
                        mma_bf16(acc[mt][nt], A[mt][0].y, A[mt][1].y, A[mt][2].y, A[mt][3].y,
                                 B0.x, B1.x);
                    }
                }
            }
        }
    }

    int gy = by0 + wid;
#pragma unroll
    for (int mt = 0; mt < 2; mt++) {
        int gx = bx0 + mt * 16 + gid;
#pragma unroll
        for (int nt = 0; nt < 8; nt++) {
            int co = nt * 8 + 2 * tg;
            float* o = out + ((size_t)(b * 64 + co) * H + gy) * H;
            o[gx] = acc[mt][nt][0];
            o[(size_t)H * H + gx] = acc[mt][nt][1];
            o[gx + 8] = acc[mt][nt][2];
            o[(size_t)H * H + gx + 8] = acc[mt][nt][3];
        }
    }
}

// ---------------- avgpool (raw mean) + fused bn2 stats ----------------
__global__ void avgpool_stats_kernel(const float* __restrict__ in, float* __restrict__ out,
                                     float* __restrict__ st) {
    int idx = blockIdx.x * 256 + threadIdx.x;
    int x = idx & 127;
    int y = (idx >> 7) & 127;
    int bc = idx >> 14;  // constant within a block (16384 px per bc, 256 | 16384)
    const float* p = in + ((size_t)bc * 256 + 2 * y) * 256 + 2 * x;
    float v0 = p[0], v1 = p[1], v2 = p[256], v3 = p[257];
    out[idx] = (v0 + v1 + v2 + v3) * 0.25f;
    float s = v0 + v1 + v2 + v3;
    float q = v0 * v0 + v1 * v1 + v2 * v2 + v3 * v3;
    __shared__ float ss[256], sq[256];
    ss[threadIdx.x] = s;
    sq[threadIdx.x] = q;
    __syncthreads();
    for (int stp = 128; stp > 0; stp >>= 1) {
        if (threadIdx.x < stp) {
            ss[threadIdx.x] += ss[threadIdx.x + stp];
            sq[threadIdx.x] += sq[threadIdx.x + stp];
        }
        __syncthreads();
    }
    if (threadIdx.x == 0) {
        atomicAdd(st + bc * 2, ss[0]);
        atomicAdd(st + bc * 2 + 1, sq[0]);
    }
}

// ---------------- 1x1 conv + bilinear residual ----------------
__global__ __launch_bounds__(256) void conv1x1_kernel(const float* __restrict__ in,
                                                      const float* __restrict__ aff,
                                                      const float* __restrict__ wts,
                                                      float* __restrict__ out) {
    int b = blockIdx.y;
    int p = blockIdx.x * 256 + threadIdx.x;
    __shared__ float wsh[4][64];
    __shared__ float sc[64], bi[64];
    int tid = threadIdx.x;
    wsh[tid >> 6][tid & 63] = wts[b * 256 + tid];
    if (tid < 64) {
        sc[tid] = aff[(b * 64 + tid) * 2];
        bi[tid] = aff[(b * 64 + tid) * 2 + 1];
    }
    __syncthreads();
    float acc[4] = {0.f, 0.f, 0.f, 0.f};
    const float* pin = in + (size_t)b * 64 * 16384 + p;
#pragma unroll 8
    for (int ci = 0; ci < 64; ci++) {
        float v = fmaf(pin[(size_t)ci * 16384], sc[ci], bi[ci]);
#pragma unroll
        for (int co = 0; co < 4; co++) acc[co] = fmaf(v, wsh[co][ci], acc[co]);
    }
#pragma unroll
    for (int co = 0; co < 4; co++) out[((size_t)b * 4 + co) * 16384 + p] = acc[co];
}

__global__ void up_add_kernel(const float* __restrict__ in, const float* __restrict__ x,
                              float* __restrict__ out) {
    int idx = blockIdx.x * 256 + threadIdx.x;
    if (idx >= 16 * 4 * 256 * 256) return;
    int ox = idx & 255;
    int oy = (idx >> 8) & 255;
    int bc = idx >> 16;
    const float r = (float)(127.0 / 255.0);
    float px = ox * r, py = oy * r;
    int x0 = (int)px, y0 = (int)py;
    float fx = px - x0, fy = py - y0;
    int x1 = min(x0 + 1, 127), y1 = min(y0 + 1, 127);
    const float* p = in + (size_t)bc * 16384;
    float v00 = p[y0 * 128 + x0], v01 = p[y0 * 128 + x1];
    float v10 = p[y1 * 128 + x0], v11 = p[y1 * 128 + x1];
    float v0 = v00 * (1.f - fx) + v01 * fx;
    float v1 = v10 * (1.f - fx) + v11 * fx;
    out[idx] = v0 * (1.f - fy) + v1 * fy + x[idx];
}

// ---------------- host-side smem size mirrors ----------------
static int smem_bytes(int COUT_B, int DIL, int TH) {
    int R = 2 * DIL;
    int PX = 32 + 2 * R, PY = TH + 2 * R;
    int PLANE0 = PX * PY;
    int PS = PLANE0 + ((4 - PLANE0 % 16) + 16) % 16;
    return (25 * 8 * (COUT_B + 4) + 8 * PS) * 8;
}
static int wide_smem(int DIL) {
    int R = 2 * DIL;
    int PX = 32 + 2 * R, PY = 8 + 2 * R;
    int PLANE0 = PX * PY;
    int PS = PLANE0 + ((4 - PLANE0 % 16) + 16) % 16;
    return (5 * 8 * 68 + 8 * PS) * 8;
}

// ---------------- launch ----------------
extern "C" void kernel_launch(void* const* d_in, const int* in_sizes, int n_in,
                              void* d_out, int out_size) {
    const float* x = (const float*)d_in[0];
    const int* action = (const int*)d_in[1];
    const float* w[7];
    const float* wb[7];
    for (int i = 0; i < 7; i++) {
        w[i] = (const float*)d_in[2 + 2 * i];
        wb[i] = (const float*)d_in[3 + 2 * i];
    }
    const float* bns[7];
    const float* bnb[7];
    for (int i = 0; i < 7; i++) {
        bns[i] = (const float*)d_in[16 + 2 * i];
        bnb[i] = (const float*)d_in[17 + 2 * i];
    }

    uint2 *k2, *k3, *k4, *k5, *k6;
    uint4* c1;
    float* k7;
    float *t1, *t2, *t3, *t4, *t5, *t6, *t7, *t8, *aff, *st2;
    cudaGetSymbolAddress((void**)&k2, g_k2);
    cudaGetSymbolAddress((void**)&k3, g_k3);
    cudaGetSymbolAddress((void**)&k4, g_k4);
    cudaGetSymbolAddress((void**)&k5, g_k5);
    cudaGetSymbolAddress((void**)&k6, g_k6);
    cudaGetSymbolAddress((void**)&c1, g_c1);
    cudaGetSymbolAddress((void**)&k7, g_k7);
    cudaGetSymbolAddress((void**)&t1, g_t1);
    cudaGetSymbolAddress((void**)&t2, g_t2);
    cudaGetSymbolAddress((void**)&t3, g_t3);
    cudaGetSymbolAddress((void**)&t4, g_t4);
    cudaGetSymbolAddress((void**)&t5, g_t5);
    cudaGetSymbolAddress((void**)&t6, g_t6);
    cudaGetSymbolAddress((void**)&t7, g_t7);
    cudaGetSymbolAddress((void**)&t8, g_t8);
    cudaGetSymbolAddress((void**)&aff, g_aff);
    cudaGetSymbolAddress((void**)&st2, g_st2);

    const int AOFF = 16 * 64 * 2;

    cudaFuncSetAttribute(conv5_bf16_kernel<16, 16, 16, 256, 1, 16, true, true>,
                         cudaFuncAttributeMaxDynamicSharedMemorySize, smem_bytes(16, 1, 16));
    cudaFuncSetAttribute(conv5_bf16_kernel<16, 32, 32, 128, 2, 8, true, false>,
                         cudaFuncAttributeMaxDynamicSharedMemorySize, smem_bytes(32, 2, 8));
    cudaFuncSetAttribute(conv5_bf16_kernel<32, 32, 32, 128, 1, 16, true, true>,
                         cudaFuncAttributeMaxDynamicSharedMemorySize, smem_bytes(32, 1, 16));
    cudaFuncSetAttribute(conv5_wide_kernel<32, 128, 2, false>,
                         cudaFuncAttributeMaxDynamicSharedMemorySize, wide_smem(2));
    cudaFuncSetAttribute(conv5_wide_kernel<64, 128, 1, true>,
                         cudaFuncAttributeMaxDynamicSharedMemorySize, wide_smem(1));

    // #1, #2: weight gen (+ zero bn2 stats buffer)
    genA_kernel<<<3000, 256>>>(w[1], wb[1], w[2], wb[2], w[3], wb[3], w[4], wb[4], action, k2, k3,
                               k4, k5, st2);
    genB_kernel<<<3267, 256>>>(w[5], wb[5], w[0], wb[0], w[6], wb[6], action, k6, c1, k7);
    // #3: bn0 stats on x
    stats_kernel<65536><<<16 * 4, 256>>>(x, bns[0], bnb[0], aff + 0 * AOFF, 4);
    // #4: conv1 (k8, 32x32 tile)
    conv1_k8_kernel<<<dim3(8, 8, 16), 256>>>(x, aff + 0 * AOFF, c1, t1);
    // #5: bn1 stats
    stats_kernel<65536><<<16 * 16, 256>>>(t1, bns[1], bnb[1], aff + 1 * AOFF, 16);
    // #6: conv2
    conv5_bf16_kernel<16, 16, 16, 256, 1, 16, true, true>
        <<<dim3(8, 16, 16), 256, smem_bytes(16, 1, 16)>>>(t1, aff + 1 * AOFF, k2, t2);
    // avgpool (raw mean) + bn2 stats fused
    avgpool_stats_kernel<<<16384, 256>>>(t2, t3, st2);
    fin_kernel<<<1, 256>>>(st2, bns[2], bnb[2], aff + 2 * AOFF, 16, 1.f / 65536.f);
    // conv3 (affine bn2 applied on load)
    conv5_bf16_kernel<16, 32, 32, 128, 2, 8, true, false>
        <<<dim3(4, 16, 16), 256, smem_bytes(32, 2, 8)>>>(t3, aff + 2 * AOFF, k3, t4);
    stats_kernel<16384><<<16 * 32, 256>>>(t4, bns[3], bnb[3], aff + 3 * AOFF, 32);
    conv5_bf16_kernel<32, 32, 32, 128, 1, 16, true, true>
        <<<dim3(4, 8, 16), 256, smem_bytes(32, 1, 16)>>>(t4, aff + 3 * AOFF, k4, t5);
    stats_kernel<16384><<<16 * 32, 256>>>(t5, bns[4], bnb[4], aff + 4 * AOFF, 32);
    // conv5 wide (CB=64)
    conv5_wide_kernel<32, 128, 2, false>
        <<<dim3(4, 16, 16), 256, wide_smem(2)>>>(t5, aff + 4 * AOFF, k5, t6);
    stats_kernel<16384><<<16 * 64, 256>>>(t6, bns[5], bnb[5], aff + 5 * AOFF, 64);
    // conv6 wide (CB=64)
    conv5_wide_kernel<64, 128, 1, true>
        <<<dim3(4, 16, 16), 256, wide_smem(1)>>>(t6, aff + 5 * AOFF, k6, t7);
    stats_kernel<16384><<<16 * 64, 256>>>(t7, bns[6], bnb[6], aff + 6 * AOFF, 64);
    conv1x1_kernel<<<dim3(64, 16), 256>>>(t7, aff + 6 * AOFF, k7, t8);
    up_add_kernel<<<(16 * 4 * 256 * 256 + 255) / 256, 256>>>(t8, x, (float*)d_out);
}

// round 14
// speedup vs baseline: 1.3810x; 1.1840x over previous
#include <cuda_runtime.h>
#include <cuda_bf16.h>
#include <cstdint>

#define EPS 1e-5f

// ---------------- scratch (static __device__ — no allocation) ----------------
__device__ uint2 g_k2[16 * 1 * 25 * 8 * 16];
__device__ uint2 g_k3[16 * 1 * 25 * 8 * 32];
__device__ uint2 g_k4[16 * 2 * 25 * 8 * 32];
__device__ uint2 g_k5[16 * 2 * 25 * 8 * 64];
__device__ uint4 g_c1[16 * 25 * 16 * 2];
__device__ float g_k7[16 * 4 * 64];

// conv6 int8 path
__device__ uint2 g_q6[16 * 2 * 25 * 64 * 8];       // weights: [b][ch][tap][co][8 uint2]
__device__ uint4 g_qa6[16 * 2 * 128 * 128 * 4];    // activations: [b][ch][y][x][4 uint4]
__device__ float g_sb6[16 * 64];                   // weight amax per (b,cout)
__device__ unsigned g_sa6[16];                     // activation amax per b (float bits)

__device__ float g_t1[16 * 16 * 256 * 256];
__device__ float g_t2[16 * 16 * 256 * 256];
__device__ float g_t3[16 * 16 * 128 * 128];
__device__ float g_t4[16 * 32 * 128 * 128];
__device__ float g_t5[16 * 32 * 128 * 128];
__device__ float g_t6[16 * 64 * 128 * 128];
__device__ float g_t7[16 * 64 * 128 * 128];
__device__ float g_t8[16 * 4 * 128 * 128];

__device__ float g_aff[7 * 16 * 64 * 2];  // BN affine [layer][b*C+c][2]
__device__ float g_st2[16 * 16 * 2];      // fused bn2 stats (sum, sumsq)

// ---------------- helpers ----------------
__device__ __forceinline__ uint32_t packbf(float a, float b) {
    __nv_bfloat162 h;
    h.x = __float2bfloat16(a);
    h.y = __float2bfloat16(b);
    return *reinterpret_cast<uint32_t*>(&h);
}

__device__ __forceinline__ uint2 bsplit2(float v0, float v1) {
    __nv_bfloat16 h0 = __float2bfloat16(v0);
    __nv_bfloat16 h1 = __float2bfloat16(v1);
    float l0 = v0 - __bfloat162float(h0);
    float l1 = v1 - __bfloat162float(h1);
    uint2 u;
    u.x = packbf(v0, v1);
    u.y = packbf(l0, l1);
    return u;
}

__device__ __forceinline__ void mma_bf16(float c[4], uint32_t a0, uint32_t a1, uint32_t a2,
                                         uint32_t a3, uint32_t b0, uint32_t b1) {
    asm volatile(
        "mma.sync.aligned.m16n8k16.row.col.f32.bf16.bf16.f32 "
        "{%0,%1,%2,%3},{%4,%5,%6,%7},{%8,%9},{%0,%1,%2,%3};"
        : "+f"(c[0]), "+f"(c[1]), "+f"(c[2]), "+f"(c[3])
        : "r"(a0), "r"(a1), "r"(a2), "r"(a3), "r"(b0), "r"(b1));
}

__device__ __forceinline__ void mma_bf16_k8(float c[4], uint32_t a0, uint32_t a1, uint32_t b0) {
    asm volatile(
        "mma.sync.aligned.m16n8k8.row.col.f32.bf16.bf16.f32 "
        "{%0,%1,%2,%3},{%4,%5},{%6},{%0,%1,%2,%3};"
        : "+f"(c[0]), "+f"(c[1]), "+f"(c[2]), "+f"(c[3])
        : "r"(a0), "r"(a1), "r"(b0));
}

__device__ __forceinline__ void mma_s8(int c[4], uint32_t a0, uint32_t a1, uint32_t a2,
                                       uint32_t a3, uint32_t b0, uint32_t b1) {
    asm volatile(
        "mma.sync.aligned.m16n8k32.row.col.s32.s8.s8.s32 "
        "{%0,%1,%2,%3},{%4,%5,%6,%7},{%8,%9},{%0,%1,%2,%3};"
        : "+r"(c[0]), "+r"(c[1]), "+r"(c[2]), "+r"(c[3])
        : "r"(a0), "r"(a1), "r"(a2), "r"(a3), "r"(b0), "r"(b1));
}

// ---------------- weight generation ----------------
__device__ __forceinline__ void gen_one(const float* __restrict__ w, const float* __restrict__ bias,
                                        const int* __restrict__ action, uint2* __restrict__ out,
                                        int CIN, int NCH, int COUT, int i) {
    int co = i % COUT;
    int r = i / COUT;
    int kp = r % 8;
    r /= 8;
    int tap = r % 25;
    r /= 25;
    int chv = r % NCH;
    int b = r / NCH;
    int a = action[b];
    int ci0 = chv * 16 + kp * 2;
    float v0 = 0.f, v1 = 0.f;
    if (ci0 < CIN) {
        int o = (co * CIN + ci0) * 25 + tap;
        v0 = w[o * 6 + a] + bias[o];
    }
    if (ci0 + 1 < CIN) {
        int o = (co * CIN + ci0 + 1) * 25 + tap;
        v1 = w[o * 6 + a] + bias[o];
    }
    out[i] = bsplit2(v0, v1);
}

__global__ void genA_kernel(const float* w2, const float* b2, const float* w3, const float* b3,
                            const float* w4, const float* b4, const float* w5, const float* b5,
                            const int* __restrict__ action, uint2* k2, uint2* k3, uint2* k4,
                            uint2* k5, float* st2, unsigned* sa6) {
    int i = blockIdx.x * 256 + threadIdx.x;
    if (i < 16 * 16 * 2) st2[i] = 0.f;
    if (i < 16) sa6[i] = 0u;
    if (i < 51200) gen_one(w2, b2, action, k2, 16, 1, 16, i);
    else if (i < 153600) gen_one(w3, b3, action, k3, 16, 1, 32, i - 51200);
    else if (i < 358400) gen_one(w4, b4, action, k4, 32, 2, 32, i - 153600);
    else if (i < 768000) gen_one(w5, b5, action, k5, 32, 2, 64, i - 358400);
}

// conv1 + conv7 weights
__global__ void genB_kernel(const float* w1, const float* b1, const float* w7, const float* b7,
                            const int* __restrict__ action, uint4* c1, float* k7) {
    int i = blockIdx.x * 256 + threadIdx.x;
    if (i < 12800) {
        int j = i;  // [b][tap][co][pass]
        int pass = j & 1;
        int r = j >> 1;
        int co = r & 15;
        r >>= 4;
        int tap = r % 25;
        int b = r / 25;
        int a = action[b];
        float h[4], l[4];
#pragma unroll
        for (int ci = 0; ci < 4; ci++) {
            int o = (co * 4 + ci) * 25 + tap;
            float v = w1[o * 6 + a] + b1[o];
            __nv_bfloat16 hb = __float2bfloat16(v);
            h[ci] = v;
            l[ci] = v - __bfloat162float(hb);
        }
        uint4 u;
        if (pass == 0) {
            u.x = packbf(h[0], h[1]);
            u.y = packbf(h[2], h[3]);
            u.z = u.x;
            u.w = u.y;
        } else {
            u.x = packbf(l[0], l[1]);
            u.y = packbf(l[2], l[3]);
            u.z = 0;
            u.w = 0;
        }
        c1[j] = u;
    } else if (i < 12800 + 4096) {
        int j = i - 12800;
        int b = j / 256, o = j - b * 256;
        k7[j] = w7[o * 6 + action[b]] + b7[o];
    }
}

// conv6 weight amax: block per (b, cout) over 64*25=1600 values
__global__ void genw6_amax_kernel(const float* __restrict__ w, const float* __restrict__ bias,
                                  const int* __restrict__ action, float* __restrict__ sb) {
    int bc = blockIdx.x;  // b*64 + co
    int b = bc >> 6, co = bc & 63;
    int a = action[b];
    float m = 0.f;
    for (int i = threadIdx.x; i < 1600; i += 256) {
        int o = co * 1600 + i;  // (co*64+ci)*25+tap == co*1600 + ci*25+tap
        m = fmaxf(m, fabsf(w[o * 6 + a] + bias[o]));
    }
    __shared__ float sm[256];
    sm[threadIdx.x] = m;
    __syncthreads();
    for (int st = 128; st > 0; st >>= 1) {
        if (threadIdx.x < st) sm[threadIdx.x] = fmaxf(sm[threadIdx.x], sm[threadIdx.x + st]);
        __syncthreads();
    }
    if (threadIdx.x == 0) sb[bc] = fmaxf(sm[0], 1e-20f);
}

// conv6 weight quantize: thread per uint2 of g_q6
__global__ void genw6_quant_kernel(const float* __restrict__ w, const float* __restrict__ bias,
                                   const int* __restrict__ action, const float* __restrict__ sb,
                                   uint2* __restrict__ q) {
    int idx = blockIdx.x * 256 + threadIdx.x;
    if (idx >= 16 * 2 * 25 * 64 * 8) return;
    int j = idx & 7;
    int r = idx >> 3;
    int co = r & 63;
    r >>= 6;
    int tap = r % 25;
    r /= 25;
    int ch = r & 1;
    int b = r >> 1;
    int a = action[b];
    float inv = 127.f / sb[b * 64 + co];
    int jj = j & 3;
    int is_l = j >> 2;
    uint32_t wd[2];
#pragma unroll
    for (int half = 0; half < 2; half++) {
        uint32_t pk = 0;
#pragma unroll
        for (int e = 0; e < 4; e++) {
            int k = half * 16 + jj * 4 + e;
            int ci = ch * 32 + k;
            int o = (co * 64 + ci) * 25 + tap;
            float v = w[o * 6 + a] + bias[o];
            float rr = v * inv;
            int qh = __float2int_rn(rr);
            qh = max(-127, min(127, qh));
            int byte;
            if (is_l) {
                int ql = __float2int_rn((rr - (float)qh) * 128.f);
                byte = max(-127, min(127, ql));
            } else {
                byte = qh;
            }
            pk |= ((uint32_t)(uint8_t)(int8_t)byte) << (e * 8);
        }
        wd[half] = pk;
    }
    q[idx] = make_uint2(wd[0], wd[1]);
}

// ---------------- per-(b,c) BN stats -> affine ----------------
template <int N>
__global__ void stats_kernel(const float* __restrict__ in, const float* __restrict__ s,
                             const float* __restrict__ bb, float* __restrict__ aff, int C) {
    int bc = blockIdx.x;
    const float* p = in + (size_t)bc * N;
    float sum = 0.f, sq = 0.f;
    for (int i = threadIdx.x; i < N; i += 256) {
        float v = p[i];
        sum += v;
        sq += v * v;
    }
    __shared__ float ssum[256], ssq[256];
    ssum[threadIdx.x] = sum;
    ssq[threadIdx.x] = sq;
    __syncthreads();
    for (int st = 128; st > 0; st >>= 1) {
        if (threadIdx.x < st) {
            ssum[threadIdx.x] += ssum[threadIdx.x + st];
            ssq[threadIdx.x] += ssq[threadIdx.x + st];
        }
        __syncthreads();
    }
    if (threadIdx.x == 0) {
        int c = bc % C;
        float mean = ssum[0] / (float)N;
        float var = ssq[0] / (float)N - mean * mean;
        float sc = rsqrtf(var + EPS) * s[c];
        aff[2 * bc] = sc;
        aff[2 * bc + 1] = bb[c] - mean * sc;
    }
}

// stats + relu-amax (for bn5 -> conv6 int8 activation scale)
template <int N>
__global__ void stats_amax_kernel(const float* __restrict__ in, const float* __restrict__ s,
                                  const float* __restrict__ bb, float* __restrict__ aff, int C,
                                  unsigned* __restrict__ sa) {
    int bc = blockIdx.x;
    const float* p = in + (size_t)bc * N;
    float sum = 0.f, sq = 0.f, mn = 1e30f, mx = -1e30f;
    for (int i = threadIdx.x; i < N; i += 256) {
        float v = p[i];
        sum += v;
        sq += v * v;
        mn = fminf(mn, v);
        mx = fmaxf(mx, v);
    }
    __shared__ float ssum[256], ssq[256], smn[256], smx[256];
    ssum[threadIdx.x] = sum;
    ssq[threadIdx.x] = sq;
    smn[threadIdx.x] = mn;
    smx[threadIdx.x] = mx;
    __syncthreads();
    for (int st = 128; st > 0; st >>= 1) {
        if (threadIdx.x < st) {
            ssum[threadIdx.x] += ssum[threadIdx.x + st];
            ssq[threadIdx.x] += ssq[threadIdx.x + st];
            smn[threadIdx.x] = fminf(smn[threadIdx.x], smn[threadIdx.x + st]);
            smx[threadIdx.x] = fmaxf(smx[threadIdx.x], smx[threadIdx.x + st]);
        }
        __syncthreads();
    }
    if (threadIdx.x == 0) {
        int c = bc % C, b = bc / C;
        float mean = ssum[0] / (float)N;
        float var = ssq[0] / (float)N - mean * mean;
        float sc = rsqrtf(var + EPS) * s[c];
        float bi = bb[c] - mean * sc;
        aff[2 * bc] = sc;
        aff[2 * bc + 1] = bi;
        float amax = fmaxf(0.f, fmaxf(smn[0] * sc + bi, smx[0] * sc + bi));
        atomicMax(sa + b, __float_as_uint(amax));
    }
}

// ---------------- finalize fused stats -> affine (bn2) ----------------
__global__ void fin_kernel(const float* __restrict__ st, const float* __restrict__ s,
                           const float* __restrict__ bb, float* __restrict__ aff, int C,
                           float invN) {
    int i = threadIdx.x;
    if (i >= C * 16) return;
    int b = i / C, c = i - b * C;
    float sum = st[(b * C + c) * 2];
    float sq = st[(b * C + c) * 2 + 1];
    float mean = sum * invN;
    float var = sq * invN - mean * mean;
    float sc = rsqrtf(var + EPS) * s[c];
    aff[2 * (b * C + c)] = sc;
    aff[2 * (b * C + c) + 1] = bb[c] - mean * sc;
}

// ---------------- conv6 activation quantize: relu(bn5(t6)) -> int8 h/l packed -------------
__global__ void quant6_act_kernel(const float* __restrict__ t6, const float* __restrict__ aff5,
                                  const unsigned* __restrict__ sa, uint4* __restrict__ qa) {
    int idx = blockIdx.x * 256 + threadIdx.x;  // [b][ch][pix]
    int pix = idx & 16383;
    int r = idx >> 14;
    int ch = r & 1;
    int b = r >> 1;
    float sA = __uint_as_float(sa[b]);
    float inv = (sA > 0.f) ? 127.f / sA : 0.f;
    const float* base = t6 + ((size_t)(b * 64 + ch * 32)) * 16384 + pix;
    const float* af = aff5 + (b * 64 + ch * 32) * 2;
    uint32_t Hw[8], Lw[8];
#pragma unroll
    for (int t = 0; t < 8; t++) {
        Hw[t] = 0;
        Lw[t] = 0;
    }
#pragma unroll
    for (int c = 0; c < 32; c++) {
        float v = fmaf(base[(size_t)c * 16384], __ldg(af + 2 * c), __ldg(af + 2 * c + 1));
        v = fmaxf(v, 0.f);
        float rr = v * inv;
        int qh = __float2int_rn(rr);
        qh = min(qh, 127);
        int ql = __float2int_rn((rr - (float)qh) * 128.f);
        ql = max(-127, min(127, ql));
        int wi = (c < 16) ? 2 * (c >> 2) : 2 * ((c - 16) >> 2) + 1;
        int sh = (c & 3) * 8;
        Hw[wi] |= ((uint32_t)(uint8_t)(int8_t)qh) << sh;
        Lw[wi] |= ((uint32_t)(uint8_t)(int8_t)ql) << sh;
    }
    uint4* dst = qa + (size_t)idx * 4;
    dst[0] = make_uint4(Hw[0], Hw[1], Hw[2], Hw[3]);
    dst[1] = make_uint4(Hw[4], Hw[5], Hw[6], Hw[7]);
    dst[2] = make_uint4(Lw[0], Lw[1], Lw[2], Lw[3]);
    dst[3] = make_uint4(Lw[4], Lw[5], Lw[6], Lw[7]);
}

// ---------------- conv6 int8: tile 32x4, warp = 16px x 64cout, dual s32 acc ----------------
__global__ __launch_bounds__(256, 2) void conv6_i8_kernel(const uint4* __restrict__ qa,
                                                          const uint2* __restrict__ qw,
                                                          const float* __restrict__ sb,
                                                          const unsigned* __restrict__ sa,
                                                          float* __restrict__ out) {
    const int H = 128;
    extern __shared__ uint2 sm2[];
    uint2* patch = sm2;               // 288 px * 8 uint2
    uint2* wt = sm2 + 288 * 8;        // 5*64*8 uint2
    float* sAB = (float*)(sm2 + 288 * 8 + 5 * 64 * 8);  // 64 floats

    int tid = threadIdx.x, wid = tid >> 5, lane = tid & 31;
    int tg = lane & 3, gid = lane >> 2;
    int yin = wid >> 1, xh = wid & 1;
    int bx0 = blockIdx.x * 32, by0 = blockIdx.y * 4, b = blockIdx.z;

    if (tid < 64) {
        float sA = __uint_as_float(sa[b]);
        sAB[tid] = sA * sb[b * 64 + tid] * (1.f / 16129.f);
    }

    int acch[8][4], accc[8][4];
#pragma unroll
    for (int nt = 0; nt < 8; nt++)
#pragma unroll
        for (int k = 0; k < 4; k++) {
            acch[nt][k] = 0;
            accc[nt][k] = 0;
        }

    for (int ch = 0; ch < 2; ch++) {
        __syncthreads();
        // patch fill: pure copy of pre-quantized data (zero pad halo)
        for (int p = tid; p < 288; p += 256) {
            int py = p / 36, px = p - py * 36;
            int gy = by0 - 2 + py, gx = bx0 - 2 + px;
            uint4* d4 = (uint4*)(patch + p * 8);
            if ((unsigned)gy < 128u && (unsigned)gx < 128u) {
                const uint4* s4 = qa + ((size_t)((b * 2 + ch) * 128 + gy) * 128 + gx) * 4;
                d4[0] = s4[0];
                d4[1] = s4[1];
                d4[2] = s4[2];
                d4[3] = s4[3];
            } else {
                uint4 z = make_uint4(0, 0, 0, 0);
                d4[0] = z;
                d4[1] = z;
                d4[2] = z;
                d4[3] = z;
            }
        }
        const uint2* wcb = qw + (size_t)(b * 2 + ch) * 25 * 64 * 8;
#pragma unroll 1
        for (int ky = 0; ky < 5; ky++) {
            __syncthreads();
            for (int i = tid; i < 5 * 64 * 8; i += 256) wt[i] = wcb[(size_t)ky * 5 * 64 * 8 + i];
            __syncthreads();
#pragma unroll
            for (int kx = 0; kx < 5; kx++) {
                int p = (yin + ky) * 36 + xh * 16 + gid + kx;
                uint2 Ah0 = patch[p * 8 + tg];
                uint2 Ah1 = patch[(p + 8) * 8 + tg];
                uint2 Al0 = patch[p * 8 + 4 + tg];
                uint2 Al1 = patch[(p + 8) * 8 + 4 + tg];
#pragma unroll
                for (int nt = 0; nt < 8; nt++) {
                    int co = nt * 8 + gid;
                    uint2 Bh = wt[(kx * 64 + co) * 8 + tg];
                    uint2 Bl = wt[(kx * 64 + co) * 8 + 4 + tg];
                    mma_s8(acch[nt], Ah0.x, Ah1.x, Ah0.y, Ah1.y, Bh.x, Bh.y);
                    mma_s8(accc[nt], Al0.x, Al1.x, Al0.y, Al1.y, Bh.x, Bh.y);
                    mma_s8(accc[nt], Ah0.x, Ah1.x, Ah0.y, Ah1.y, Bl.x, Bl.y);
                }
            }
        }
    }

    // epilogue: dequantize + store fp32
    int gy = by0 + yin, gx = bx0 + xh * 16 + gid;
#pragma unroll
    for (int nt = 0; nt < 8; nt++) {
        int co = nt * 8 + 2 * tg;
        float s0 = sAB[co], s1 = sAB[co + 1];
        float* o = out + ((size_t)(b * 64 + co) * H + gy) * H;
        o[gx] = s0 * fmaf((float)accc[nt][0], 0.0078125f, (float)acch[nt][0]);
        o[(size_t)H * H + gx] = s1 * fmaf((float)accc[nt][1], 0.0078125f, (float)acch[nt][1]);
        o[gx + 8] = s0 * fmaf((float)accc[nt][2], 0.0078125f, (float)acch[nt][2]);
        o[(size_t)H * H + gx + 8] = s1 * fmaf((float)accc[nt][3], 0.0078125f, (float)acch[nt][3]);
    }
}

// ---------------- conv1: CIN=4, k8 two-pass, 32x32 tile ----------------
__global__ __launch_bounds__(256, 2) void conv1_k8_kernel(const float* __restrict__ in,
                                                          const float* __restrict__ aff,
                                                          const uint4* __restrict__ wts,
                                                          float* __restrict__ out) {
    const int H = 256, R = 4;
    __shared__ uint4 patch[40 * 40];
    __shared__ uint4 wt[25 * 16 * 2];

    int tid = threadIdx.x, wid = tid >> 5, lane = tid & 31;
    int tg = lane & 3, gid = lane >> 2;
    int bx0 = blockIdx.x * 32, by0 = blockIdx.y * 32, b = blockIdx.z;

    const float* inb = in + (size_t)b * 4 * H * H;
    float s0 = aff[b * 8], bi0 = aff[b * 8 + 1];
    float s1 = aff[b * 8 + 2], bi1 = aff[b * 8 + 3];
    float s2 = aff[b * 8 + 4], bi2 = aff[b * 8 + 5];
    float s3 = aff[b * 8 + 6], bi3 = aff[b * 8 + 7];

    for (int idx = tid; idx < 40 * 40; idx += 256) {
        int py = idx / 40, px = idx - py * 40;
        int gy = by0 - R + py, gx = bx0 - R + px;
        float v0 = 0.f, v1 = 0.f, v2 = 0.f, v3 = 0.f;
        if ((unsigned)gy < 256u && (unsigned)gx < 256u) {
            size_t p0 = (size_t)gy * 256 + gx;
            v0 = fmaf(inb[p0], s0, bi0);
            v1 = fmaf(inb[p0 + 65536], s1, bi1);
            v2 = fmaf(inb[p0 + 131072], s2, bi2);
            v3 = fmaf(inb[p0 + 196608], s3, bi3);
        }
        __nv_bfloat16 h0 = __float2bfloat16(v0), h1 = __float2bfloat16(v1);
        __nv_bfloat16 h2 = __float2bfloat16(v2), h3 = __float2bfloat16(v3);
        uint4 u;
        u.x = packbf(v0, v1);
        u.y = packbf(v2, v3);
        u.z = packbf(v0 - __bfloat162float(h0), v1 - __bfloat162float(h1));
        u.w = packbf(v2 - __bfloat162float(h2), v3 - __bfloat162float(h3));
        patch[idx] = u;
    }
    const uint4* wb = wts + (size_t)b * 800;
    for (int idx = tid; idx < 800; idx += 256) wt[idx] = wb[idx];
    __syncthreads();

    float acc[8][2][4];
#pragma unroll
    for (int mt = 0; mt < 8; mt++)
#pragma unroll
        for (int nt = 0; nt < 2; nt++)
#pragma unroll
            for (int k = 0; k < 4; k++) acc[mt][nt][k] = 0.f;

    const uint32_t* pu = reinterpret_cast<const uint32_t*>(patch);
    const uint32_t* wu = reinterpret_cast<const uint32_t*>(wt);

#pragma unroll
    for (int ky = 0; ky < 5; ky++) {
#pragma unroll
        for (int kx = 0; kx < 5; kx++) {
            int tap = ky * 5 + kx;
            uint32_t breg[2][2];
#pragma unroll
            for (int nt = 0; nt < 2; nt++)
#pragma unroll
                for (int ps = 0; ps < 2; ps++)
                    breg[nt][ps] = wu[(((tap * 16 + nt * 8 + gid) * 2) + ps) * 4 + tg];
#pragma unroll
            for (int mt = 0; mt < 8; mt++) {
                int r = mt >> 1, hx = mt & 1;
                int p = (wid * 4 + r + ky * 2) * 40 + hx * 16 + gid + kx * 2;
                uint32_t a0 = pu[p * 4 + tg];
                uint32_t a1 = pu[(p + 8) * 4 + tg];
#pragma unroll
                for (int nt = 0; nt < 2; nt++) {
                    mma_bf16_k8(acc[mt][nt], a0, a1, breg[nt][0]);
                    mma_bf16_k8(acc[mt][nt], a0, a1, breg[nt][1]);
                }
            }
        }
    }

#pragma unroll
    for (int mt = 0; mt < 8; mt++) {
        int r = mt >> 1, hx = mt & 1;
        int gy = by0 + wid * 4 + r;
        int gx = bx0 + hx * 16 + gid;
#pragma unroll
        for (int nt = 0; nt < 2; nt++) {
            int co = nt * 8 + 2 * tg;
            float* o = out + ((size_t)(b * 16 + co) * H + gy) * H;
            o[gx] = acc[mt][nt][0];
            o[(size_t)H * H + gx] = acc[mt][nt][1];
            o[gx + 8] = acc[mt][nt][2];
            o[(size_t)H * H + gx + 8] = acc[mt][nt][3];
        }
    }
}

// ---------------- bf16x3 tensor-core 5x5 conv (conv2..4) ----------------
template <int CIN, int COUT, int COUT_B, int H, int DIL, int TH, bool AFF, bool RELU>
__global__ __launch_bounds__(256, 2) void conv5_bf16_kernel(const float* __restrict__ in,
                                                            const float* __restrict__ aff,
                                                            const uint2* __restrict__ wts,
                                                            float* __restrict__ out) {
    constexpr int R = 2 * DIL;
    constexpr int PX = 32 + 2 * R;
    constexpr int PY = TH + 2 * R;
    constexpr int PLANE0 = PX * PY;
    constexpr int PS = PLANE0 + ((4 - PLANE0 % 16) + 16) % 16;
    constexpr int WS = COUT_B + 4;
    constexpr int NT = COUT_B / 8;
    constexpr int MT = (TH / 8) * 2;
    constexpr int RPW = TH / 8;
    constexpr int CGRP = COUT / COUT_B;
    constexpr int CINPAD = (CIN + 15) & ~15;
    constexpr int NCH = CINPAD / 16;

    extern __shared__ uint2 sm[];
    uint2* wtile = sm;
    uint2* patch = sm + 25 * 8 * WS;

    int tid = threadIdx.x, wid = tid >> 5, lane = tid & 31;
    int tg = lane & 3, gid = lane >> 2;
    int bx0 = blockIdx.x * 32;
    int ytile = blockIdx.y / CGRP;
    int cg = blockIdx.y % CGRP;
    int by0 = ytile * TH;
    int b = blockIdx.z;
    int co0 = cg * COUT_B;

    const float* inb = in + (size_t)b * CIN * H * H;
    const float* affb = aff + b * CIN * 2;
    const uint2* wb = wts + ((size_t)b * NCH * 25 * 8) * COUT + co0;

    float acc[MT][NT][4];
#pragma unroll
    for (int mt = 0; mt < MT; mt++)
#pragma unroll
        for (int nt = 0; nt < NT; nt++)
#pragma unroll
            for (int k = 0; k < 4; k++) acc[mt][nt][k] = 0.f;

    int baseA[MT];
#pragma unroll
    for (int mt = 0; mt < MT; mt++) {
        int rofs = (MT == 4) ? (mt >> 1) : 0;
        int pxo = ((MT == 4) ? (mt & 1) : mt) * 16;
        baseA[mt] = tg * PS + (wid * RPW + rofs) * PX + pxo + gid;
    }

    for (int ch = 0; ch < NCH; ch++) {
        __syncthreads();
        for (int idx = tid; idx < 8 * PLANE0; idx += 256) {
            int p = idx / PLANE0;
            int rem = idx - p * PLANE0;
            int py = rem / PX, px = rem - py * PX;
            int gy = by0 - R + py, gx = bx0 - R + px;
            int c0 = ch * 16 + 2 * p;
            float v0 = 0.f, v1 = 0.f;
            if ((unsigned)gy < (unsigned)H && (unsigned)gx < (unsigned)H) {
                if (c0 < CIN) {
                    v0 = inb[((size_t)c0 * H + gy) * H + gx];
                    if (AFF) {
                        v0 = fmaf(v0, __ldg(affb + 2 * c0), __ldg(affb + 2 * c0 + 1));
                        if (RELU) v0 = fmaxf(v0, 0.f);
                    }
                }
                if (c0 + 1 < CIN) {
                    v1 = inb[((size_t)(c0 + 1) * H + gy) * H + gx];
                    if (AFF) {
                        v1 = fmaf(v1, __ldg(affb + 2 * c0 + 2), __ldg(affb + 2 * c0 + 3));
                        if (RELU) v1 = fmaxf(v1, 0.f);
                    }
                }
            }
            patch[p * PS + py * PX + px] = bsplit2(v0, v1);
        }
        const uint2* wc = wb + (size_t)ch * 25 * 8 * COUT;
        for (int idx = tid; idx < 25 * 8 * COUT_B; idx += 256) {
            int t8 = idx / COUT_B;
            int co = idx - t8 * COUT_B;
            wtile[t8 * WS + co] = wc[(size_t)t8 * COUT + co];
        }
        __syncthreads();

#pragma unroll
        for (int ky = 0; ky < 5; ky++) {
#pragma unroll
            for (int kx = 0; kx < 5; kx++) {
                const uint2* wt = wtile + (ky * 5 + kx) * 8 * WS;
                uint2 Bf[NT][2];
#pragma unroll
                for (int nt = 0; nt < NT; nt++) {
                    Bf[nt][0] = wt[tg * WS + nt * 8 + gid];
                    Bf[nt][1] = wt[(tg + 4) * WS + nt * 8 + gid];
                }
#pragma unroll
                for (int mt = 0; mt < MT; mt++) {
                    int ao = baseA[mt] + ky * DIL * PX + kx * DIL;
                    uint2 A0 = patch[ao];
                    uint2 A1 = patch[ao + 8];
                    uint2 A2 = patch[ao + 4 * PS];
                    uint2 A3 = patch[ao + 4 * PS + 8];
#pragma unroll
                    for (int nt = 0; nt < NT; nt++) {
                        mma_bf16(acc[mt][nt], A0.x, A1.x, A2.x, A3.x, Bf[nt][0].x, Bf[nt][1].x);
                        mma_bf16(acc[mt][nt], A0.x, A1.x, A2.x, A3.x, Bf[nt][0].y, Bf[nt][1].y);
                        mma_bf16(acc[mt][nt], A0.y, A1.y, A2.y, A3.y, Bf[nt][0].x, Bf[nt][1].x);
                    }
                }
            }
        }
    }

#pragma unroll
    for (int mt = 0; mt < MT; mt++) {
        int rofs = (MT == 4) ? (mt >> 1) : 0;
        int pxo = ((MT == 4) ? (mt & 1) : mt) * 16;
        int gy = by0 + wid * RPW + rofs;
        int gx = bx0 + pxo + gid;
#pragma unroll
        for (int nt = 0; nt < NT; nt++) {
            int co = co0 + nt * 8 + 2 * tg;
            float* o = out + ((size_t)(b * COUT + co) * H + gy) * H;
            o[gx] = acc[mt][nt][0];
            o[(size_t)H * H + gx] = acc[mt][nt][1];
            o[gx + 8] = acc[mt][nt][2];
            o[(size_t)H * H + gx + 8] = acc[mt][nt][3];
        }
    }
}

// ---------------- wide conv (COUT_B=64, TH=8): conv5 ----------------
template <int CIN, int H, int DIL, bool RELU>
__global__ __launch_bounds__(256, 2) void conv5_wide_kernel(const float* __restrict__ in,
                                                            const float* __restrict__ aff,
                                                            const uint2* __restrict__ wts,
                                                            float* __restrict__ out) {
    constexpr int R = 2 * DIL;
    constexpr int PX = 32 + 2 * R;
    constexpr int PY = 8 + 2 * R;
    constexpr int PLANE0 = PX * PY;
    constexpr int PS = PLANE0 + ((4 - PLANE0 % 16) + 16) % 16;
    constexpr int WS = 68;
    constexpr int NCH = CIN / 16;

    extern __shared__ uint2 sm[];
    uint2* wtile = sm;
    uint2* patch = sm + 5 * 8 * WS;

    int tid = threadIdx.x, wid = tid >> 5, lane = tid & 31;
    int tg = lane & 3, gid = lane >> 2;
    int bx0 = blockIdx.x * 32;
    int by0 = blockIdx.y * 8;
    int b = blockIdx.z;

    const float* inb = in + (size_t)b * CIN * H * H;
    const float* affb = aff + b * CIN * 2;
    const uint2* wb = wts + ((size_t)b * NCH * 25 * 8) * 64;

    float acc[2][8][4];
#pragma unroll
    for (int mt = 0; mt < 2; mt++)
#pragma unroll
        for (int nt = 0; nt < 8; nt++)
#pragma unroll
            for (int k = 0; k < 4; k++) acc[mt][nt][k] = 0.f;

    int baseA0 = tg * PS + wid * PX + gid;

    for (int ch = 0; ch < NCH; ch++) {
        __syncthreads();
        for (int idx = tid; idx < 8 * PLANE0; idx += 256) {
            int p = idx / PLANE0;
            int rem = idx - p * PLANE0;
            int py = rem / PX, px = rem - py * PX;
            int gy = by0 - R + py, gx = bx0 - R + px;
            int c0 = ch * 16 + 2 * p;
            float v0 = 0.f, v1 = 0.f;
            if ((unsigned)gy < (unsigned)H && (unsigned)gx < (unsigned)H) {
                v0 = fmaf(inb[((size_t)c0 * H + gy) * H + gx], __ldg(affb + 2 * c0),
                          __ldg(affb + 2 * c0 + 1));
                v1 = fmaf(inb[((size_t)(c0 + 1) * H + gy) * H + gx], __ldg(affb + 2 * c0 + 2),
                          __ldg(affb + 2 * c0 + 3));
                if (RELU) {
                    v0 = fmaxf(v0, 0.f);
                    v1 = fmaxf(v1, 0.f);
                }
            }
            patch[p * PS + py * PX + px] = bsplit2(v0, v1);
        }
        const uint2* wc = wb + (size_t)ch * 25 * 8 * 64;
#pragma unroll 1
        for (int ky = 0; ky < 5; ky++) {
            __syncthreads();
            for (int idx = tid; idx < 5 * 8 * 64; idx += 256) {
                int kx = idx >> 9;
                int rem = idx & 511;
                int kp = rem >> 6;
                int co = rem & 63;
                wtile[(kx * 8 + kp) * WS + co] = wc[((ky * 5 + kx) * 8 + kp) * 64 + co];
            }
            __syncthreads();
#pragma unroll
            for (int kx = 0; kx < 5; kx++) {
                uint2 A[2][4];
#pragma unroll
                for (int mt = 0; mt < 2; mt++) {
                    int ao = baseA0 + mt * 16 + ky * DIL * PX + kx * DIL;
                    A[mt][0] = patch[ao];
                    A[mt][1] = patch[ao + 8];
                    A[mt][2] = patch[ao + 4 * PS];
                    A[mt][3] = patch[ao + 4 * PS + 8];
                }
                const uint2* wt = wtile + kx * 8 * WS;
#pragma unroll
                for (int nt = 0; nt < 8; nt++) {
                    uint2 B0 = wt[tg * WS + nt * 8 + gid];
                    uint2 B1 = wt[(tg + 4) * WS + nt * 8 + gid];
#pragma unroll
                    for (int mt = 0; mt < 2; mt++) {
                        mma_bf16(acc[mt][nt], A[mt][0].x, A[mt][1].x, A[mt][2].x, A[mt][3].x,
                                 B0.x, B1.x);
                        mma_bf16(acc[mt][nt], A[mt][0].x, A[mt][1].x, A[mt][2].x, A[mt][3].x,
                                 B0.y, B1.y);
                        mma_bf16(acc[mt][nt], A[mt][0].y, A[mt][1].y, A[mt][2].y, A[mt][3].y,
                                 B0.x, B1.x);
                    }
                }
            }
        }
    }

    int gy = by0 + wid;
#pragma unroll
    for (int mt = 0; mt < 2; mt++) {
        int gx = bx0 + mt * 16 + gid;
#pragma unroll
        for (int nt = 0; nt < 8; nt++) {
            int co = nt * 8 + 2 * tg;
            float* o = out + ((size_t)(b * 64 + co) * H + gy) * H;
            o[gx] = acc[mt][nt][0];
            o[(size_t)H * H + gx] = acc[mt][nt][1];
            o[gx + 8] = acc[mt][nt][2];
            o[(size_t)H * H + gx + 8] = acc[mt][nt][3];
        }
    }
}

// ---------------- avgpool (raw mean) + fused bn2 stats ----------------
__global__ void avgpool_stats_kernel(const float* __restrict__ in, float* __restrict__ out,
                                     float* __restrict__ st) {
    int idx = blockIdx.x * 256 + threadIdx.x;
    int x = idx & 127;
    int y = (idx >> 7) & 127;
    int bc = idx >> 14;
    const float* p = in + ((size_t)bc * 256 + 2 * y) * 256 + 2 * x;
    float v0 = p[0], v1 = p[1], v2 = p[256], v3 = p[257];
    out[idx] = (v0 + v1 + v2 + v3) * 0.25f;
    float s = v0 + v1 + v2 + v3;
    float q = v0 * v0 + v1 * v1 + v2 * v2 + v3 * v3;
    __shared__ float ss[256], sq[256];
    ss[threadIdx.x] = s;
    sq[threadIdx.x] = q;
    __syncthreads();
    for (int stp = 128; stp > 0; stp >>= 1) {
        if (threadIdx.x < stp) {
            ss[threadIdx.x] += ss[threadIdx.x + stp];
            sq[threadIdx.x] += sq[threadIdx.x + stp];
        }
        __syncthreads();
    }
    if (threadIdx.x == 0) {
        atomicAdd(st + bc * 2, ss[0]);
        atomicAdd(st + bc * 2 + 1, sq[0]);
    }
}

// ---------------- 1x1 conv + bilinear residual ----------------
__global__ __launch_bounds__(256) void conv1x1_kernel(const float* __restrict__ in,
                                                      const float* __restrict__ aff,
                                                      const float* __restrict__ wts,
                                                      float* __restrict__ out) {
    int b = blockIdx.y;
    int p = blockIdx.x * 256 + threadIdx.x;
    __shared__ float wsh[4][64];
    __shared__ float sc[64], bi[64];
    int tid = threadIdx.x;
    wsh[tid >> 6][tid & 63] = wts[b * 256 + tid];
    if (tid < 64) {
        sc[tid] = aff[(b * 64 + tid) * 2];
        bi[tid] = aff[(b * 64 + tid) * 2 + 1];
    }
    __syncthreads();
    float acc[4] = {0.f, 0.f, 0.f, 0.f};
    const float* pin = in + (size_t)b * 64 * 16384 + p;
#pragma unroll 8
    for (int ci = 0; ci < 64; ci++) {
        float v = fmaf(pin[(size_t)ci * 16384], sc[ci], bi[ci]);
#pragma unroll
        for (int co = 0; co < 4; co++) acc[co] = fmaf(v, wsh[co][ci], acc[co]);
    }
#pragma unroll
    for (int co = 0; co < 4; co++) out[((size_t)b * 4 + co) * 16384 + p] = acc[co];
}

__global__ void up_add_kernel(const float* __restrict__ in, const float* __restrict__ x,
                              float* __restrict__ out) {
    int idx = blockIdx.x * 256 + threadIdx.x;
    if (idx >= 16 * 4 * 256 * 256) return;
    int ox = idx & 255;
    int oy = (idx >> 8) & 255;
    int bc = idx >> 16;
    const float r = (float)(127.0 / 255.0);
    float px = ox * r, py = oy * r;
    int x0 = (int)px, y0 = (int)py;
    float fx = px - x0, fy = py - y0;
    int x1 = min(x0 + 1, 127), y1 = min(y0 + 1, 127);
    const float* p = in + (size_t)bc * 16384;
    float v00 = p[y0 * 128 + x0], v01 = p[y0 * 128 + x1];
    float v10 = p[y1 * 128 + x0], v11 = p[y1 * 128 + x1];
    float v0 = v00 * (1.f - fx) + v01 * fx;
    float v1 = v10 * (1.f - fx) + v11 * fx;
    out[idx] = v0 * (1.f - fy) + v1 * fy + x[idx];
}

// ---------------- host-side smem size mirrors ----------------
static int smem_bytes(int COUT_B, int DIL, int TH) {
    int R = 2 * DIL;
    int PX = 32 + 2 * R, PY = TH + 2 * R;
    int PLANE0 = PX * PY;
    int PS = PLANE0 + ((4 - PLANE0 % 16) + 16) % 16;
    return (25 * 8 * (COUT_B + 4) + 8 * PS) * 8;
}
static int wide_smem(int DIL) {
    int R = 2 * DIL;
    int PX = 32 + 2 * R, PY = 8 + 2 * R;
    int PLANE0 = PX * PY;
    int PS = PLANE0 + ((4 - PLANE0 % 16) + 16) % 16;
    return (5 * 8 * 68 + 8 * PS) * 8;
}
static int i8_smem() { return (288 * 8 + 5 * 64 * 8) * 8 + 64 * 4; }

// ---------------- launch ----------------
extern "C" void kernel_launch(void* const* d_in, const int* in_sizes, int n_in,
                              void* d_out, int out_size) {
    const float* x = (const float*)d_in[0];
    const int* action = (const int*)d_in[1];
    const float* w[7];
    const float* wb[7];
    for (int i = 0; i < 7; i++) {
        w[i] = (const float*)d_in[2 + 2 * i];
        wb[i] = (const float*)d_in[3 + 2 * i];
    }
    const float* bns[7];
    const float* bnb[7];
    for (int i = 0; i < 7; i++) {
        bns[i] = (const float*)d_in[16 + 2 * i];
        bnb[i] = (const float*)d_in[17 + 2 * i];
    }

    uint2 *k2, *k3, *k4, *k5, *q6;
    uint4 *c1, *qa6;
    float *k7, *sb6;
    unsigned* sa6;
    float *t1, *t2, *t3, *t4, *t5, *t6, *t7, *t8, *aff, *st2;
    cudaGetSymbolAddress((void**)&k2, g_k2);
    cudaGetSymbolAddress((void**)&k3, g_k3);
    cudaGetSymbolAddress((void**)&k4, g_k4);
    cudaGetSymbolAddress((void**)&k5, g_k5);
    cudaGetSymbolAddress((void**)&q6, g_q6);
    cudaGetSymbolAddress((void**)&qa6, g_qa6);
    cudaGetSymbolAddress((void**)&sb6, g_sb6);
    cudaGetSymbolAddress((void**)&sa6, g_sa6);
    cudaGetSymbolAddress((void**)&c1, g_c1);
    cudaGetSymbolAddress((void**)&k7, g_k7);
    cudaGetSymbolAddress((void**)&t1, g_t1);
    cudaGetSymbolAddress((void**)&t2, g_t2);
    cudaGetSymbolAddress((void**)&t3, g_t3);
    cudaGetSymbolAddress((void**)&t4, g_t4);
    cudaGetSymbolAddress((void**)&t5, g_t5);
    cudaGetSymbolAddress((void**)&t6, g_t6);
    cudaGetSymbolAddress((void**)&t7, g_t7);
    cudaGetSymbolAddress((void**)&t8, g_t8);
    cudaGetSymbolAddress((void**)&aff, g_aff);
    cudaGetSymbolAddress((void**)&st2, g_st2);

    const int AOFF = 16 * 64 * 2;

    cudaFuncSetAttribute(conv5_bf16_kernel<16, 16, 16, 256, 1, 16, true, true>,
                         cudaFuncAttributeMaxDynamicSharedMemorySize, smem_bytes(16, 1, 16));
    cudaFuncSetAttribute(conv5_bf16_kernel<16, 32, 32, 128, 2, 8, true, false>,
                         cudaFuncAttributeMaxDynamicSharedMemorySize, smem_bytes(32, 2, 8));
    cudaFuncSetAttribute(conv5_bf16_kernel<32, 32, 32, 128, 1, 16, true, true>,
                         cudaFuncAttributeMaxDynamicSharedMemorySize, smem_bytes(32, 1, 16));
    cudaFuncSetAttribute(conv5_wide_kernel<32, 128, 2, false>,
                         cudaFuncAttributeMaxDynamicSharedMemorySize, wide_smem(2));
    cudaFuncSetAttribute(conv6_i8_kernel, cudaFuncAttributeMaxDynamicSharedMemorySize, i8_smem());

    // weight gen (+ zero stats/scale buffers)
    genA_kernel<<<3000, 256>>>(w[1], wb[1], w[2], wb[2], w[3], wb[3], w[4], wb[4], action, k2, k3,
                               k4, k5, st2, sa6);
    genB_kernel<<<66, 256>>>(w[0], wb[0], w[6], wb[6], action, c1, k7);
    genw6_amax_kernel<<<1024, 256>>>(w[5], wb[5], action, sb6);
    genw6_quant_kernel<<<1600, 256>>>(w[5], wb[5], action, sb6, q6);
    // bn0 stats on x
    stats_kernel<65536><<<16 * 4, 256>>>(x, bns[0], bnb[0], aff + 0 * AOFF, 4);
    // conv1
    conv1_k8_kernel<<<dim3(8, 8, 16), 256>>>(x, aff + 0 * AOFF, c1, t1);
    // bn1 stats
    stats_kernel<65536><<<16 * 16, 256>>>(t1, bns[1], bnb[1], aff + 1 * AOFF, 16);
    // conv2
    conv5_bf16_kernel<16, 16, 16, 256, 1, 16, true, true>
        <<<dim3(8, 16, 16), 256, smem_bytes(16, 1, 16)>>>(t1, aff + 1 * AOFF, k2, t2);
    // avgpool + bn2 stats fused
    avgpool_stats_kernel<<<16384, 256>>>(t2, t3, st2);
    fin_kernel<<<1, 256>>>(st2, bns[2], bnb[2], aff + 2 * AOFF, 16, 1.f / 65536.f);
    // conv3
    conv5_bf16_kernel<16, 32, 32, 128, 2, 8, true, false>
        <<<dim3(4, 16, 16), 256, smem_bytes(32, 2, 8)>>>(t3, aff + 2 * AOFF, k3, t4);
    stats_kernel<16384><<<16 * 32, 256>>>(t4, bns[3], bnb[3], aff + 3 * AOFF, 32);
    conv5_bf16_kernel<32, 32, 32, 128, 1, 16, true, true>
        <<<dim3(4, 8, 16), 256, smem_bytes(32, 1, 16)>>>(t4, aff + 3 * AOFF, k4, t5);
    stats_kernel<16384><<<16 * 32, 256>>>(t5, bns[4], bnb[4], aff + 4 * AOFF, 32);
    // conv5 wide
    conv5_wide_kernel<32, 128, 2, false>
        <<<dim3(4, 16, 16), 256, wide_smem(2)>>>(t5, aff + 4 * AOFF, k5, t6);
    // bn5 stats + activation amax
    stats_amax_kernel<16384><<<16 * 64, 256>>>(t6, bns[5], bnb[5], aff + 5 * AOFF, 64, sa6);
    // quantize conv6 activations
    quant6_act_kernel<<<2048, 256>>>(t6, aff + 5 * AOFF, sa6, qa6);
    // conv6 int8
    conv6_i8_kernel<<<dim3(4, 32, 16), 256, i8_smem()>>>(qa6, q6, sb6, sa6, t7);
    stats_kernel<16384><<<16 * 64, 256>>>(t7, bns[6], bnb[6], aff + 6 * AOFF, 64);
    conv1x1_kernel<<<dim3(64, 16), 256>>>(t7, aff + 6 * AOFF, k7, t8);
    up_add_kernel<<<(16 * 4 * 256 * 256 + 255) / 256, 256>>>(t8, x, (float*)d_out);
}

// round 15
// speedup vs baseline: 1.6001x; 1.1586x over previous
#include <cuda_runtime.h>
#include <cuda_bf16.h>
#include <cstdint>

#define EPS 1e-5f

// ---------------- scratch (static __device__ — no allocation) ----------------
__device__ uint2 g_k2[16 * 1 * 25 * 8 * 16];
__device__ uint2 g_k3[16 * 1 * 25 * 8 * 32];
__device__ uint4 g_c1[16 * 25 * 16 * 2];
__device__ float g_k7[16 * 4 * 64];

// int8 path (conv4, conv5, conv6)
__device__ uint2 g_q4[16 * 1 * 25 * 32 * 8];
__device__ uint2 g_q5[16 * 1 * 25 * 64 * 8];
__device__ uint2 g_q6[16 * 2 * 25 * 64 * 8];
__device__ uint4 g_qa4[16 * 1 * 128 * 128 * 4];
__device__ uint4 g_qa5[16 * 1 * 128 * 128 * 4];
__device__ uint4 g_qa6[16 * 2 * 128 * 128 * 4];
__device__ float g_sb4[16 * 32];
__device__ float g_sb5[16 * 64];
__device__ float g_sb6[16 * 64];
__device__ unsigned g_sa4[16];
__device__ unsigned g_sa5[16];
__device__ unsigned g_sa6[16];

__device__ float g_t1[16 * 16 * 256 * 256];
__device__ float g_t2[16 * 16 * 256 * 256];
__device__ float g_t3[16 * 16 * 128 * 128];
__device__ float g_t4[16 * 32 * 128 * 128];
__device__ float g_t5[16 * 32 * 128 * 128];
__device__ float g_t6[16 * 64 * 128 * 128];
__device__ float g_t7[16 * 64 * 128 * 128];
__device__ float g_t8[16 * 4 * 128 * 128];

__device__ float g_aff[7 * 16 * 64 * 2];
__device__ float g_st2[16 * 16 * 2];

// ---------------- helpers ----------------
__device__ __forceinline__ uint32_t packbf(float a, float b) {
    __nv_bfloat162 h;
    h.x = __float2bfloat16(a);
    h.y = __float2bfloat16(b);
    return *reinterpret_cast<uint32_t*>(&h);
}

__device__ __forceinline__ uint2 bsplit2(float v0, float v1) {
    __nv_bfloat16 h0 = __float2bfloat16(v0);
    __nv_bfloat16 h1 = __float2bfloat16(v1);
    float l0 = v0 - __bfloat162float(h0);
    float l1 = v1 - __bfloat162float(h1);
    uint2 u;
    u.x = packbf(v0, v1);
    u.y = packbf(l0, l1);
    return u;
}

__device__ __forceinline__ void mma_bf16(float c[4], uint32_t a0, uint32_t a1, uint32_t a2,
                                         uint32_t a3, uint32_t b0, uint32_t b1) {
    asm volatile(
        "mma.sync.aligned.m16n8k16.row.col.f32.bf16.bf16.f32 "
        "{%0,%1,%2,%3},{%4,%5,%6,%7},{%8,%9},{%0,%1,%2,%3};"
        : "+f"(c[0]), "+f"(c[1]), "+f"(c[2]), "+f"(c[3])
        : "r"(a0), "r"(a1), "r"(a2), "r"(a3), "r"(b0), "r"(b1));
}

__device__ __forceinline__ void mma_bf16_k8(float c[4], uint32_t a0, uint32_t a1, uint32_t b0) {
    asm volatile(
        "mma.sync.aligned.m16n8k8.row.col.f32.bf16.bf16.f32 "
        "{%0,%1,%2,%3},{%4,%5},{%6},{%0,%1,%2,%3};"
        : "+f"(c[0]), "+f"(c[1]), "+f"(c[2]), "+f"(c[3])
        : "r"(a0), "r"(a1), "r"(b0));
}

__device__ __forceinline__ void mma_s8(int c[4], uint32_t a0, uint32_t a1, uint32_t a2,
                                       uint32_t a3, uint32_t b0, uint32_t b1) {
    asm volatile(
        "mma.sync.aligned.m16n8k32.row.col.s32.s8.s8.s32 "
        "{%0,%1,%2,%3},{%4,%5,%6,%7},{%8,%9},{%0,%1,%2,%3};"
        : "+r"(c[0]), "+r"(c[1]), "+r"(c[2]), "+r"(c[3])
        : "r"(a0), "r"(a1), "r"(a2), "r"(a3), "r"(b0), "r"(b1));
}

// ---------------- weight generation ----------------
__device__ __forceinline__ void gen_one(const float* __restrict__ w, const float* __restrict__ bias,
                                        const int* __restrict__ action, uint2* __restrict__ out,
                                        int CIN, int NCH, int COUT, int i) {
    int co = i % COUT;
    int r = i / COUT;
    int kp = r % 8;
    r /= 8;
    int tap = r % 25;
    r /= 25;
    int chv = r % NCH;
    int b = r / NCH;
    int a = action[b];
    int ci0 = chv * 16 + kp * 2;
    float v0 = 0.f, v1 = 0.f;
    if (ci0 < CIN) {
        int o = (co * CIN + ci0) * 25 + tap;
        v0 = w[o * 6 + a] + bias[o];
    }
    if (ci0 + 1 < CIN) {
        int o = (co * CIN + ci0 + 1) * 25 + tap;
        v1 = w[o * 6 + a] + bias[o];
    }
    out[i] = bsplit2(v0, v1);
}

__global__ void genA_kernel(const float* w2, const float* b2, const float* w3, const float* b3,
                            const int* __restrict__ action, uint2* k2, uint2* k3, float* st2,
                            unsigned* sa4, unsigned* sa5, unsigned* sa6) {
    int i = blockIdx.x * 256 + threadIdx.x;
    if (i < 16 * 16 * 2) st2[i] = 0.f;
    if (i < 16) {
        sa4[i] = 0u;
        sa5[i] = 0u;
        sa6[i] = 0u;
    }
    if (i < 51200) gen_one(w2, b2, action, k2, 16, 1, 16, i);
    else if (i < 153600) gen_one(w3, b3, action, k3, 16, 1, 32, i - 51200);
}

__global__ void genB_kernel(const float* w1, const float* b1, const float* w7, const float* b7,
                            const int* __restrict__ action, uint4* c1, float* k7) {
    int i = blockIdx.x * 256 + threadIdx.x;
    if (i < 12800) {
        int j = i;
        int pass = j & 1;
        int r = j >> 1;
        int co = r & 15;
        r >>= 4;
        int tap = r % 25;
        int b = r / 25;
        int a = action[b];
        float h[4], l[4];
#pragma unroll
        for (int ci = 0; ci < 4; ci++) {
            int o = (co * 4 + ci) * 25 + tap;
            float v = w1[o * 6 + a] + b1[o];
            __nv_bfloat16 hb = __float2bfloat16(v);
            h[ci] = v;
            l[ci] = v - __bfloat162float(hb);
        }
        uint4 u;
        if (pass == 0) {
            u.x = packbf(h[0], h[1]);
            u.y = packbf(h[2], h[3]);
            u.z = u.x;
            u.w = u.y;
        } else {
            u.x = packbf(l[0], l[1]);
            u.y = packbf(l[2], l[3]);
            u.z = 0;
            u.w = 0;
        }
        c1[j] = u;
    } else if (i < 12800 + 4096) {
        int j = i - 12800;
        int b = j / 256, o = j - b * 256;
        k7[j] = w7[o * 6 + action[b]] + b7[o];
    }
}

// int8 weight amax: block per (b, cout), reduce over CIN*25
__global__ void gi8_amax_kernel(const float* __restrict__ w, const float* __restrict__ bias,
                                const int* __restrict__ action, float* __restrict__ sb, int CIN,
                                int COUT) {
    int bc = blockIdx.x;
    int b = bc / COUT, co = bc - b * COUT;
    int a = action[b];
    int K = CIN * 25;
    float m = 0.f;
    for (int i = threadIdx.x; i < K; i += 256) {
        int o = co * K + i;
        m = fmaxf(m, fabsf(w[o * 6 + a] + bias[o]));
    }
    __shared__ float sm[256];
    sm[threadIdx.x] = m;
    __syncthreads();
    for (int st = 128; st > 0; st >>= 1) {
        if (threadIdx.x < st) sm[threadIdx.x] = fmaxf(sm[threadIdx.x], sm[threadIdx.x + st]);
        __syncthreads();
    }
    if (threadIdx.x == 0) sb[bc] = fmaxf(sm[0], 1e-20f);
}

// int8 weight quantize: layout [b][ch][tap][co][8 uint2]
__global__ void gi8_quant_kernel(const float* __restrict__ w, const float* __restrict__ bias,
                                 const int* __restrict__ action, const float* __restrict__ sb,
                                 uint2* __restrict__ q, int CIN, int COUT) {
    int NCH = CIN / 32;
    int total = 16 * NCH * 25 * COUT * 8;
    int idx = blockIdx.x * 256 + threadIdx.x;
    if (idx >= total) return;
    int j = idx & 7;
    int r = idx >> 3;
    int co = r % COUT;
    r /= COUT;
    int tap = r % 25;
    r /= 25;
    int ch = r % NCH;
    int b = r / NCH;
    int a = action[b];
    float inv = 127.f / sb[b * COUT + co];
    int jj = j & 3;
    int is_l = j >> 2;
    uint32_t wd[2];
#pragma unroll
    for (int half = 0; half < 2; half++) {
        uint32_t pk = 0;
#pragma unroll
        for (int e = 0; e < 4; e++) {
            int k = half * 16 + jj * 4 + e;
            int ci = ch * 32 + k;
            int o = (co * CIN + ci) * 25 + tap;
            float v = w[o * 6 + a] + bias[o];
            float rr = v * inv;
            int qh = __float2int_rn(rr);
            qh = max(-127, min(127, qh));
            int byte;
            if (is_l) {
                int ql = __float2int_rn((rr - (float)qh) * 128.f);
                byte = max(-127, min(127, ql));
            } else {
                byte = qh;
            }
            pk |= ((uint32_t)(uint8_t)(int8_t)byte) << (e * 8);
        }
        wd[half] = pk;
    }
    q[idx] = make_uint2(wd[0], wd[1]);
}

// ---------------- BN stats ----------------
template <int N>
__global__ void stats_kernel(const float* __restrict__ in, const float* __restrict__ s,
                             const float* __restrict__ bb, float* __restrict__ aff, int C) {
    int bc = blockIdx.x;
    const float* p = in + (size_t)bc * N;
    float sum = 0.f, sq = 0.f;
    for (int i = threadIdx.x; i < N; i += 256) {
        float v = p[i];
        sum += v;
        sq += v * v;
    }
    __shared__ float ssum[256], ssq[256];
    ssum[threadIdx.x] = sum;
    ssq[threadIdx.x] = sq;
    __syncthreads();
    for (int st = 128; st > 0; st >>= 1) {
        if (threadIdx.x < st) {
            ssum[threadIdx.x] += ssum[threadIdx.x + st];
            ssq[threadIdx.x] += ssq[threadIdx.x + st];
        }
        __syncthreads();
    }
    if (threadIdx.x == 0) {
        int c = bc % C;
        float mean = ssum[0] / (float)N;
        float var = ssq[0] / (float)N - mean * mean;
        float sc = rsqrtf(var + EPS) * s[c];
        aff[2 * bc] = sc;
        aff[2 * bc + 1] = bb[c] - mean * sc;
    }
}

// stats + amax of post-affine (relu-clamped or abs) for int8 scales
template <int N>
__global__ void stats_amax_kernel(const float* __restrict__ in, const float* __restrict__ s,
                                  const float* __restrict__ bb, float* __restrict__ aff, int C,
                                  unsigned* __restrict__ sa, int relu) {
    int bc = blockIdx.x;
    const float* p = in + (size_t)bc * N;
    float sum = 0.f, sq = 0.f, mn = 1e30f, mx = -1e30f;
    for (int i = threadIdx.x; i < N; i += 256) {
        float v = p[i];
        sum += v;
        sq += v * v;
        mn = fminf(mn, v);
        mx = fmaxf(mx, v);
    }
    __shared__ float ssum[256], ssq[256], smn[256], smx[256];
    ssum[threadIdx.x] = sum;
    ssq[threadIdx.x] = sq;
    smn[threadIdx.x] = mn;
    smx[threadIdx.x] = mx;
    __syncthreads();
    for (int st = 128; st > 0; st >>= 1) {
        if (threadIdx.x < st) {
            ssum[threadIdx.x] += ssum[threadIdx.x + st];
            ssq[threadIdx.x] += ssq[threadIdx.x + st];
            smn[threadIdx.x] = fminf(smn[threadIdx.x], smn[threadIdx.x + st]);
            smx[threadIdx.x] = fmaxf(smx[threadIdx.x], smx[threadIdx.x + st]);
        }
        __syncthreads();
    }
    if (threadIdx.x == 0) {
        int c = bc % C, b = bc / C;
        float mean = ssum[0] / (float)N;
        float var = ssq[0] / (float)N - mean * mean;
        float sc = rsqrtf(var + EPS) * s[c];
        float bi = bb[c] - mean * sc;
        aff[2 * bc] = sc;
        aff[2 * bc + 1] = bi;
        float e0 = smn[0] * sc + bi, e1 = smx[0] * sc + bi;
        float hi = fmaxf(e0, e1), lo = fminf(e0, e1);
        float amax = relu ? fmaxf(0.f, hi) : fmaxf(fabsf(hi), fabsf(lo));
        atomicMax(sa + b, __float_as_uint(amax));
    }
}

__global__ void fin_kernel(const float* __restrict__ st, const float* __restrict__ s,
                           const float* __restrict__ bb, float* __restrict__ aff, int C,
                           float invN) {
    int i = threadIdx.x;
    if (i >= C * 16) return;
    int b = i / C, c = i - b * C;
    float sum = st[(b * C + c) * 2];
    float sq = st[(b * C + c) * 2 + 1];
    float mean = sum * invN;
    float var = sq * invN - mean * mean;
    float sc = rsqrtf(var + EPS) * s[c];
    aff[2 * (b * C + c)] = sc;
    aff[2 * (b * C + c) + 1] = bb[c] - mean * sc;
}

// ---------------- activation quantize: affine(+relu) -> int8 h/l packed ----------------
__global__ void quant_act_kernel(const float* __restrict__ t, const float* __restrict__ aff,
                                 const unsigned* __restrict__ sa, uint4* __restrict__ qa, int NCH,
                                 int relu) {
    int idx = blockIdx.x * 256 + threadIdx.x;  // [b][ch][pix]
    int pix = idx & 16383;
    int r = idx >> 14;
    int ch = r % NCH;
    int b = r / NCH;
    int C = NCH * 32;
    float sA = __uint_as_float(sa[b]);
    float inv = (sA > 0.f) ? 127.f / sA : 0.f;
    const float* base = t + ((size_t)(b * C + ch * 32)) * 16384 + pix;
    const float* af = aff + (b * C + ch * 32) * 2;
    uint32_t Hw[8], Lw[8];
#pragma unroll
    for (int k = 0; k < 8; k++) {
        Hw[k] = 0;
        Lw[k] = 0;
    }
#pragma unroll
    for (int c = 0; c < 32; c++) {
        float v = fmaf(base[(size_t)c * 16384], __ldg(af + 2 * c), __ldg(af + 2 * c + 1));
        if (relu) v = fmaxf(v, 0.f);
        float rr = v * inv;
        int qh = __float2int_rn(rr);
        qh = max(-127, min(127, qh));
        int ql = __float2int_rn((rr - (float)qh) * 128.f);
        ql = max(-127, min(127, ql));
        int wi = (c < 16) ? 2 * (c >> 2) : 2 * ((c - 16) >> 2) + 1;
        int sh = (c & 3) * 8;
        Hw[wi] |= ((uint32_t)(uint8_t)(int8_t)qh) << sh;
        Lw[wi] |= ((uint32_t)(uint8_t)(int8_t)ql) << sh;
    }
    uint4* dst = qa + (size_t)idx * 4;
    dst[0] = make_uint4(Hw[0], Hw[1], Hw[2], Hw[3]);
    dst[1] = make_uint4(Hw[4], Hw[5], Hw[6], Hw[7]);
    dst[2] = make_uint4(Lw[0], Lw[1], Lw[2], Lw[3]);
    dst[3] = make_uint4(Lw[4], Lw[5], Lw[6], Lw[7]);
}

// ---------------- int8x2 5x5 conv (conv4/5/6): tile 32x4, warp = 16px x COUT ----------------
template <int CIN, int COUT, int H, int DIL>
__global__ __launch_bounds__(256, 2) void conv_i8_kernel(const uint4* __restrict__ qa,
                                                         const uint2* __restrict__ qw,
                                                         const float* __restrict__ sb,
                                                         const unsigned* __restrict__ sa,
                                                         float* __restrict__ out) {
    constexpr int NCH = CIN / 32;
    constexpr int NT = COUT / 8;
    constexpr int R = 2 * DIL;
    constexpr int PXP = 32 + 2 * R;
    constexpr int PYP = 4 + 2 * R;
    constexpr int NPIX = PXP * PYP;

    extern __shared__ uint2 smq[];
    uint2* patch = smq;                 // NPIX * 8 uint2
    uint2* wt = smq + NPIX * 8;         // 5*COUT*8 uint2
    float* sAB = (float*)(smq + NPIX * 8 + 5 * COUT * 8);

    int tid = threadIdx.x, wid = tid >> 5, lane = tid & 31;
    int tg = lane & 3, gid = lane >> 2;
    int yin = wid >> 1, xh = wid & 1;
    int bx0 = blockIdx.x * 32, by0 = blockIdx.y * 4, b = blockIdx.z;

    if (tid < COUT) {
        float sA = __uint_as_float(sa[b]);
        sAB[tid] = sA * sb[b * COUT + tid] * (1.f / 16129.f);
    }

    int acch[NT][4], accc[NT][4];
#pragma unroll
    for (int nt = 0; nt < NT; nt++)
#pragma unroll
        for (int k = 0; k < 4; k++) {
            acch[nt][k] = 0;
            accc[nt][k] = 0;
        }

    for (int ch = 0; ch < NCH; ch++) {
        __syncthreads();
        for (int p = tid; p < NPIX; p += 256) {
            int py = p / PXP, px = p - py * PXP;
            int gy = by0 - R + py, gx = bx0 - R + px;
            uint4* d4 = (uint4*)(patch + p * 8);
            if ((unsigned)gy < (unsigned)H && (unsigned)gx < (unsigned)H) {
                const uint4* s4 = qa + ((size_t)((b * NCH + ch) * H + gy) * H + gx) * 4;
                d4[0] = s4[0];
                d4[1] = s4[1];
                d4[2] = s4[2];
                d4[3] = s4[3];
            } else {
                uint4 z = make_uint4(0, 0, 0, 0);
                d4[0] = z;
                d4[1] = z;
                d4[2] = z;
                d4[3] = z;
            }
        }
        const uint2* wcb = qw + ((size_t)(b * NCH + ch) * 25 * COUT) * 8;
#pragma unroll 1
        for (int ky = 0; ky < 5; ky++) {
            __syncthreads();
            for (int i = tid; i < 5 * COUT * 8; i += 256)
                wt[i] = wcb[(size_t)ky * 5 * COUT * 8 + i];
            __syncthreads();
#pragma unroll
            for (int kx = 0; kx < 5; kx++) {
                int p = (yin + ky * DIL) * PXP + xh * 16 + gid + kx * DIL;
                uint2 Ah0 = patch[p * 8 + tg];
                uint2 Ah1 = patch[(p + 8) * 8 + tg];
                uint2 Al0 = patch[p * 8 + 4 + tg];
                uint2 Al1 = patch[(p + 8) * 8 + 4 + tg];
#pragma unroll
                for (int nt = 0; nt < NT; nt++) {
                    int co = nt * 8 + gid;
                    uint2 Bh = wt[(kx * COUT + co) * 8 + tg];
                    uint2 Bl = wt[(kx * COUT + co) * 8 + 4 + tg];
                    mma_s8(acch[nt], Ah0.x, Ah1.x, Ah0.y, Ah1.y, Bh.x, Bh.y);
                    mma_s8(accc[nt], Al0.x, Al1.x, Al0.y, Al1.y, Bh.x, Bh.y);
                    mma_s8(accc[nt], Ah0.x, Ah1.x, Ah0.y, Ah1.y, Bl.x, Bl.y);
                }
            }
        }
    }

    int gy = by0 + yin, gx = bx0 + xh * 16 + gid;
#pragma unroll
    for (int nt = 0; nt < NT; nt++) {
        int co = nt * 8 + 2 * tg;
        float s0 = sAB[co], s1 = sAB[co + 1];
        float* o = out + ((size_t)(b * COUT + co) * H + gy) * H;
        o[gx] = s0 * fmaf((float)accc[nt][0], 0.0078125f, (float)acch[nt][0]);
        o[(size_t)H * H + gx] = s1 * fmaf((float)accc[nt][1], 0.0078125f, (float)acch[nt][1]);
        o[gx + 8] = s0 * fmaf((float)accc[nt][2], 0.0078125f, (float)acch[nt][2]);
        o[(size_t)H * H + gx + 8] = s1 * fmaf((float)accc[nt][3], 0.0078125f, (float)acch[nt][3]);
    }
}

// ---------------- conv1: CIN=4, k8 two-pass, 32x32 tile ----------------
__global__ __launch_bounds__(256, 2) void conv1_k8_kernel(const float* __restrict__ in,
                                                          const float* __restrict__ aff,
                                                          const uint4* __restrict__ wts,
                                                          float* __restrict__ out) {
    const int H = 256, R = 4;
    __shared__ uint4 patch[40 * 40];
    __shared__ uint4 wt[25 * 16 * 2];

    int tid = threadIdx.x, wid = tid >> 5, lane = tid & 31;
    int tg = lane & 3, gid = lane >> 2;
    int bx0 = blockIdx.x * 32, by0 = blockIdx.y * 32, b = blockIdx.z;

    const float* inb = in + (size_t)b * 4 * H * H;
    float s0 = aff[b * 8], bi0 = aff[b * 8 + 1];
    float s1 = aff[b * 8 + 2], bi1 = aff[b * 8 + 3];
    float s2 = aff[b * 8 + 4], bi2 = aff[b * 8 + 5];
    float s3 = aff[b * 8 + 6], bi3 = aff[b * 8 + 7];

    for (int idx = tid; idx < 40 * 40; idx += 256) {
        int py = idx / 40, px = idx - py * 40;
        int gy = by0 - R + py, gx = bx0 - R + px;
        float v0 = 0.f, v1 = 0.f, v2 = 0.f, v3 = 0.f;
        if ((unsigned)gy < 256u && (unsigned)gx < 256u) {
            size_t p0 = (size_t)gy * 256 + gx;
            v0 = fmaf(inb[p0], s0, bi0);
            v1 = fmaf(inb[p0 + 65536], s1, bi1);
            v2 = fmaf(inb[p0 + 131072], s2, bi2);
            v3 = fmaf(inb[p0 + 196608], s3, bi3);
        }
        __nv_bfloat16 h0 = __float2bfloat16(v0), h1 = __float2bfloat16(v1);
        __nv_bfloat16 h2 = __float2bfloat16(v2), h3 = __float2bfloat16(v3);
        uint4 u;
        u.x = packbf(v0, v1);
        u.y = packbf(v2, v3);
        u.z = packbf(v0 - __bfloat162float(h0), v1 - __bfloat162float(h1));
        u.w = packbf(v2 - __bfloat162float(h2), v3 - __bfloat162float(h3));
        patch[idx] = u;
    }
    const uint4* wb = wts + (size_t)b * 800;
    for (int idx = tid; idx < 800; idx += 256) wt[idx] = wb[idx];
    __syncthreads();

    float acc[8][2][4];
#pragma unroll
    for (int mt = 0; mt < 8; mt++)
#pragma unroll
        for (int nt = 0; nt < 2; nt++)
#pragma unroll
            for (int k = 0; k < 4; k++) acc[mt][nt][k] = 0.f;

    const uint32_t* pu = reinterpret_cast<const uint32_t*>(patch);
    const uint32_t* wu = reinterpret_cast<const uint32_t*>(wt);

#pragma unroll
    for (int ky = 0; ky < 5; ky++) {
#pragma unroll
        for (int kx = 0; kx < 5; kx++) {
            int tap = ky * 5 + kx;
            uint32_t breg[2][2];
#pragma unroll
            for (int nt = 0; nt < 2; nt++)
#pragma unroll
                for (int ps = 0; ps < 2; ps++)
                    breg[nt][ps] = wu[(((tap * 16 + nt * 8 + gid) * 2) + ps) * 4 + tg];
#pragma unroll
            for (int mt = 0; mt < 8; mt++) {
                int r = mt >> 1, hx = mt & 1;
                int p = (wid * 4 + r + ky * 2) * 40 + hx * 16 + gid + kx * 2;
                uint32_t a0 = pu[p * 4 + tg];
                uint32_t a1 = pu[(p + 8) * 4 + tg];
#pragma unroll
                for (int nt = 0; nt < 2; nt++) {
                    mma_bf16_k8(acc[mt][nt], a0, a1, breg[nt][0]);
                    mma_bf16_k8(acc[mt][nt], a0, a1, breg[nt][1]);
                }
            }
        }
    }

#pragma unroll
    for (int mt = 0; mt < 8; mt++) {
        int r = mt >> 1, hx = mt & 1;
        int gy = by0 + wid * 4 + r;
        int gx = bx0 + hx * 16 + gid;
#pragma unroll
        for (int nt = 0; nt < 2; nt++) {
            int co = nt * 8 + 2 * tg;
            float* o = out + ((size_t)(b * 16 + co) * H + gy) * H;
            o[gx] = acc[mt][nt][0];
            o[(size_t)H * H + gx] = acc[mt][nt][1];
            o[gx + 8] = acc[mt][nt][2];
            o[(size_t)H * H + gx + 8] = acc[mt][nt][3];
        }
    }
}

// ---------------- bf16x3 conv (conv2, conv3) ----------------
template <int CIN, int COUT, int COUT_B, int H, int DIL, int TH, bool AFF, bool RELU>
__global__ __launch_bounds__(256, 2) void conv5_bf16_kernel(const float* __restrict__ in,
                                                            const float* __restrict__ aff,
                                                            const uint2* __restrict__ wts,
                                                            float* __restrict__ out) {
    constexpr int R = 2 * DIL;
    constexpr int PX = 32 + 2 * R;
    constexpr int PY = TH + 2 * R;
    constexpr int PLANE0 = PX * PY;
    constexpr int PS = PLANE0 + ((4 - PLANE0 % 16) + 16) % 16;
    constexpr int WS = COUT_B + 4;
    constexpr int NT = COUT_B / 8;
    constexpr int MT = (TH / 8) * 2;
    constexpr int RPW = TH / 8;
    constexpr int CGRP = COUT / COUT_B;
    constexpr int CINPAD = (CIN + 15) & ~15;
    constexpr int NCH = CINPAD / 16;

    extern __shared__ uint2 sm[];
    uint2* wtile = sm;
    uint2* patch = sm + 25 * 8 * WS;

    int tid = threadIdx.x, wid = tid >> 5, lane = tid & 31;
    int tg = lane & 3, gid = lane >> 2;
    int bx0 = blockIdx.x * 32;
    int ytile = blockIdx.y / CGRP;
    int cg = blockIdx.y % CGRP;
    int by0 = ytile * TH;
    int b = blockIdx.z;
    int co0 = cg * COUT_B;

    const float* inb = in + (size_t)b * CIN * H * H;
    const float* affb = aff + b * CIN * 2;
    const uint2* wb = wts + ((size_t)b * NCH * 25 * 8) * COUT + co0;

    float acc[MT][NT][4];
#pragma unroll
    for (int mt = 0; mt < MT; mt++)
#pragma unroll
        for (int nt = 0; nt < NT; nt++)
#pragma unroll
            for (int k = 0; k < 4; k++) acc[mt][nt][k] = 0.f;

    int baseA[MT];
#pragma unroll
    for (int mt = 0; mt < MT; mt++) {
        int rofs = (MT == 4) ? (mt >> 1) : 0;
        int pxo = ((MT == 4) ? (mt & 1) : mt) * 16;
        baseA[mt] = tg * PS + (wid * RPW + rofs) * PX + pxo + gid;
    }

    for (int ch = 0; ch < NCH; ch++) {
        __syncthreads();
        for (int idx = tid; idx < 8 * PLANE0; idx += 256) {
            int p = idx / PLANE0;
            int rem = idx - p * PLANE0;
            int py = rem / PX, px = rem - py * PX;
            int gy = by0 - R + py, gx = bx0 - R + px;
            int c0 = ch * 16 + 2 * p;
            float v0 = 0.f, v1 = 0.f;
            if ((unsigned)gy < (unsigned)H && (unsigned)gx < (unsigned)H) {
                if (c0 < CIN) {
                    v0 = inb[((size_t)c0 * H + gy) * H + gx];
                    if (AFF) {
                        v0 = fmaf(v0, __ldg(affb + 2 * c0), __ldg(affb + 2 * c0 + 1));
                        if (RELU) v0 = fmaxf(v0, 0.f);
                    }
                }
                if (c0 + 1 < CIN) {
                    v1 = inb[((size_t)(c0 + 1) * H + gy) * H + gx];
                    if (AFF) {
                        v1 = fmaf(v1, __ldg(affb + 2 * c0 + 2), __ldg(affb + 2 * c0 + 3));
                        if (RELU) v1 = fmaxf(v1, 0.f);
                    }
                }
            }
            patch[p * PS + py * PX + px] = bsplit2(v0, v1);
        }
        const uint2* wc = wb + (size_t)ch * 25 * 8 * COUT;
        for (int idx = tid; idx < 25 * 8 * COUT_B; idx += 256) {
            int t8 = idx / COUT_B;
            int co = idx - t8 * COUT_B;
            wtile[t8 * WS + co] = wc[(size_t)t8 * COUT + co];
        }
        __syncthreads();

#pragma unroll
        for (int ky = 0; ky < 5; ky++) {
#pragma unroll
            for (int kx = 0; kx < 5; kx++) {
                const uint2* wt = wtile + (ky * 5 + kx) * 8 * WS;
                uint2 Bf[NT][2];
#pragma unroll
                for (int nt = 0; nt < NT; nt++) {
                    Bf[nt][0] = wt[tg * WS + nt * 8 + gid];
                    Bf[nt][1] = wt[(tg + 4) * WS + nt * 8 + gid];
                }
#pragma unroll
                for (int mt = 0; mt < MT; mt++) {
                    int ao = baseA[mt] + ky * DIL * PX + kx * DIL;
                    uint2 A0 = patch[ao];
                    uint2 A1 = patch[ao + 8];
                    uint2 A2 = patch[ao + 4 * PS];
                    uint2 A3 = patch[ao + 4 * PS + 8];
#pragma unroll
                    for (int nt = 0; nt < NT; nt++) {
                        mma_bf16(acc[mt][nt], A0.x, A1.x, A2.x, A3.x, Bf[nt][0].x, Bf[nt][1].x);
                        mma_bf16(acc[mt][nt], A0.x, A1.x, A2.x, A3.x, Bf[nt][0].y, Bf[nt][1].y);
                        mma_bf16(acc[mt][nt], A0.y, A1.y, A2.y, A3.y, Bf[nt][0].x, Bf[nt][1].x);
                    }
                }
            }
        }
    }

#pragma unroll
    for (int mt = 0; mt < MT; mt++) {
        int rofs = (MT == 4) ? (mt >> 1) : 0;
        int pxo = ((MT == 4) ? (mt & 1) : mt) * 16;
        int gy = by0 + wid * RPW + rofs;
        int gx = bx0 + pxo + gid;
#pragma unroll
        for (int nt = 0; nt < NT; nt++) {
            int co = co0 + nt * 8 + 2 * tg;
            float* o = out + ((size_t)(b * COUT + co) * H + gy) * H;
            o[gx] = acc[mt][nt][0];
            o[(size_t)H * H + gx] = acc[mt][nt][1];
            o[gx + 8] = acc[mt][nt][2];
            o[(size_t)H * H + gx + 8] = acc[mt][nt][3];
        }
    }
}

// ---------------- avgpool (raw mean) + fused bn2 stats ----------------
__global__ void avgpool_stats_kernel(const float* __restrict__ in, float* __restrict__ out,
                                     float* __restrict__ st) {
    int idx = blockIdx.x * 256 + threadIdx.x;
    int x = idx & 127;
    int y = (idx >> 7) & 127;
    int bc = idx >> 14;
    const float* p = in + ((size_t)bc * 256 + 2 * y) * 256 + 2 * x;
    float v0 = p[0], v1 = p[1], v2 = p[256], v3 = p[257];
    out[idx] = (v0 + v1 + v2 + v3) * 0.25f;
    float s = v0 + v1 + v2 + v3;
    float q = v0 * v0 + v1 * v1 + v2 * v2 + v3 * v3;
    __shared__ float ss[256], sq[256];
    ss[threadIdx.x] = s;
    sq[threadIdx.x] = q;
    __syncthreads();
    for (int stp = 128; stp > 0; stp >>= 1) {
        if (threadIdx.x < stp) {
            ss[threadIdx.x] += ss[threadIdx.x + stp];
            sq[threadIdx.x] += sq[threadIdx.x + stp];
        }
        __syncthreads();
    }
    if (threadIdx.x == 0) {
        atomicAdd(st + bc * 2, ss[0]);
        atomicAdd(st + bc * 2 + 1, sq[0]);
    }
}

// ---------------- 1x1 conv + bilinear residual ----------------
__global__ __launch_bounds__(256) void conv1x1_kernel(const float* __restrict__ in,
                                                      const float* __restrict__ aff,
                                                      const float* __restrict__ wts,
                                                      float* __restrict__ out) {
    int b = blockIdx.y;
    int p = blockIdx.x * 256 + threadIdx.x;
    __shared__ float wsh[4][64];
    __shared__ float sc[64], bi[64];
    int tid = threadIdx.x;
    wsh[tid >> 6][tid & 63] = wts[b * 256 + tid];
    if (tid < 64) {
        sc[tid] = aff[(b * 64 + tid) * 2];
        bi[tid] = aff[(b * 64 + tid) * 2 + 1];
    }
    __syncthreads();
    float acc[4] = {0.f, 0.f, 0.f, 0.f};
    const float* pin = in + (size_t)b * 64 * 16384 + p;
#pragma unroll 8
    for (int ci = 0; ci < 64; ci++) {
        float v = fmaf(pin[(size_t)ci * 16384], sc[ci], bi[ci]);
#pragma unroll
        for (int co = 0; co < 4; co++) acc[co] = fmaf(v, wsh[co][ci], acc[co]);
    }
#pragma unroll
    for (int co = 0; co < 4; co++) out[((size_t)b * 4 + co) * 16384 + p] = acc[co];
}

__global__ void up_add_kernel(const float* __restrict__ in, const float* __restrict__ x,
                              float* __restrict__ out) {
    int idx = blockIdx.x * 256 + threadIdx.x;
    if (idx >= 16 * 4 * 256 * 256) return;
    int ox = idx & 255;
    int oy = (idx >> 8) & 255;
    int bc = idx >> 16;
    const float r = (float)(127.0 / 255.0);
    float px = ox * r, py = oy * r;
    int x0 = (int)px, y0 = (int)py;
    float fx = px - x0, fy = py - y0;
    int x1 = min(x0 + 1, 127), y1 = min(y0 + 1, 127);
    const float* p = in + (size_t)bc * 16384;
    float v00 = p[y0 * 128 + x0], v01 = p[y0 * 128 + x1];
    float v10 = p[y1 * 128 + x0], v11 = p[y1 * 128 + x1];
    float v0 = v00 * (1.f - fx) + v01 * fx;
    float v1 = v10 * (1.f - fx) + v11 * fx;
    out[idx] = v0 * (1.f - fy) + v1 * fy + x[idx];
}

// ---------------- host-side smem size mirrors ----------------
static int smem_bytes(int COUT_B, int DIL, int TH) {
    int R = 2 * DIL;
    int PX = 32 + 2 * R, PY = TH + 2 * R;
    int PLANE0 = PX * PY;
    int PS = PLANE0 + ((4 - PLANE0 % 16) + 16) % 16;
    return (25 * 8 * (COUT_B + 4) + 8 * PS) * 8;
}
static int i8_smem(int COUT, int DIL) {
    int R = 2 * DIL;
    int NPIX = (32 + 2 * R) * (4 + 2 * R);
    return (NPIX * 8 + 5 * COUT * 8) * 8 + COUT * 4;
}

// ---------------- launch ----------------
extern "C" void kernel_launch(void* const* d_in, const int* in_sizes, int n_in,
                              void* d_out, int out_size) {
    const float* x = (const float*)d_in[0];
    const int* action = (const int*)d_in[1];
    const float* w[7];
    const float* wb[7];
    for (int i = 0; i < 7; i++) {
        w[i] = (const float*)d_in[2 + 2 * i];
        wb[i] = (const float*)d_in[3 + 2 * i];
    }
    const float* bns[7];
    const float* bnb[7];
    for (int i = 0; i < 7; i++) {
        bns[i] = (const float*)d_in[16 + 2 * i];
        bnb[i] = (const float*)d_in[17 + 2 * i];
    }

    uint2 *k2, *k3, *q4, *q5, *q6;
    uint4 *c1, *qa4, *qa5, *qa6;
    float *k7, *sb4, *sb5, *sb6;
    unsigned *sa4, *sa5, *sa6;
    float *t1, *t2, *t3, *t4, *t5, *t6, *t7, *t8, *aff, *st2;
    cudaGetSymbolAddress((void**)&k2, g_k2);
    cudaGetSymbolAddress((void**)&k3, g_k3);
    cudaGetSymbolAddress((void**)&q4, g_q4);
    cudaGetSymbolAddress((void**)&q5, g_q5);
    cudaGetSymbolAddress((void**)&q6, g_q6);
    cudaGetSymbolAddress((void**)&qa4, g_qa4);
    cudaGetSymbolAddress((void**)&qa5, g_qa5);
    cudaGetSymbolAddress((void**)&qa6, g_qa6);
    cudaGetSymbolAddress((void**)&sb4, g_sb4);
    cudaGetSymbolAddress((void**)&sb5, g_sb5);
    cudaGetSymbolAddress((void**)&sb6, g_sb6);
    cudaGetSymbolAddress((void**)&sa4, g_sa4);
    cudaGetSymbolAddress((void**)&sa5, g_sa5);
    cudaGetSymbolAddress((void**)&sa6, g_sa6);
    cudaGetSymbolAddress((void**)&c1, g_c1);
    cudaGetSymbolAddress((void**)&k7, g_k7);
    cudaGetSymbolAddress((void**)&t1, g_t1);
    cudaGetSymbolAddress((void**)&t2, g_t2);
    cudaGetSymbolAddress((void**)&t3, g_t3);
    cudaGetSymbolAddress((void**)&t4, g_t4);
    cudaGetSymbolAddress((void**)&t5, g_t5);
    cudaGetSymbolAddress((void**)&t6, g_t6);
    cudaGetSymbolAddress((void**)&t7, g_t7);
    cudaGetSymbolAddress((void**)&t8, g_t8);
    cudaGetSymbolAddress((void**)&aff, g_aff);
    cudaGetSymbolAddress((void**)&st2, g_st2);

    const int AOFF = 16 * 64 * 2;

    cudaFuncSetAttribute(conv5_bf16_kernel<16, 16, 16, 256, 1, 16, true, true>,
                         cudaFuncAttributeMaxDynamicSharedMemorySize, smem_bytes(16, 1, 16));
    cudaFuncSetAttribute(conv5_bf16_kernel<16, 32, 32, 128, 2, 8, true, false>,
                         cudaFuncAttributeMaxDynamicSharedMemorySize, smem_bytes(32, 2, 8));
    cudaFuncSetAttribute(conv_i8_kernel<32, 32, 128, 1>,
                         cudaFuncAttributeMaxDynamicSharedMemorySize, i8_smem(32, 1));
    cudaFuncSetAttribute(conv_i8_kernel<32, 64, 128, 2>,
                         cudaFuncAttributeMaxDynamicSharedMemorySize, i8_smem(64, 2));
    cudaFuncSetAttribute(conv_i8_kernel<64, 64, 128, 1>,
                         cudaFuncAttributeMaxDynamicSharedMemorySize, i8_smem(64, 1));

    // weight gen + scale/stat zeroing
    genA_kernel<<<600, 256>>>(w[1], wb[1], w[2], wb[2], action, k2, k3, st2, sa4, sa5, sa6);
    genB_kernel<<<66, 256>>>(w[0], wb[0], w[6], wb[6], action, c1, k7);
    gi8_amax_kernel<<<16 * 32, 256>>>(w[3], wb[3], action, sb4, 32, 32);
    gi8_amax_kernel<<<16 * 64, 256>>>(w[4], wb[4], action, sb5, 32, 64);
    gi8_amax_kernel<<<16 * 64, 256>>>(w[5], wb[5], action, sb6, 64, 64);
    gi8_quant_kernel<<<400, 256>>>(w[3], wb[3], action, sb4, q4, 32, 32);
    gi8_quant_kernel<<<800, 256>>>(w[4], wb[4], action, sb5, q5, 32, 64);
    gi8_quant_kernel<<<1600, 256>>>(w[5], wb[5], action, sb6, q6, 64, 64);
    // bn0 stats on x
    stats_kernel<65536><<<16 * 4, 256>>>(x, bns[0], bnb[0], aff + 0 * AOFF, 4);
    // conv1
    conv1_k8_kernel<<<dim3(8, 8, 16), 256>>>(x, aff + 0 * AOFF, c1, t1);
    stats_kernel<65536><<<16 * 16, 256>>>(t1, bns[1], bnb[1], aff + 1 * AOFF, 16);
    // conv2 (bf16)
    conv5_bf16_kernel<16, 16, 16, 256, 1, 16, true, true>
        <<<dim3(8, 16, 16), 256, smem_bytes(16, 1, 16)>>>(t1, aff + 1 * AOFF, k2, t2);
    avgpool_stats_kernel<<<16384, 256>>>(t2, t3, st2);
    fin_kernel<<<1, 256>>>(st2, bns[2], bnb[2], aff + 2 * AOFF, 16, 1.f / 65536.f);
    // conv3 (bf16)
    conv5_bf16_kernel<16, 32, 32, 128, 2, 8, true, false>
        <<<dim3(4, 16, 16), 256, smem_bytes(32, 2, 8)>>>(t3, aff + 2 * AOFF, k3, t4);
    // bn3 stats + relu amax -> conv4 int8
    stats_amax_kernel<16384><<<16 * 32, 256>>>(t4, bns[3], bnb[3], aff + 3 * AOFF, 32, sa4, 1);
    quant_act_kernel<<<1024, 256>>>(t4, aff + 3 * AOFF, sa4, qa4, 1, 1);
    conv_i8_kernel<32, 32, 128, 1>
        <<<dim3(4, 32, 16), 256, i8_smem(32, 1)>>>(qa4, q4, sb4, sa4, t5);
    // bn4 stats + abs amax (no relu) -> conv5 int8
    stats_amax_kernel<16384><<<16 * 32, 256>>>(t5, bns[4], bnb[4], aff + 4 * AOFF, 32, sa5, 0);
    quant_act_kernel<<<1024, 256>>>(t5, aff + 4 * AOFF, sa5, qa5, 1, 0);
    conv_i8_kernel<32, 64, 128, 2>
        <<<dim3(4, 32, 16), 256, i8_smem(64, 2)>>>(qa5, q5, sb5, sa5, t6);
    // bn5 stats + relu amax -> conv6 int8
    stats_amax_kernel<16384><<<16 * 64, 256>>>(t6, bns[5], bnb[5], aff + 5 * AOFF, 64, sa6, 1);
    quant_act_kernel<<<2048, 256>>>(t6, aff + 5 * AOFF, sa6, qa6, 2, 1);
    conv_i8_kernel<64, 64, 128, 1>
        <<<dim3(4, 32, 16), 256, i8_smem(64, 1)>>>(qa6, q6, sb6, sa6, t7);
    // bn6, conv7, upsample+residual
    stats_kernel<16384><<<16 * 64, 256>>>(t7, bns[6], bnb[6], aff + 6 * AOFF, 64);
    conv1x1_kernel<<<dim3(64, 16), 256>>>(t7, aff + 6 * AOFF, k7, t8);
    up_add_kernel<<<(16 * 4 * 256 * 256 + 255) / 256, 256>>>(t8, x, (float*)d_out);
}

// round 16
// speedup vs baseline: 1.6866x; 1.0541x over previous
#include <cuda_runtime.h>
#include <cuda_bf16.h>
#include <cstdint>

#define EPS 1e-5f

// ---------------- scratch (static __device__ — no allocation) ----------------
__device__ uint4 g_c1[16 * 25 * 16 * 2];
__device__ float g_k7[16 * 4 * 64];

// int8 weights (paired-tap layout for conv2/3: [b][g(13)][co][8 uint2])
__device__ uint2 g_q2[16 * 13 * 16 * 8];
__device__ uint2 g_q3[16 * 13 * 32 * 8];
// int8 weights (chunked layout conv4/5/6: [b][ch][tap][co][8 uint2])
__device__ uint2 g_q4[16 * 1 * 25 * 32 * 8];
__device__ uint2 g_q5[16 * 1 * 25 * 64 * 8];
__device__ uint2 g_q6[16 * 2 * 25 * 64 * 8];
// quantized activations
__device__ uint4 g_qa2[16 * 65536 * 2];  // 16ch: [b][pix][hi u4, lo u4]
__device__ uint4 g_qa3[16 * 16384 * 2];
__device__ uint4 g_qa4[16 * 1 * 16384 * 4];  // 32ch: [b][ch][pix][4 u4]
__device__ uint4 g_qa5[16 * 1 * 16384 * 4];
__device__ uint4 g_qa6[16 * 2 * 16384 * 4];
__device__ float g_sb2[16 * 16];
__device__ float g_sb3[16 * 32];
__device__ float g_sb4[16 * 32];
__device__ float g_sb5[16 * 64];
__device__ float g_sb6[16 * 64];
__device__ unsigned g_sa2[16], g_sa3[16], g_sa4[16], g_sa5[16], g_sa6[16];
__device__ unsigned g_mm3[16 * 16 * 2];  // pooled min/max keys per (b,c)

__device__ float g_t1[16 * 16 * 256 * 256];
__device__ float g_t2[16 * 16 * 256 * 256];
__device__ float g_t3[16 * 16 * 128 * 128];
__device__ float g_t4[16 * 32 * 128 * 128];
__device__ float g_t5[16 * 32 * 128 * 128];
__device__ float g_t6[16 * 64 * 128 * 128];
__device__ float g_t7[16 * 64 * 128 * 128];
__device__ float g_t8[16 * 4 * 128 * 128];

__device__ float g_aff[7 * 16 * 64 * 2];
__device__ float g_st2[16 * 16 * 2];

// ---------------- helpers ----------------
__device__ __forceinline__ uint32_t packbf(float a, float b) {
    __nv_bfloat162 h;
    h.x = __float2bfloat16(a);
    h.y = __float2bfloat16(b);
    return *reinterpret_cast<uint32_t*>(&h);
}

__device__ __forceinline__ void mma_bf16_k8(float c[4], uint32_t a0, uint32_t a1, uint32_t b0) {
    asm volatile(
        "mma.sync.aligned.m16n8k8.row.col.f32.bf16.bf16.f32 "
        "{%0,%1,%2,%3},{%4,%5},{%6},{%0,%1,%2,%3};"
        : "+f"(c[0]), "+f"(c[1]), "+f"(c[2]), "+f"(c[3])
        : "r"(a0), "r"(a1), "r"(b0));
}

__device__ __forceinline__ void mma_s8(int c[4], uint32_t a0, uint32_t a1, uint32_t a2,
                                       uint32_t a3, uint32_t b0, uint32_t b1) {
    asm volatile(
        "mma.sync.aligned.m16n8k32.row.col.s32.s8.s8.s32 "
        "{%0,%1,%2,%3},{%4,%5,%6,%7},{%8,%9},{%0,%1,%2,%3};"
        : "+r"(c[0]), "+r"(c[1]), "+r"(c[2]), "+r"(c[3])
        : "r"(a0), "r"(a1), "r"(a2), "r"(a3), "r"(b0), "r"(b1));
}

__device__ __forceinline__ int8_t q8(float rr) {
    int v = __float2int_rn(rr);
    return (int8_t)max(-127, min(127, v));
}

// monotonic float<->uint keys for atomic min/max
__device__ __forceinline__ unsigned fkey(float v) {
    unsigned u = __float_as_uint(v);
    return (u & 0x80000000u) ? ~u : (u | 0x80000000u);
}
__device__ __forceinline__ float funkey(unsigned m) {
    unsigned u = (m & 0x80000000u) ? (m ^ 0x80000000u) : ~m;
    return __uint_as_float(u);
}

// ---------------- init ----------------
__global__ void init_kernel(float* st2, unsigned* mm3, unsigned* sa2, unsigned* sa3, unsigned* sa4,
                            unsigned* sa5, unsigned* sa6) {
    int i = threadIdx.x;
    if (i < 512) {
        st2[i] = 0.f;
        mm3[i] = (i & 1) ? 0u : 0xFFFFFFFFu;  // odd = max key, even = min key
    }
    if (i < 16) {
        sa2[i] = 0u;
        sa3[i] = 0u;
        sa4[i] = 0u;
        sa5[i] = 0u;
        sa6[i] = 0u;
    }
}

// ---------------- conv1 + conv7 weights ----------------
__global__ void genB_kernel(const float* w1, const float* b1, const float* w7, const float* b7,
                            const int* __restrict__ action, uint4* c1, float* k7) {
    int i = blockIdx.x * 256 + threadIdx.x;
    if (i < 12800) {
        int j = i;
        int pass = j & 1;
        int r = j >> 1;
        int co = r & 15;
        r >>= 4;
        int tap = r % 25;
        int b = r / 25;
        int a = action[b];
        float h[4], l[4];
#pragma unroll
        for (int ci = 0; ci < 4; ci++) {
            int o = (co * 4 + ci) * 25 + tap;
            float v = w1[o * 6 + a] + b1[o];
            __nv_bfloat16 hb = __float2bfloat16(v);
            h[ci] = v;
            l[ci] = v - __bfloat162float(hb);
        }
        uint4 u;
        if (pass == 0) {
            u.x = packbf(h[0], h[1]);
            u.y = packbf(h[2], h[3]);
            u.z = u.x;
            u.w = u.y;
        } else {
            u.x = packbf(l[0], l[1]);
            u.y = packbf(l[2], l[3]);
            u.z = 0;
            u.w = 0;
        }
        c1[j] = u;
    } else if (i < 12800 + 4096) {
        int j = i - 12800;
        int b = j / 256, o = j - b * 256;
        k7[j] = w7[o * 6 + action[b]] + b7[o];
    }
}

// ---------------- int8 weight amax ----------------
__global__ void gi8_amax_kernel(const float* __restrict__ w, const float* __restrict__ bias,
                                const int* __restrict__ action, float* __restrict__ sb, int CIN,
                                int COUT) {
    int bc = blockIdx.x;
    int b = bc / COUT, co = bc - b * COUT;
    int a = action[b];
    int K = CIN * 25;
    float m = 0.f;
    for (int i = threadIdx.x; i < K; i += 256) {
        int o = co * K + i;
        m = fmaxf(m, fabsf(w[o * 6 + a] + bias[o]));
    }
    __shared__ float sm[256];
    sm[threadIdx.x] = m;
    __syncthreads();
    for (int st = 128; st > 0; st >>= 1) {
        if (threadIdx.x < st) sm[threadIdx.x] = fmaxf(sm[threadIdx.x], sm[threadIdx.x + st]);
        __syncthreads();
    }
    if (threadIdx.x == 0) sb[bc] = fmaxf(sm[0], 1e-20f);
}

// ---------------- int8 weight quantize (chunked, conv4/5/6) ----------------
__global__ void gi8_quant_kernel(const float* __restrict__ w, const float* __restrict__ bias,
                                 const int* __restrict__ action, const float* __restrict__ sb,
                                 uint2* __restrict__ q, int CIN, int COUT) {
    int NCH = CIN / 32;
    int total = 16 * NCH * 25 * COUT * 8;
    int idx = blockIdx.x * 256 + threadIdx.x;
    if (idx >= total) return;
    int j = idx & 7;
    int r = idx >> 3;
    int co = r % COUT;
    r /= COUT;
    int tap = r % 25;
    r /= 25;
    int ch = r % NCH;
    int b = r / NCH;
    int a = action[b];
    float inv = 127.f / sb[b * COUT + co];
    int jj = j & 3;
    int is_l = j >> 2;
    uint32_t wd[2];
#pragma unroll
    for (int half = 0; half < 2; half++) {
        uint32_t pk = 0;
#pragma unroll
        for (int e = 0; e < 4; e++) {
            int k = half * 16 + jj * 4 + e;
            int ci = ch * 32 + k;
            int o = (co * CIN + ci) * 25 + tap;
            float v = w[o * 6 + a] + bias[o];
            float rr = v * inv;
            int qh = __float2int_rn(rr);
            qh = max(-127, min(127, qh));
            int byte;
            if (is_l) {
                int ql = __float2int_rn((rr - (float)qh) * 128.f);
                byte = max(-127, min(127, ql));
            } else {
                byte = qh;
            }
            pk |= ((uint32_t)(uint8_t)(int8_t)byte) << (e * 8);
        }
        wd[half] = pk;
    }
    q[idx] = make_uint2(wd[0], wd[1]);
}

// ---------------- int8 weight quantize (paired-tap, conv2/3, CIN=16) ----------------
// record per (b,g,co): 8 uint2 = [hi 32B: tapA ch0..15 | tapB ch0..15][lo 32B]
__global__ void gi8p_quant_kernel(const float* __restrict__ w, const float* __restrict__ bias,
                                  const int* __restrict__ action, const float* __restrict__ sb,
                                  uint2* __restrict__ q, int COUT) {
    int total = 16 * 13 * COUT * 8;
    int idx = blockIdx.x * 256 + threadIdx.x;
    if (idx >= total) return;
    int j = idx & 7;
    int r = idx >> 3;
    int co = r % COUT;
    r /= COUT;
    int g = r % 13;
    int b = r / 13;
    int a = action[b];
    int tA = 2 * g, tB = (g == 12) ? -1 : 2 * g + 1;
    float inv = 127.f / sb[b * COUT + co];
    int is_l = j >> 2;
    int tgj = j & 3;
    uint32_t wd[2];
#pragma unroll
    for (int half = 0; half < 2; half++) {
        uint32_t pk = 0;
#pragma unroll
        for (int e = 0; e < 4; e++) {
            int k = tgj * 8 + half * 4 + e;
            int ch = k & 15;
            int tap = (k < 16) ? tA : tB;
            int byte = 0;
            if (tap >= 0) {
                int o = (co * 16 + ch) * 25 + tap;
                float v = w[o * 6 + a] + bias[o];
                float rr = v * inv;
                int qh = __float2int_rn(rr);
                qh = max(-127, min(127, qh));
                if (is_l) {
                    int ql = __float2int_rn((rr - (float)qh) * 128.f);
                    byte = max(-127, min(127, ql));
                } else {
                    byte = qh;
                }
            }
            pk |= ((uint32_t)(uint8_t)(int8_t)byte) << (e * 8);
        }
        wd[half] = pk;
    }
    q[idx] = make_uint2(wd[0], wd[1]);
}

// ---------------- BN stats ----------------
template <int N>
__global__ void stats_kernel(const float* __restrict__ in, const float* __restrict__ s,
                             const float* __restrict__ bb, float* __restrict__ aff, int C) {
    int bc = blockIdx.x;
    const float* p = in + (size_t)bc * N;
    float sum = 0.f, sq = 0.f;
    for (int i = threadIdx.x; i < N; i += 256) {
        float v = p[i];
        sum += v;
        sq += v * v;
    }
    __shared__ float ssum[256], ssq[256];
    ssum[threadIdx.x] = sum;
    ssq[threadIdx.x] = sq;
    __syncthreads();
    for (int st = 128; st > 0; st >>= 1) {
        if (threadIdx.x < st) {
            ssum[threadIdx.x] += ssum[threadIdx.x + st];
            ssq[threadIdx.x] += ssq[threadIdx.x + st];
        }
        __syncthreads();
    }
    if (threadIdx.x == 0) {
        int c = bc % C;
        float mean = ssum[0] / (float)N;
        float var = ssq[0] / (float)N - mean * mean;
        float sc = rsqrtf(var + EPS) * s[c];
        aff[2 * bc] = sc;
        aff[2 * bc + 1] = bb[c] - mean * sc;
    }
}

template <int N>
__global__ void stats_amax_kernel(const float* __restrict__ in, const float* __restrict__ s,
                                  const float* __restrict__ bb, float* __restrict__ aff, int C,
                                  unsigned* __restrict__ sa, int relu) {
    int bc = blockIdx.x;
    const float* p = in + (size_t)bc * N;
    float sum = 0.f, sq = 0.f, mn = 1e30f, mx = -1e30f;
    for (int i = threadIdx.x; i < N; i += 256) {
        float v = p[i];
        sum += v;
        sq += v * v;
        mn = fminf(mn, v);
        mx = fmaxf(mx, v);
    }
    __shared__ float ssum[256], ssq[256], smn[256], smx[256];
    ssum[threadIdx.x] = sum;
    ssq[threadIdx.x] = sq;
    smn[threadIdx.x] = mn;
    smx[threadIdx.x] = mx;
    __syncthreads();
    for (int st = 128; st > 0; st >>= 1) {
        if (threadIdx.x < st) {
            ssum[threadIdx.x] += ssum[threadIdx.x + st];
            ssq[threadIdx.x] += ssq[threadIdx.x + st];
            smn[threadIdx.x] = fminf(smn[threadIdx.x], smn[threadIdx.x + st]);
            smx[threadIdx.x] = fmaxf(smx[threadIdx.x], smx[threadIdx.x + st]);
        }
        __syncthreads();
    }
    if (threadIdx.x == 0) {
        int c = bc % C, b = bc / C;
        float mean = ssum[0] / (float)N;
        float var = ssq[0] / (float)N - mean * mean;
        float sc = rsqrtf(var + EPS) * s[c];
        float bi = bb[c] - mean * sc;
        aff[2 * bc] = sc;
        aff[2 * bc + 1] = bi;
        float e0 = smn[0] * sc + bi, e1 = smx[0] * sc + bi;
        float hi = fmaxf(e0, e1), lo = fminf(e0, e1);
        float amax = relu ? fmaxf(0.f, hi) : fmaxf(fabsf(hi), fabsf(lo));
        atomicMax(sa + b, __float_as_uint(amax));
    }
}

// bn2 finalize: affine from st2 + conv3 input amax from mm3
__global__ void fin3_kernel(const float* __restrict__ st, const unsigned* __restrict__ mm,
                            const float* __restrict__ s, const float* __restrict__ bb,
                            float* __restrict__ aff, unsigned* __restrict__ sa) {
    int i = threadIdx.x;
    if (i >= 256) return;
    int b = i >> 4, c = i & 15;
    float sum = st[i * 2];
    float sq = st[i * 2 + 1];
    float mean = sum * (1.f / 65536.f);
    float var = sq * (1.f / 65536.f) - mean * mean;
    float sc = rsqrtf(var + EPS) * s[c];
    float bi = bb[c] - mean * sc;
    aff[2 * i] = sc;
    aff[2 * i + 1] = bi;
    float mn = funkey(mm[i * 2]), mx = funkey(mm[i * 2 + 1]);
    float e0 = mn * sc + bi, e1 = mx * sc + bi;
    float amax = fmaxf(fabsf(e0), fabsf(e1));
    atomicMax(sa + b, __float_as_uint(amax));
}

// ---------------- activation quantize (16ch, conv2/3 inputs) ----------------
__global__ void quant_act16_kernel(const float* __restrict__ t, const float* __restrict__ aff,
                                   const unsigned* __restrict__ sa, uint4* __restrict__ qa,
                                   int h2log, int relu) {
    int idx = blockIdx.x * 256 + threadIdx.x;
    int pix = idx & ((1 << h2log) - 1);
    int b = idx >> h2log;
    size_t H2 = (size_t)1 << h2log;
    float sA = __uint_as_float(sa[b]);
    float inv = (sA > 0.f) ? 127.f / sA : 0.f;
    const float* base = t + (size_t)b * 16 * H2 + pix;
    const float* af = aff + b * 16 * 2;
    uint32_t Hw[4], Lw[4];
#pragma unroll
    for (int k = 0; k < 4; k++) {
        Hw[k] = 0;
        Lw[k] = 0;
    }
#pragma unroll
    for (int c = 0; c < 16; c++) {
        float v = fmaf(base[(size_t)c * H2], __ldg(af + 2 * c), __ldg(af + 2 * c + 1));
        if (relu) v = fmaxf(v, 0.f);
        float rr = v * inv;
        int qh = __float2int_rn(rr);
        qh = max(-127, min(127, qh));
        int ql = __float2int_rn((rr - (float)qh) * 128.f);
        ql = max(-127, min(127, ql));
        int wi = c >> 2, sh = (c & 3) * 8;
        Hw[wi] |= ((uint32_t)(uint8_t)(int8_t)qh) << sh;
        Lw[wi] |= ((uint32_t)(uint8_t)(int8_t)ql) << sh;
    }
    uint4* dst = qa + (size_t)idx * 2;
    dst[0] = make_uint4(Hw[0], Hw[1], Hw[2], Hw[3]);
    dst[1] = make_uint4(Lw[0], Lw[1], Lw[2], Lw[3]);
}

// ---------------- activation quantize (32ch chunks, conv4/5/6 inputs) ----------------
__global__ void quant_act_kernel(const float* __restrict__ t, const float* __restrict__ aff,
                                 const unsigned* __restrict__ sa, uint4* __restrict__ qa, int NCH,
                                 int relu) {
    int idx = blockIdx.x * 256 + threadIdx.x;
    int pix = idx & 16383;
    int r = idx >> 14;
    int ch = r % NCH;
    int b = r / NCH;
    int C = NCH * 32;
    float sA = __uint_as_float(sa[b]);
    float inv = (sA > 0.f) ? 127.f / sA : 0.f;
    const float* base = t + ((size_t)(b * C + ch * 32)) * 16384 + pix;
    const float* af = aff + (b * C + ch * 32) * 2;
    uint32_t Hw[8], Lw[8];
#pragma unroll
    for (int k = 0; k < 8; k++) {
        Hw[k] = 0;
        Lw[k] = 0;
    }
#pragma unroll
    for (int c = 0; c < 32; c++) {
        float v = fmaf(base[(size_t)c * 16384], __ldg(af + 2 * c), __ldg(af + 2 * c + 1));
        if (relu) v = fmaxf(v, 0.f);
        float rr = v * inv;
        int qh = __float2int_rn(rr);
        qh = max(-127, min(127, qh));
        int ql = __float2int_rn((rr - (float)qh) * 128.f);
        ql = max(-127, min(127, ql));
        int wi = (c < 16) ? 2 * (c >> 2) : 2 * ((c - 16) >> 2) + 1;
        int sh = (c & 3) * 8;
        Hw[wi] |= ((uint32_t)(uint8_t)(int8_t)qh) << sh;
        Lw[wi] |= ((uint32_t)(uint8_t)(int8_t)ql) << sh;
    }
    uint4* dst = qa + (size_t)idx * 4;
    dst[0] = make_uint4(Hw[0], Hw[1], Hw[2], Hw[3]);
    dst[1] = make_uint4(Hw[4], Hw[5], Hw[6], Hw[7]);
    dst[2] = make_uint4(Lw[0], Lw[1], Lw[2], Lw[3]);
    dst[3] = make_uint4(Lw[4], Lw[5], Lw[6], Lw[7]);
}

// ---------------- int8x2 paired-tap conv (conv2/3, CIN=16) ----------------
// tile 32x4, warp = 16px x COUT; 13 k32 groups pack two taps each.
template <int COUT, int H, int DIL>
__global__ __launch_bounds__(256, 2) void conv_i8p_kernel(const uint4* __restrict__ qa,
                                                          const uint2* __restrict__ qw,
                                                          const float* __restrict__ sb,
                                                          const unsigned* __restrict__ sa,
                                                          float* __restrict__ out) {
    constexpr int NT = COUT / 8;
    constexpr int R = 2 * DIL;
    constexpr int PXP = 32 + 2 * R;
    constexpr int PYP = 4 + 2 * R;
    constexpr int NPIX = PXP * PYP;

    extern __shared__ uint4 smp[];
    uint4* patch = smp;                            // NPIX * 2 uint4 (hi 16B, lo 16B)
    uint2* wt = (uint2*)(smp + NPIX * 2);          // 13*COUT*8
    float* sAB = (float*)(wt + 13 * COUT * 8);

    int tid = threadIdx.x, wid = tid >> 5, lane = tid & 31;
    int tg = lane & 3, gid = lane >> 2;
    int yin = wid >> 1, xh = wid & 1;
    int bx0 = blockIdx.x * 32, by0 = blockIdx.y * 4, b = blockIdx.z;

    if (tid < COUT) {
        float sA = __uint_as_float(sa[b]);
        sAB[tid] = sA * sb[b * COUT + tid] * (1.f / 16129.f);
    }
    // patch fill: copy pre-quantized 32B records
    for (int p = tid; p < NPIX; p += 256) {
        int py = p / PXP, px = p - py * PXP;
        int gy = by0 - R + py, gx = bx0 - R + px;
        if ((unsigned)gy < (unsigned)H && (unsigned)gx < (unsigned)H) {
            const uint4* s4 = qa + ((size_t)(b * H + gy) * H + gx) * 2;
            patch[p * 2] = s4[0];
            patch[p * 2 + 1] = s4[1];
        } else {
            uint4 z = make_uint4(0, 0, 0, 0);
            patch[p * 2] = z;
            patch[p * 2 + 1] = z;
        }
    }
    // stage all weights (single chunk)
    {
        const uint2* wcb = qw + (size_t)b * 13 * COUT * 8;
        for (int i = tid; i < 13 * COUT * 8; i += 256) wt[i] = wcb[i];
    }
    __syncthreads();

    int acch[NT][4], accc[NT][4];
#pragma unroll
    for (int nt = 0; nt < NT; nt++)
#pragma unroll
        for (int k = 0; k < 4; k++) {
            acch[nt][k] = 0;
            accc[nt][k] = 0;
        }

    const uint2* pv = (const uint2*)patch;  // pixel record = 4 uint2 [hi0,hi1,lo0,lo1]
    int p0 = yin * PXP + xh * 16 + gid;
    int u = tg & 1;

#pragma unroll
    for (int g = 0; g < 13; g++) {
        int tA = 2 * g;
        int tB = (g == 12) ? tA : tA + 1;
        int offA = (tA / 5) * DIL * PXP + (tA % 5) * DIL;
        int offB = (tB / 5) * DIL * PXP + (tB % 5) * DIL;
        int off = (tg < 2) ? offA : offB;
        int pp = p0 + off;
        uint2 Ah0 = pv[pp * 4 + u];
        uint2 Ah1 = pv[(pp + 8) * 4 + u];
        uint2 Al0 = pv[pp * 4 + 2 + u];
        uint2 Al1 = pv[(pp + 8) * 4 + 2 + u];
#pragma unroll
        for (int nt = 0; nt < NT; nt++) {
            int co = nt * 8 + gid;
            uint2 Bh = wt[(g * COUT + co) * 8 + tg];
            uint2 Bl = wt[(g * COUT + co) * 8 + 4 + tg];
            mma_s8(acch[nt], Ah0.x, Ah1.x, Ah0.y, Ah1.y, Bh.x, Bh.y);
            mma_s8(accc[nt], Al0.x, Al1.x, Al0.y, Al1.y, Bh.x, Bh.y);
            mma_s8(accc[nt], Ah0.x, Ah1.x, Ah0.y, Ah1.y, Bl.x, Bl.y);
        }
    }

    int gy = by0 + yin, gx = bx0 + xh * 16 + gid;
#pragma unroll
    for (int nt = 0; nt < NT; nt++) {
        int co = nt * 8 + 2 * tg;
        float s0 = sAB[co], s1 = sAB[co + 1];
        float* o = out + ((size_t)(b * COUT + co) * H + gy) * H;
        o[gx] = s0 * fmaf((float)accc[nt][0], 0.0078125f, (float)acch[nt][0]);
        o[(size_t)H * H + gx] = s1 * fmaf((float)accc[nt][1], 0.0078125f, (float)acch[nt][1]);
        o[gx + 8] = s0 * fmaf((float)accc[nt][2], 0.0078125f, (float)acch[nt][2]);
        o[(size_t)H * H + gx + 8] = s1 * fmaf((float)accc[nt][3], 0.0078125f, (float)acch[nt][3]);
    }
}

// ---------------- int8x2 chunked conv (conv4/5/6) ----------------
template <int CIN, int COUT, int H, int DIL>
__global__ __launch_bounds__(256, 2) void conv_i8_kernel(const uint4* __restrict__ qa,
                                                         const uint2* __restrict__ qw,
                                                         const float* __restrict__ sb,
                                                         const unsigned* __restrict__ sa,
                                                         float* __restrict__ out) {
    constexpr int NCH = CIN / 32;
    constexpr int NT = COUT / 8;
    constexpr int R = 2 * DIL;
    constexpr int PXP = 32 + 2 * R;
    constexpr int PYP = 4 + 2 * R;
    constexpr int NPIX = PXP * PYP;

    extern __shared__ uint2 smq[];
    uint2* patch = smq;
    uint2* wt = smq + NPIX * 8;
    float* sAB = (float*)(smq + NPIX * 8 + 5 * COUT * 8);

    int tid = threadIdx.x, wid = tid >> 5, lane = tid & 31;
    int tg = lane & 3, gid = lane >> 2;
    int yin = wid >> 1, xh = wid & 1;
    int bx0 = blockIdx.x * 32, by0 = blockIdx.y * 4, b = blockIdx.z;

    if (tid < COUT) {
        float sA = __uint_as_float(sa[b]);
        sAB[tid] = sA * sb[b * COUT + tid] * (1.f / 16129.f);
    }

    int acch[NT][4], accc[NT][4];
#pragma unroll
    for (int nt = 0; nt < NT; nt++)
#pragma unroll
        for (int k = 0; k < 4; k++) {
            acch[nt][k] = 0;
            accc[nt][k] = 0;
        }

    for (int ch = 0; ch < NCH; ch++) {
        __syncthreads();
        for (int p = tid; p < NPIX; p += 256) {
            int py = p / PXP, px = p - py * PXP;
            int gy = by0 - R + py, gx = bx0 - R + px;
            uint4* d4 = (uint4*)(patch + p * 8);
            if ((unsigned)gy < (unsigned)H && (unsigned)gx < (unsigned)H) {
                const uint4* s4 = qa + ((size_t)((b * NCH + ch) * H + gy) * H + gx) * 4;
                d4[0] = s4[0];
                d4[1] = s4[1];
                d4[2] = s4[2];
                d4[3] = s4[3];
            } else {
                uint4 z = make_uint4(0, 0, 0, 0);
                d4[0] = z;
                d4[1] = z;
                d4[2] = z;
                d4[3] = z;
            }
        }
        const uint2* wcb = qw + ((size_t)(b * NCH + ch) * 25 * COUT) * 8;
#pragma unroll 1
        for (int ky = 0; ky < 5; ky++) {
            __syncthreads();
            for (int i = tid; i < 5 * COUT * 8; i += 256)
                wt[i] = wcb[(size_t)ky * 5 * COUT * 8 + i];
            __syncthreads();
#pragma unroll
            for (int kx = 0; kx < 5; kx++) {
                int p = (yin + ky * DIL) * PXP + xh * 16 + gid + kx * DIL;
                uint2 Ah0 = patch[p * 8 + tg];
                uint2 Ah1 = patch[(p + 8) * 8 + tg];
                uint2 Al0 = patch[p * 8 + 4 + tg];
                uint2 Al1 = patch[(p + 8) * 8 + 4 + tg];
#pragma unroll
                for (int nt = 0; nt < NT; nt++) {
                    int co = nt * 8 + gid;
                    uint2 Bh = wt[(kx * COUT + co) * 8 + tg];
                    uint2 Bl = wt[(kx * COUT + co) * 8 + 4 + tg];
                    mma_s8(acch[nt], Ah0.x, Ah1.x, Ah0.y, Ah1.y, Bh.x, Bh.y);
                    mma_s8(accc[nt], Al0.x, Al1.x, Al0.y, Al1.y, Bh.x, Bh.y);
                    mma_s8(accc[nt], Ah0.x, Ah1.x, Ah0.y, Ah1.y, Bl.x, Bl.y);
                }
            }
        }
    }

    int gy = by0 + yin, gx = bx0 + xh * 16 + gid;
#pragma unroll
    for (int nt = 0; nt < NT; nt++) {
        int co = nt * 8 + 2 * tg;
        float s0 = sAB[co], s1 = sAB[co + 1];
        float* o = out + ((size_t)(b * COUT + co) * H + gy) * H;
        o[gx] = s0 * fmaf((float)accc[nt][0], 0.0078125f, (float)acch[nt][0]);
        o[(size_t)H * H + gx] = s1 * fmaf((float)accc[nt][1], 0.0078125f, (float)acch[nt][1]);
        o[gx + 8] = s0 * fmaf((float)accc[nt][2], 0.0078125f, (float)acch[nt][2]);
        o[(size_t)H * H + gx + 8] = s1 * fmaf((float)accc[nt][3], 0.0078125f, (float)acch[nt][3]);
    }
}

// ---------------- conv1: CIN=4, k8 two-pass, 32x32 tile ----------------
__global__ __launch_bounds__(256, 2) void conv1_k8_kernel(const float* __restrict__ in,
                                                          const float* __restrict__ aff,
                                                          const uint4* __restrict__ wts,
                                                          float* __restrict__ out) {
    const int H = 256, R = 4;
    __shared__ uint4 patch[40 * 40];
    __shared__ uint4 wt[25 * 16 * 2];

    int tid = threadIdx.x, wid = tid >> 5, lane = tid & 31;
    int tg = lane & 3, gid = lane >> 2;
    int bx0 = blockIdx.x * 32, by0 = blockIdx.y * 32, b = blockIdx.z;

    const float* inb = in + (size_t)b * 4 * H * H;
    float s0 = aff[b * 8], bi0 = aff[b * 8 + 1];
    float s1 = aff[b * 8 + 2], bi1 = aff[b * 8 + 3];
    float s2 = aff[b * 8 + 4], bi2 = aff[b * 8 + 5];
    float s3 = aff[b * 8 + 6], bi3 = aff[b * 8 + 7];

    for (int idx = tid; idx < 40 * 40; idx += 256) {
        int py = idx / 40, px = idx - py * 40;
        int gy = by0 - R + py, gx = bx0 - R + px;
        float v0 = 0.f, v1 = 0.f, v2 = 0.f, v3 = 0.f;
        if ((unsigned)gy < 256u && (unsigned)gx < 256u) {
            size_t p0 = (size_t)gy * 256 + gx;
            v0 = fmaf(inb[p0], s0, bi0);
            v1 = fmaf(inb[p0 + 65536], s1, bi1);
            v2 = fmaf(inb[p0 + 131072], s2, bi2);
            v3 = fmaf(inb[p0 + 196608], s3, bi3);
        }
        __nv_bfloat16 h0 = __float2bfloat16(v0), h1 = __float2bfloat16(v1);
        __nv_bfloat16 h2 = __float2bfloat16(v2), h3 = __float2bfloat16(v3);
        uint4 u;
        u.x = packbf(v0, v1);
        u.y = packbf(v2, v3);
        u.z = packbf(v0 - __bfloat162float(h0), v1 - __bfloat162float(h1));
        u.w = packbf(v2 - __bfloat162float(h2), v3 - __bfloat162float(h3));
        patch[idx] = u;
    }
    const uint4* wb = wts + (size_t)b * 800;
    for (int idx = tid; idx < 800; idx += 256) wt[idx] = wb[idx];
    __syncthreads();

    float acc[8][2][4];
#pragma unroll
    for (int mt = 0; mt < 8; mt++)
#pragma unroll
        for (int nt = 0; nt < 2; nt++)
#pragma unroll
            for (int k = 0; k < 4; k++) acc[mt][nt][k] = 0.f;

    const uint32_t* pu = reinterpret_cast<const uint32_t*>(patch);
    const uint32_t* wu = reinterpret_cast<const uint32_t*>(wt);

#pragma unroll
    for (int ky = 0; ky < 5; ky++) {
#pragma unroll
        for (int kx = 0; kx < 5; kx++) {
            int tap = ky * 5 + kx;
            uint32_t breg[2][2];
#pragma unroll
            for (int nt = 0; nt < 2; nt++)
#pragma unroll
                for (int ps = 0; ps < 2; ps++)
                    breg[nt][ps] = wu[(((tap * 16 + nt * 8 + gid) * 2) + ps) * 4 + tg];
#pragma unroll
            for (int mt = 0; mt < 8; mt++) {
                int r = mt >> 1, hx = mt & 1;
                int p = (wid * 4 + r + ky * 2) * 40 + hx * 16 + gid + kx * 2;
                uint32_t a0 = pu[p * 4 + tg];
                uint32_t a1 = pu[(p + 8) * 4 + tg];
#pragma unroll
                for (int nt = 0; nt < 2; nt++) {
                    mma_bf16_k8(acc[mt][nt], a0, a1, breg[nt][0]);
                    mma_bf16_k8(acc[mt][nt], a0, a1, breg[nt][1]);
                }
            }
        }
    }

#pragma unroll
    for (int mt = 0; mt < 8; mt++) {
        int r = mt >> 1, hx = mt & 1;
        int gy = by0 + wid * 4 + r;
        int gx = bx0 + hx * 16 + gid;
#pragma unroll
        for (int nt = 0; nt < 2; nt++) {
            int co = nt * 8 + 2 * tg;
            float* o = out + ((size_t)(b * 16 + co) * H + gy) * H;
            o[gx] = acc[mt][nt][0];
            o[(size_t)H * H + gx] = acc[mt][nt][1];
            o[gx + 8] = acc[mt][nt][2];
            o[(size_t)H * H + gx + 8] = acc[mt][nt][3];
        }
    }
}

// ---------------- avgpool (raw mean) + bn2 stats + min/max ----------------
__global__ void avgpool_stats_kernel(const float* __restrict__ in, float* __restrict__ out,
                                     float* __restrict__ st, unsigned* __restrict__ mm) {
    int idx = blockIdx.x * 256 + threadIdx.x;
    int x = idx & 127;
    int y = (idx >> 7) & 127;
    int bc = idx >> 14;
    const float* p = in + ((size_t)bc * 256 + 2 * y) * 256 + 2 * x;
    float v0 = p[0], v1 = p[1], v2 = p[256], v3 = p[257];
    float m = (v0 + v1 + v2 + v3) * 0.25f;
    out[idx] = m;
    float s = v0 + v1 + v2 + v3;
    float q = v0 * v0 + v1 * v1 + v2 * v2 + v3 * v3;
    __shared__ float ss[256], sq[256], smn[256], smx[256];
    ss[threadIdx.x] = s;
    sq[threadIdx.x] = q;
    smn[threadIdx.x] = m;
    smx[threadIdx.x] = m;
    __syncthreads();
    for (int stp = 128; stp > 0; stp >>= 1) {
        if (threadIdx.x < stp) {
            ss[threadIdx.x] += ss[threadIdx.x + stp];
            sq[threadIdx.x] += sq[threadIdx.x + stp];
            smn[threadIdx.x] = fminf(smn[threadIdx.x], smn[threadIdx.x + stp]);
            smx[threadIdx.x] = fmaxf(smx[threadIdx.x], smx[threadIdx.x + stp]);
        }
        __syncthreads();
    }
    if (threadIdx.x == 0) {
        atomicAdd(st + bc * 2, ss[0]);
        atomicAdd(st + bc * 2 + 1, sq[0]);
        atomicMin(mm + bc * 2, fkey(smn[0]));
        atomicMax(mm + bc * 2 + 1, fkey(smx[0]));
    }
}

// ---------------- 1x1 conv + bilinear residual ----------------
__global__ __launch_bounds__(256) void conv1x1_kernel(const float* __restrict__ in,
                                                      const float* __restrict__ aff,
                                                      const float* __restrict__ wts,
                                                      float* __restrict__ out) {
    int b = blockIdx.y;
    int p = blockIdx.x * 256 + threadIdx.x;
    __shared__ float wsh[4][64];
    __shared__ float sc[64], bi[64];
    int tid = threadIdx.x;
    wsh[tid >> 6][tid & 63] = wts[b * 256 + tid];
    if (tid < 64) {
        sc[tid] = aff[(b * 64 + tid) * 2];
        bi[tid] = aff[(b * 64 + tid) * 2 + 1];
    }
    __syncthreads();
    float acc[4] = {0.f, 0.f, 0.f, 0.f};
    const float* pin = in + (size_t)b * 64 * 16384 + p;
#pragma unroll 8
    for (int ci = 0; ci < 64; ci++) {
        float v = fmaf(pin[(size_t)ci * 16384], sc[ci], bi[ci]);
#pragma unroll
        for (int co = 0; co < 4; co++) acc[co] = fmaf(v, wsh[co][ci], acc[co]);
    }
#pragma unroll
    for (int co = 0; co < 4; co++) out[((size_t)b * 4 + co) * 16384 + p] = acc[co];
}

__global__ void up_add_kernel(const float* __restrict__ in, const float* __restrict__ x,
                              float* __restrict__ out) {
    int idx = blockIdx.x * 256 + threadIdx.x;
    if (idx >= 16 * 4 * 256 * 256) return;
    int ox = idx & 255;
    int oy = (idx >> 8) & 255;
    int bc = idx >> 16;
    const float r = (float)(127.0 / 255.0);
    float px = ox * r, py = oy * r;
    int x0 = (int)px, y0 = (int)py;
    float fx = px - x0, fy = py - y0;
    int x1 = min(x0 + 1, 127), y1 = min(y0 + 1, 127);
    const float* p = in + (size_t)bc * 16384;
    float v00 = p[y0 * 128 + x0], v01 = p[y0 * 128 + x1];
    float v10 = p[y1 * 128 + x0], v11 = p[y1 * 128 + x1];
    float v0 = v00 * (1.f - fx) + v01 * fx;
    float v1 = v10 * (1.f - fx) + v11 * fx;
    out[idx] = v0 * (1.f - fy) + v1 * fy + x[idx];
}

// ---------------- host-side smem size mirrors ----------------
static int i8_smem(int COUT, int DIL) {
    int R = 2 * DIL;
    int NPIX = (32 + 2 * R) * (4 + 2 * R);
    return (NPIX * 8 + 5 * COUT * 8) * 8 + COUT * 4;
}
static int i8p_smem(int COUT, int DIL) {
    int R = 2 * DIL;
    int NPIX = (32 + 2 * R) * (4 + 2 * R);
    return NPIX * 32 + 13 * COUT * 64 + COUT * 4;
}

// ---------------- launch ----------------
extern "C" void kernel_launch(void* const* d_in, const int* in_sizes, int n_in,
                              void* d_out, int out_size) {
    const float* x = (const float*)d_in[0];
    const int* action = (const int*)d_in[1];
    const float* w[7];
    const float* wb[7];
    for (int i = 0; i < 7; i++) {
        w[i] = (const float*)d_in[2 + 2 * i];
        wb[i] = (const float*)d_in[3 + 2 * i];
    }
    const float* bns[7];
    const float* bnb[7];
    for (int i = 0; i < 7; i++) {
        bns[i] = (const float*)d_in[16 + 2 * i];
        bnb[i] = (const float*)d_in[17 + 2 * i];
    }

    uint2 *q2, *q3, *q4, *q5, *q6;
    uint4 *c1, *qa2, *qa3, *qa4, *qa5, *qa6;
    float *k7, *sb2, *sb3, *sb4, *sb5, *sb6;
    unsigned *sa2, *sa3, *sa4, *sa5, *sa6, *mm3;
    float *t1, *t2, *t3, *t4, *t5, *t6, *t7, *t8, *aff, *st2;
    cudaGetSymbolAddress((void**)&q2, g_q2);
    cudaGetSymbolAddress((void**)&q3, g_q3);
    cudaGetSymbolAddress((void**)&q4, g_q4);
    cudaGetSymbolAddress((void**)&q5, g_q5);
    cudaGetSymbolAddress((void**)&q6, g_q6);
    cudaGetSymbolAddress((void**)&qa2, g_qa2);
    cudaGetSymbolAddress((void**)&qa3, g_qa3);
    cudaGetSymbolAddress((void**)&qa4, g_qa4);
    cudaGetSymbolAddress((void**)&qa5, g_qa5);
    cudaGetSymbolAddress((void**)&qa6, g_qa6);
    cudaGetSymbolAddress((void**)&sb2, g_sb2);
    cudaGetSymbolAddress((void**)&sb3, g_sb3);
    cudaGetSymbolAddress((void**)&sb4, g_sb4);
    cudaGetSymbolAddress((void**)&sb5, g_sb5);
    cudaGetSymbolAddress((void**)&sb6, g_sb6);
    cudaGetSymbolAddress((void**)&sa2, g_sa2);
    cudaGetSymbolAddress((void**)&sa3, g_sa3);
    cudaGetSymbolAddress((void**)&sa4, g_sa4);
    cudaGetSymbolAddress((void**)&sa5, g_sa5);
    cudaGetSymbolAddress((void**)&sa6, g_sa6);
    cudaGetSymbolAddress((void**)&mm3, g_mm3);
    cudaGetSymbolAddress((void**)&c1, g_c1);
    cudaGetSymbolAddress((void**)&k7, g_k7);
    cudaGetSymbolAddress((void**)&t1, g_t1);
    cudaGetSymbolAddress((void**)&t2, g_t2);
    cudaGetSymbolAddress((void**)&t3, g_t3);
    cudaGetSymbolAddress((void**)&t4, g_t4);
    cudaGetSymbolAddress((void**)&t5, g_t5);
    cudaGetSymbolAddress((void**)&t6, g_t6);
    cudaGetSymbolAddress((void**)&t7, g_t7);
    cudaGetSymbolAddress((void**)&t8, g_t8);
    cudaGetSymbolAddress((void**)&aff, g_aff);
    cudaGetSymbolAddress((void**)&st2, g_st2);

    const int AOFF = 16 * 64 * 2;

    cudaFuncSetAttribute(conv_i8p_kernel<16, 256, 1>, cudaFuncAttributeMaxDynamicSharedMemorySize,
                         i8p_smem(16, 1));
    cudaFuncSetAttribute(conv_i8p_kernel<32, 128, 2>, cudaFuncAttributeMaxDynamicSharedMemorySize,
                         i8p_smem(32, 2));
    cudaFuncSetAttribute(conv_i8_kernel<32, 32, 128, 1>,
                         cudaFuncAttributeMaxDynamicSharedMemorySize, i8_smem(32, 1));
    cudaFuncSetAttribute(conv_i8_kernel<32, 64, 128, 2>,
                         cudaFuncAttributeMaxDynamicSharedMemorySize, i8_smem(64, 2));
    cudaFuncSetAttribute(conv_i8_kernel<64, 64, 128, 1>,
                         cudaFuncAttributeMaxDynamicSharedMemorySize, i8_smem(64, 1));

    // init + weight gen/quant
    init_kernel<<<1, 512>>>(st2, mm3, sa2, sa3, sa4, sa5, sa6);
    genB_kernel<<<66, 256>>>(w[0], wb[0], w[6], wb[6], action, c1, k7);
    gi8_amax_kernel<<<16 * 16, 256>>>(w[1], wb[1], action, sb2, 16, 16);
    gi8_amax_kernel<<<16 * 32, 256>>>(w[2], wb[2], action, sb3, 16, 32);
    gi8_amax_kernel<<<16 * 32, 256>>>(w[3], wb[3], action, sb4, 32, 32);
    gi8_amax_kernel<<<16 * 64, 256>>>(w[4], wb[4], action, sb5, 32, 64);
    gi8_amax_kernel<<<16 * 64, 256>>>(w[5], wb[5], action, sb6, 64, 64);
    gi8p_quant_kernel<<<104, 256>>>(w[1], wb[1], action, sb2, q2, 16);
    gi8p_quant_kernel<<<208, 256>>>(w[2], wb[2], action, sb3, q3, 32);
    gi8_quant_kernel<<<400, 256>>>(w[3], wb[3], action, sb4, q4, 32, 32);
    gi8_quant_kernel<<<800, 256>>>(w[4], wb[4], action, sb5, q5, 32, 64);
    gi8_quant_kernel<<<1600, 256>>>(w[5], wb[5], action, sb6, q6, 64, 64);
    // bn0 stats on x
    stats_kernel<65536><<<16 * 4, 256>>>(x, bns[0], bnb[0], aff + 0 * AOFF, 4);
    // conv1 (bf16 k8)
    conv1_k8_kernel<<<dim3(8, 8, 16), 256>>>(x, aff + 0 * AOFF, c1, t1);
    // bn1 stats + amax -> conv2 int8
    stats_amax_kernel<65536><<<16 * 16, 256>>>(t1, bns[1], bnb[1], aff + 1 * AOFF, 16, sa2, 1);
    quant_act16_kernel<<<4096, 256>>>(t1, aff + 1 * AOFF, sa2, qa2, 16, 1);
    conv_i8p_kernel<16, 256, 1>
        <<<dim3(8, 64, 16), 256, i8p_smem(16, 1)>>>(qa2, q2, sb2, sa2, t2);
    // avgpool + bn2 stats + min/max
    avgpool_stats_kernel<<<16384, 256>>>(t2, t3, st2, mm3);
    fin3_kernel<<<1, 256>>>(st2, mm3, bns[2], bnb[2], aff + 2 * AOFF, sa3);
    quant_act16_kernel<<<1024, 256>>>(t3, aff + 2 * AOFF, sa3, qa3, 14, 0);
    conv_i8p_kernel<32, 128, 2>
        <<<dim3(4, 32, 16), 256, i8p_smem(32, 2)>>>(qa3, q3, sb3, sa3, t4);
    // bn3 stats + relu amax -> conv4 int8
    stats_amax_kernel<16384><<<16 * 32, 256>>>(t4, bns[3], bnb[3], aff + 3 * AOFF, 32, sa4, 1);
    quant_act_kernel<<<1024, 256>>>(t4, aff + 3 * AOFF, sa4, qa4, 1, 1);
    conv_i8_kernel<32, 32, 128, 1>
        <<<dim3(4, 32, 16), 256, i8_smem(32, 1)>>>(qa4, q4, sb4, sa4, t5);
    // bn4 stats + abs amax -> conv5 int8
    stats_amax_kernel<16384><<<16 * 32, 256>>>(t5, bns[4], bnb[4], aff + 4 * AOFF, 32, sa5, 0);
    quant_act_kernel<<<1024, 256>>>(t5, aff + 4 * AOFF, sa5, qa5, 1, 0);
    conv_i8_kernel<32, 64, 128, 2>
        <<<dim3(4, 32, 16), 256, i8_smem(64, 2)>>>(qa5, q5, sb5, sa5, t6);
    // bn5 stats + relu amax -> conv6 int8
    stats_amax_kernel<16384><<<16 * 64, 256>>>(t6, bns[5], bnb[5], aff + 5 * AOFF, 64, sa6, 1);
    quant_act_kernel<<<2048, 256>>>(t6, aff + 5 * AOFF, sa6, qa6, 2, 1);
    conv_i8_kernel<64, 64, 128, 1>
        <<<dim3(4, 32, 16), 256, i8_smem(64, 1)>>>(qa6, q6, sb6, sa6, t7);
    // bn6, conv7, upsample+residual
    stats_kernel<16384><<<16 * 64, 256>>>(t7, bns[6], bnb[6], aff + 6 * AOFF, 64);
    conv1x1_kernel<<<dim3(64, 16), 256>>>(t7, aff + 6 * AOFF, k7, t8);
    up_add_kernel<<<(16 * 4 * 256 * 256 + 255) / 256, 256>>>(t8, x, (float*)d_out);
}

// round 17
// speedup vs baseline: 1.7060x; 1.0115x over previous
#include <cuda_runtime.h>
#include <cuda_fp16.h>
#include <cstdint>

#define EPS 1e-5f

// ---------------- scratch (static __device__ — no allocation) ----------------
__device__ float g_k7[16 * 4 * 64];

// int8 weights
__device__ uint2 g_q1[16 * 4 * 16 * 8];      // conv1 paired-8tap: [b][g4][co][8 uint2]
__device__ uint2 g_q2[16 * 13 * 16 * 8];     // paired-tap
__device__ uint2 g_q3[16 * 13 * 32 * 8];
__device__ uint2 g_q4[16 * 1 * 25 * 32 * 8]; // chunked
__device__ uint2 g_q5[16 * 1 * 25 * 64 * 8];
__device__ uint2 g_q6[16 * 2 * 25 * 64 * 8];
// quantized activations
__device__ uint2 g_qa1[16 * 65536];          // 4ch: [b][pix][hi u32, lo u32]
__device__ uint4 g_qa2[16 * 65536 * 2];      // 16ch
__device__ uint4 g_qa3[16 * 16384 * 2];
__device__ uint4 g_qa4[16 * 1 * 16384 * 4];  // 32ch chunks
__device__ uint4 g_qa5[16 * 1 * 16384 * 4];
__device__ uint4 g_qa6[16 * 2 * 16384 * 4];
__device__ float g_sb1[16 * 16];
__device__ float g_sb2[16 * 16];
__device__ float g_sb3[16 * 32];
__device__ float g_sb4[16 * 32];
__device__ float g_sb5[16 * 64];
__device__ float g_sb6[16 * 64];
__device__ unsigned g_sa1[16], g_sa2[16], g_sa3[16], g_sa4[16], g_sa5[16], g_sa6[16];
__device__ unsigned g_mm3[16 * 16 * 2];

// intermediate tensors in fp16 (t8 stays fp32)
__device__ __half g_t1[16 * 16 * 256 * 256];
__device__ __half g_t2[16 * 16 * 256 * 256];
__device__ __half g_t3[16 * 16 * 128 * 128];
__device__ __half g_t4[16 * 32 * 128 * 128];
__device__ __half g_t5[16 * 32 * 128 * 128];
__device__ __half g_t6[16 * 64 * 128 * 128];
__device__ __half g_t7[16 * 64 * 128 * 128];
__device__ float g_t8[16 * 4 * 128 * 128];

__device__ float g_aff[7 * 16 * 64 * 2];
__device__ float g_st2[16 * 16 * 2];

// ---------------- helpers ----------------
__device__ __forceinline__ void mma_s8(int c[4], uint32_t a0, uint32_t a1, uint32_t a2,
                                       uint32_t a3, uint32_t b0, uint32_t b1) {
    asm volatile(
        "mma.sync.aligned.m16n8k32.row.col.s32.s8.s8.s32 "
        "{%0,%1,%2,%3},{%4,%5,%6,%7},{%8,%9},{%0,%1,%2,%3};"
        : "+r"(c[0]), "+r"(c[1]), "+r"(c[2]), "+r"(c[3])
        : "r"(a0), "r"(a1), "r"(a2), "r"(a3), "r"(b0), "r"(b1));
}

__device__ __forceinline__ int qclamp(float rr) {
    int v = __float2int_rn(rr);
    return max(-127, min(127, v));
}

__device__ __forceinline__ unsigned fkey(float v) {
    unsigned u = __float_as_uint(v);
    return (u & 0x80000000u) ? ~u : (u | 0x80000000u);
}
__device__ __forceinline__ float funkey(unsigned m) {
    unsigned u = (m & 0x80000000u) ? (m ^ 0x80000000u) : ~m;
    return __uint_as_float(u);
}

__device__ __forceinline__ float ldval(const float* p) { return *p; }
__device__ __forceinline__ float ldval(const __half* p) { return __half2float(*p); }

// ---------------- init (+ conv7 weights) ----------------
__global__ void init_kernel(float* st2, unsigned* mm3, unsigned* sa1, unsigned* sa2, unsigned* sa3,
                            unsigned* sa4, unsigned* sa5, unsigned* sa6, const float* w7,
                            const float* b7, const int* __restrict__ action, float* k7) {
    int i = blockIdx.x * 256 + threadIdx.x;
    if (i < 512) {
        st2[i] = 0.f;
        mm3[i] = (i & 1) ? 0u : 0xFFFFFFFFu;
    }
    if (i < 16) {
        sa1[i] = 0u;
        sa2[i] = 0u;
        sa3[i] = 0u;
        sa4[i] = 0u;
        sa5[i] = 0u;
        sa6[i] = 0u;
    }
    if (i < 4096) {
        int b = i / 256, o = i - b * 256;
        k7[i] = w7[o * 6 + action[b]] + b7[o];
    }
}

// ---------------- int8 weight amax (layout (co*CIN+ci)*25+tap) ----------------
__global__ void gi8_amax_kernel(const float* __restrict__ w, const float* __restrict__ bias,
                                const int* __restrict__ action, float* __restrict__ sb, int CIN,
                                int COUT) {
    int bc = blockIdx.x;
    int b = bc / COUT, co = bc - b * COUT;
    int a = action[b];
    int K = CIN * 25;
    float m = 0.f;
    for (int i = threadIdx.x; i < K; i += 256) {
        int o = co * K + i;
        m = fmaxf(m, fabsf(w[o * 6 + a] + bias[o]));
    }
    __shared__ float sm[256];
    sm[threadIdx.x] = m;
    __syncthreads();
    for (int st = 128; st > 0; st >>= 1) {
        if (threadIdx.x < st) sm[threadIdx.x] = fmaxf(sm[threadIdx.x], sm[threadIdx.x + st]);
        __syncthreads();
    }
    if (threadIdx.x == 0) sb[bc] = fmaxf(sm[0], 1e-20f);
}

// ---------------- conv1 weight quantize: [b][g4][co][8 uint2] ----------------
__global__ void gi8c1_quant_kernel(const float* __restrict__ w, const float* __restrict__ bias,
                                   const int* __restrict__ action, const float* __restrict__ sb,
                                   uint2* __restrict__ q) {
    int idx = blockIdx.x * 256 + threadIdx.x;
    if (idx >= 16 * 4 * 16 * 8) return;
    int j = idx & 7;
    int r = idx >> 3;
    int co = r & 15;
    r >>= 4;
    int g = r & 3;
    int b = r >> 2;
    int a = action[b];
    int is_l = j >> 2, tg = j & 3;
    float inv = 127.f / sb[b * 16 + co];
    uint32_t wd[2];
#pragma unroll
    for (int wdi = 0; wdi < 2; wdi++) {
        int tap = 8 * g + 2 * tg + wdi;
        uint32_t pk = 0;
        if (tap < 25) {
#pragma unroll
            for (int ch = 0; ch < 4; ch++) {
                int o = (co * 4 + ch) * 25 + tap;
                float v = w[o * 6 + a] + bias[o];
                float rr = v * inv;
                int qh = qclamp(rr);
                int byte = is_l ? qclamp((rr - (float)qh) * 128.f) : qh;
                pk |= ((uint32_t)(uint8_t)(int8_t)byte) << (ch * 8);
            }
        }
        wd[wdi] = pk;
    }
    q[idx] = make_uint2(wd[0], wd[1]);
}

// ---------------- chunked weight quantize (conv4/5/6) ----------------
__global__ void gi8_quant_kernel(const float* __restrict__ w, const float* __restrict__ bias,
                                 const int* __restrict__ action, const float* __restrict__ sb,
                                 uint2* __restrict__ q, int CIN, int COUT) {
    int NCH = CIN / 32;
    int total = 16 * NCH * 25 * COUT * 8;
    int idx = blockIdx.x * 256 + threadIdx.x;
    if (idx >= total) return;
    int j = idx & 7;
    int r = idx >> 3;
    int co = r % COUT;
    r /= COUT;
    int tap = r % 25;
    r /= 25;
    int ch = r % NCH;
    int b = r / NCH;
    int a = action[b];
    float inv = 127.f / sb[b * COUT + co];
    int jj = j & 3;
    int is_l = j >> 2;
    uint32_t wd[2];
#pragma unroll
    for (int half = 0; half < 2; half++) {
        uint32_t pk = 0;
#pragma unroll
        for (int e = 0; e < 4; e++) {
            int k = half * 16 + jj * 4 + e;
            int ci = ch * 32 + k;
            int o = (co * CIN + ci) * 25 + tap;
            float v = w[o * 6 + a] + bias[o];
            float rr = v * inv;
            int qh = qclamp(rr);
            int byte = is_l ? qclamp((rr - (float)qh) * 128.f) : qh;
            pk |= ((uint32_t)(uint8_t)(int8_t)byte) << (e * 8);
        }
        wd[half] = pk;
    }
    q[idx] = make_uint2(wd[0], wd[1]);
}

// ---------------- paired-tap weight quantize (conv2/3, CIN=16) ----------------
__global__ void gi8p_quant_kernel(const float* __restrict__ w, const float* __restrict__ bias,
                                  const int* __restrict__ action, const float* __restrict__ sb,
                                  uint2* __restrict__ q, int COUT) {
    int total = 16 * 13 * COUT * 8;
    int idx = blockIdx.x * 256 + threadIdx.x;
    if (idx >= total) return;
    int j = idx & 7;
    int r = idx >> 3;
    int co = r % COUT;
    r /= COUT;
    int g = r % 13;
    int b = r / 13;
    int a = action[b];
    int tA = 2 * g, tB = (g == 12) ? -1 : 2 * g + 1;
    float inv = 127.f / sb[b * COUT + co];
    int is_l = j >> 2;
    int tgj = j & 3;
    uint32_t wd[2];
#pragma unroll
    for (int half = 0; half < 2; half++) {
        uint32_t pk = 0;
#pragma unroll
        for (int e = 0; e < 4; e++) {
            int k = tgj * 8 + half * 4 + e;
            int ch = k & 15;
            int tap = (k < 16) ? tA : tB;
            int byte = 0;
            if (tap >= 0) {
                int o = (co * 16 + ch) * 25 + tap;
                float v = w[o * 6 + a] + bias[o];
                float rr = v * inv;
                int qh = qclamp(rr);
                byte = is_l ? qclamp((rr - (float)qh) * 128.f) : qh;
            }
            pk |= ((uint32_t)(uint8_t)(int8_t)byte) << (e * 8);
        }
        wd[half] = pk;
    }
    q[idx] = make_uint2(wd[0], wd[1]);
}

// ---------------- BN stats (templated on tensor type) ----------------
template <typename T, int N>
__global__ void stats_kernel(const T* __restrict__ in, const float* __restrict__ s,
                             const float* __restrict__ bb, float* __restrict__ aff, int C) {
    int bc = blockIdx.x;
    const T* p = in + (size_t)bc * N;
    float sum = 0.f, sq = 0.f;
    for (int i = threadIdx.x; i < N; i += 256) {
        float v = ldval(p + i);
        sum += v;
        sq += v * v;
    }
    __shared__ float ssum[256], ssq[256];
    ssum[threadIdx.x] = sum;
    ssq[threadIdx.x] = sq;
    __syncthreads();
    for (int st = 128; st > 0; st >>= 1) {
        if (threadIdx.x < st) {
            ssum[threadIdx.x] += ssum[threadIdx.x + st];
            ssq[threadIdx.x] += ssq[threadIdx.x + st];
        }
        __syncthreads();
    }
    if (threadIdx.x == 0) {
        int c = bc % C;
        float mean = ssum[0] / (float)N;
        float var = ssq[0] / (float)N - mean * mean;
        float sc = rsqrtf(var + EPS) * s[c];
        aff[2 * bc] = sc;
        aff[2 * bc + 1] = bb[c] - mean * sc;
    }
}

template <typename T, int N>
__global__ void stats_amax_kernel(const T* __restrict__ in, const float* __restrict__ s,
                                  const float* __restrict__ bb, float* __restrict__ aff, int C,
                                  unsigned* __restrict__ sa, int relu) {
    int bc = blockIdx.x;
    const T* p = in + (size_t)bc * N;
    float sum = 0.f, sq = 0.f, mn = 1e30f, mx = -1e30f;
    for (int i = threadIdx.x; i < N; i += 256) {
        float v = ldval(p + i);
        sum += v;
        sq += v * v;
        mn = fminf(mn, v);
        mx = fmaxf(mx, v);
    }
    __shared__ float ssum[256], ssq[256], smn[256], smx[256];
    ssum[threadIdx.x] = sum;
    ssq[threadIdx.x] = sq;
    smn[threadIdx.x] = mn;
    smx[threadIdx.x] = mx;
    __syncthreads();
    for (int st = 128; st > 0; st >>= 1) {
        if (threadIdx.x < st) {
            ssum[threadIdx.x] += ssum[threadIdx.x + st];
            ssq[threadIdx.x] += ssq[threadIdx.x + st];
            smn[threadIdx.x] = fminf(smn[threadIdx.x], smn[threadIdx.x + st]);
            smx[threadIdx.x] = fmaxf(smx[threadIdx.x], smx[threadIdx.x + st]);
        }
        __syncthreads();
    }
    if (threadIdx.x == 0) {
        int c = bc % C, b = bc / C;
        float mean = ssum[0] / (float)N;
        float var = ssq[0] / (float)N - mean * mean;
        float sc = rsqrtf(var + EPS) * s[c];
        float bi = bb[c] - mean * sc;
        aff[2 * bc] = sc;
        aff[2 * bc + 1] = bi;
        float e0 = smn[0] * sc + bi, e1 = smx[0] * sc + bi;
        float hi = fmaxf(e0, e1), lo = fminf(e0, e1);
        float amax = relu ? fmaxf(0.f, hi) : fmaxf(fabsf(hi), fabsf(lo));
        atomicMax(sa + b, __float_as_uint(amax));
    }
}

// bn2 finalize + conv3 input amax
__global__ void fin3_kernel(const float* __restrict__ st, const unsigned* __restrict__ mm,
                            const float* __restrict__ s, const float* __restrict__ bb,
                            float* __restrict__ aff, unsigned* __restrict__ sa) {
    int i = threadIdx.x;
    if (i >= 256) return;
    int b = i >> 4, c = i & 15;
    float sum = st[i * 2];
    float sq = st[i * 2 + 1];
    float mean = sum * (1.f / 65536.f);
    float var = sq * (1.f / 65536.f) - mean * mean;
    float sc = rsqrtf(var + EPS) * s[c];
    float bi = bb[c] - mean * sc;
    aff[2 * i] = sc;
    aff[2 * i + 1] = bi;
    float mn = funkey(mm[i * 2]), mx = funkey(mm[i * 2 + 1]);
    float e0 = mn * sc + bi, e1 = mx * sc + bi;
    float amax = fmaxf(fabsf(e0), fabsf(e1));
    atomicMax(sa + b, __float_as_uint(amax));
}

// ---------------- activation quantize: x (4ch fp32) -> qa1 ----------------
__global__ void quant_act4_kernel(const float* __restrict__ x, const float* __restrict__ aff,
                                  const unsigned* __restrict__ sa, uint2* __restrict__ qa) {
    int idx = blockIdx.x * 256 + threadIdx.x;
    int pix = idx & 65535;
    int b = idx >> 16;
    float sA = __uint_as_float(sa[b]);
    float inv = (sA > 0.f) ? 127.f / sA : 0.f;
    uint32_t hw = 0, lw = 0;
#pragma unroll
    for (int c = 0; c < 4; c++) {
        float v = fmaf(x[((size_t)(b * 4 + c) << 16) + pix], __ldg(aff + (b * 4 + c) * 2),
                       __ldg(aff + (b * 4 + c) * 2 + 1));
        float rr = v * inv;
        int qh = qclamp(rr);
        int ql = qclamp((rr - (float)qh) * 128.f);
        hw |= ((uint32_t)(uint8_t)(int8_t)qh) << (c * 8);
        lw |= ((uint32_t)(uint8_t)(int8_t)ql) << (c * 8);
    }
    qa[idx] = make_uint2(hw, lw);
}

// ---------------- activation quantize (16ch, fp16 input) ----------------
__global__ void quant_act16_kernel(const __half* __restrict__ t, const float* __restrict__ aff,
                                   const unsigned* __restrict__ sa, uint4* __restrict__ qa,
                                   int h2log, int relu) {
    int idx = blockIdx.x * 256 + threadIdx.x;
    int pix = idx & ((1 << h2log) - 1);
    int b = idx >> h2log;
    size_t H2 = (size_t)1 << h2log;
    float sA = __uint_as_float(sa[b]);
    float inv = (sA > 0.f) ? 127.f / sA : 0.f;
    const __half* base = t + (size_t)b * 16 * H2 + pix;
    const float* af = aff + b * 16 * 2;
    uint32_t Hw[4], Lw[4];
#pragma unroll
    for (int k = 0; k < 4; k++) {
        Hw[k] = 0;
        Lw[k] = 0;
    }
#pragma unroll
    for (int c = 0; c < 16; c++) {
        float v = fmaf(__half2float(base[(size_t)c * H2]), __ldg(af + 2 * c),
                       __ldg(af + 2 * c + 1));
        if (relu) v = fmaxf(v, 0.f);
        float rr = v * inv;
        int qh = qclamp(rr);
        int ql = qclamp((rr - (float)qh) * 128.f);
        int wi = c >> 2, sh = (c & 3) * 8;
        Hw[wi] |= ((uint32_t)(uint8_t)(int8_t)qh) << sh;
        Lw[wi] |= ((uint32_t)(uint8_t)(int8_t)ql) << sh;
    }
    uint4* dst = qa + (size_t)idx * 2;
    dst[0] = make_uint4(Hw[0], Hw[1], Hw[2], Hw[3]);
    dst[1] = make_uint4(Lw[0], Lw[1], Lw[2], Lw[3]);
}

// ---------------- activation quantize (32ch chunks, fp16 input) ----------------
__global__ void quant_act_kernel(const __half* __restrict__ t, const float* __restrict__ aff,
                                 const unsigned* __restrict__ sa, uint4* __restrict__ qa, int NCH,
                                 int relu) {
    int idx = blockIdx.x * 256 + threadIdx.x;
    int pix = idx & 16383;
    int r = idx >> 14;
    int ch = r % NCH;
    int b = r / NCH;
    int C = NCH * 32;
    float sA = __uint_as_float(sa[b]);
    float inv = (sA > 0.f) ? 127.f / sA : 0.f;
    const __half* base = t + ((size_t)(b * C + ch * 32)) * 16384 + pix;
    const float* af = aff + (b * C + ch * 32) * 2;
    uint32_t Hw[8], Lw[8];
#pragma unroll
    for (int k = 0; k < 8; k++) {
        Hw[k] = 0;
        Lw[k] = 0;
    }
#pragma unroll
    for (int c = 0; c < 32; c++) {
        float v = fmaf(__half2float(base[(size_t)c * 16384]), __ldg(af + 2 * c),
                       __ldg(af + 2 * c + 1));
        if (relu) v = fmaxf(v, 0.f);
        float rr = v * inv;
        int qh = qclamp(rr);
        int ql = qclamp((rr - (float)qh) * 128.f);
        int wi = (c < 16) ? 2 * (c >> 2) : 2 * ((c - 16) >> 2) + 1;
        int sh = (c & 3) * 8;
        Hw[wi] |= ((uint32_t)(uint8_t)(int8_t)qh) << sh;
        Lw[wi] |= ((uint32_t)(uint8_t)(int8_t)ql) << sh;
    }
    uint4* dst = qa + (size_t)idx * 4;
    dst[0] = make_uint4(Hw[0], Hw[1], Hw[2], Hw[3]);
    dst[1] = make_uint4(Hw[4], Hw[5], Hw[6], Hw[7]);
    dst[2] = make_uint4(Lw[0], Lw[1], Lw[2], Lw[3]);
    dst[3] = make_uint4(Lw[4], Lw[5], Lw[6], Lw[7]);
}

// ---------------- conv1 int8x2: CIN=4, k32 = 8 taps x 4ch; tile 32x8 ----------------
__global__ __launch_bounds__(256) void conv1_i8_kernel(const uint2* __restrict__ qa,
                                                       const uint2* __restrict__ qw,
                                                       const float* __restrict__ sb,
                                                       const unsigned* __restrict__ sa,
                                                       __half* __restrict__ out) {
    const int H = 256, R = 4;
    __shared__ uint2 patch[40 * 16];
    __shared__ uint2 wt[4 * 16 * 8];
    __shared__ float sAB[16];

    int tid = threadIdx.x, wid = tid >> 5, lane = tid & 31;
    int tg = lane & 3, gid = lane >> 2;
    int bx0 = blockIdx.x * 32, by0 = blockIdx.y * 8, b = blockIdx.z;

    if (tid < 16) {
        float sA = __uint_as_float(sa[b]);
        sAB[tid] = sA * sb[b * 16 + tid] * (1.f / 16129.f);
    }
    for (int p = tid; p < 640; p += 256) {
        int py = p / 40, px = p - py * 40;
        int gy = by0 - R + py, gx = bx0 - R + px;
        patch[p] = ((unsigned)gy < 256u && (unsigned)gx < 256u)
                       ? qa[((size_t)b << 16) + gy * 256 + gx]
                       : make_uint2(0u, 0u);
    }
    for (int i = tid; i < 512; i += 256) wt[i] = qw[b * 512 + i];
    __syncthreads();

    int acch[2][2][4], accc[2][2][4];
#pragma unroll
    for (int mt = 0; mt < 2; mt++)
#pragma unroll
        for (int nt = 0; nt < 2; nt++)
#pragma unroll
            for (int k = 0; k < 4; k++) {
                acch[mt][nt][k] = 0;
                accc[mt][nt][k] = 0;
            }

#pragma unroll
    for (int g = 0; g < 4; g++) {
        int tapA = 8 * g + 2 * tg;
        int tapB = tapA + 1;
        int offA = (tapA < 25) ? ((tapA / 5) * 2 * 40 + (tapA % 5) * 2) : 0;
        int offB = (tapB < 25) ? ((tapB / 5) * 2 * 40 + (tapB % 5) * 2) : 0;
#pragma unroll
        for (int mt = 0; mt < 2; mt++) {
            int p0 = wid * 40 + mt * 16 + gid;
            uint2 rA0 = patch[p0 + offA];
            uint2 rA1 = patch[p0 + 8 + offA];
            uint2 rB0 = patch[p0 + offB];
            uint2 rB1 = patch[p0 + 8 + offB];
#pragma unroll
            for (int nt = 0; nt < 2; nt++) {
                int co = nt * 8 + gid;
                uint2 wh = wt[(g * 16 + co) * 8 + tg];
                uint2 wl = wt[(g * 16 + co) * 8 + 4 + tg];
                mma_s8(acch[mt][nt], rA0.x, rA1.x, rB0.x, rB1.x, wh.x, wh.y);
                mma_s8(accc[mt][nt], rA0.y, rA1.y, rB0.y, rB1.y, wh.x, wh.y);
                mma_s8(accc[mt][nt], rA0.x, rA1.x, rB0.x, rB1.x, wl.x, wl.y);
            }
        }
    }

    int gy = by0 + wid;
#pragma unroll
    for (int mt = 0; mt < 2; mt++) {
        int gx = bx0 + mt * 16 + gid;
#pragma unroll
        for (int nt = 0; nt < 2; nt++) {
            int co = nt * 8 + 2 * tg;
            float s0 = sAB[co], s1 = sAB[co + 1];
            __half* o = out + ((size_t)(b * 16 + co) * H + gy) * H;
            o[gx] = __float2half(s0 * fmaf((float)accc[mt][nt][0], 0.0078125f,
                                           (float)acch[mt][nt][0]));
            o[(size_t)H * H + gx] = __float2half(
                s1 * fmaf((float)accc[mt][nt][1], 0.0078125f, (float)acch[mt][nt][1]));
            o[gx + 8] = __float2half(s0 * fmaf((float)accc[mt][nt][2], 0.0078125f,
                                               (float)acch[mt][nt][2]));
            o[(size_t)H * H + gx + 8] = __float2half(
                s1 * fmaf((float)accc[mt][nt][3], 0.0078125f, (float)acch[mt][nt][3]));
        }
    }
}

// ---------------- int8x2 paired-tap conv (conv2/3, CIN=16) ----------------
template <int COUT, int H, int DIL>
__global__ __launch_bounds__(256, 2) void conv_i8p_kernel(const uint4* __restrict__ qa,
                                                          const uint2* __restrict__ qw,
                                                          const float* __restrict__ sb,
                                                          const unsigned* __restrict__ sa,
                                                          __half* __restrict__ out) {
    constexpr int NT = COUT / 8;
    constexpr int R = 2 * DIL;
    constexpr int PXP = 32 + 2 * R;
    constexpr int PYP = 4 + 2 * R;
    constexpr int NPIX = PXP * PYP;

    extern __shared__ uint4 smp[];
    uint4* patch = smp;
    uint2* wt = (uint2*)(smp + NPIX * 2);
    float* sAB = (float*)(wt + 13 * COUT * 8);

    int tid = threadIdx.x, wid = tid >> 5, lane = tid & 31;
    int tg = lane & 3, gid = lane >> 2;
    int yin = wid >> 1, xh = wid & 1;
    int bx0 = blockIdx.x * 32, by0 = blockIdx.y * 4, b = blockIdx.z;

    if (tid < COUT) {
        float sA = __uint_as_float(sa[b]);
        sAB[tid] = sA * sb[b * COUT + tid] * (1.f / 16129.f);
    }
    for (int p = tid; p < NPIX; p += 256) {
        int py = p / PXP, px = p - py * PXP;
        int gy = by0 - R + py, gx = bx0 - R + px;
        if ((unsigned)gy < (unsigned)H && (unsigned)gx < (unsigned)H) {
            const uint4* s4 = qa + ((size_t)(b * H + gy) * H + gx) * 2;
            patch[p * 2] = s4[0];
            patch[p * 2 + 1] = s4[1];
        } else {
            uint4 z = make_uint4(0, 0, 0, 0);
            patch[p * 2] = z;
            patch[p * 2 + 1] = z;
        }
    }
    {
        const uint2* wcb = qw + (size_t)b * 13 * COUT * 8;
        for (int i = tid; i < 13 * COUT * 8; i += 256) wt[i] = wcb[i];
    }
    __syncthreads();

    int acch[NT][4], accc[NT][4];
#pragma unroll
    for (int nt = 0; nt < NT; nt++)
#pragma unroll
        for (int k = 0; k < 4; k++) {
            acch[nt][k] = 0;
            accc[nt][k] = 0;
        }

    const uint2* pv = (const uint2*)patch;
    int p0 = yin * PXP + xh * 16 + gid;
    int u = tg & 1;

#pragma unroll
    for (int g = 0; g < 13; g++) {
        int tA = 2 * g;
        int tB = (g == 12) ? tA : tA + 1;
        int offA = (tA / 5) * DIL * PXP + (tA % 5) * DIL;
        int offB = (tB / 5) * DIL * PXP + (tB % 5) * DIL;
        int off = (tg < 2) ? offA : offB;
        int pp = p0 + off;
        uint2 Ah0 = pv[pp * 4 + u];
        uint2 Ah1 = pv[(pp + 8) * 4 + u];
        uint2 Al0 = pv[pp * 4 + 2 + u];
        uint2 Al1 = pv[(pp + 8) * 4 + 2 + u];
#pragma unroll
        for (int nt = 0; nt < NT; nt++) {
            int co = nt * 8 + gid;
            uint2 Bh = wt[(g * COUT + co) * 8 + tg];
            uint2 Bl = wt[(g * COUT + co) * 8 + 4 + tg];
            mma_s8(acch[nt], Ah0.x, Ah1.x, Ah0.y, Ah1.y, Bh.x, Bh.y);
            mma_s8(accc[nt], Al0.x, Al1.x, Al0.y, Al1.y, Bh.x, Bh.y);
            mma_s8(accc[nt], Ah0.x, Ah1.x, Ah0.y, Ah1.y, Bl.x, Bl.y);
        }
    }

    int gy = by0 + yin, gx = bx0 + xh * 16 + gid;
#pragma unroll
    for (int nt = 0; nt < NT; nt++) {
        int co = nt * 8 + 2 * tg;
        float s0 = sAB[co], s1 = sAB[co + 1];
        __half* o = out + ((size_t)(b * COUT + co) * H + gy) * H;
        o[gx] = __float2half(s0 * fmaf((float)accc[nt][0], 0.0078125f, (float)acch[nt][0]));
        o[(size_t)H * H + gx] =
            __float2half(s1 * fmaf((float)accc[nt][1], 0.0078125f, (float)acch[nt][1]));
        o[gx + 8] = __float2half(s0 * fmaf((float)accc[nt][2], 0.0078125f, (float)acch[nt][2]));
        o[(size_t)H * H + gx + 8] =
            __float2half(s1 * fmaf((float)accc[nt][3], 0.0078125f, (float)acch[nt][3]));
    }
}

// ---------------- int8x2 chunked conv (conv4/5/6) ----------------
template <int CIN, int COUT, int H, int DIL>
__global__ __launch_bounds__(256, 2) void conv_i8_kernel(const uint4* __restrict__ qa,
                                                         const uint2* __restrict__ qw,
                                                         const float* __restrict__ sb,
                                                         const unsigned* __restrict__ sa,
                                                         __half* __restrict__ out) {
    constexpr int NCH = CIN / 32;
    constexpr int NT = COUT / 8;
    constexpr int R = 2 * DIL;
    constexpr int PXP = 32 + 2 * R;
    constexpr int PYP = 4 + 2 * R;
    constexpr int NPIX = PXP * PYP;

    extern __shared__ uint2 smq[];
    uint2* patch = smq;
    uint2* wt = smq + NPIX * 8;
    float* sAB = (float*)(smq + NPIX * 8 + 5 * COUT * 8);

    int tid = threadIdx.x, wid = tid >> 5, lane = tid & 31;
    int tg = lane & 3, gid = lane >> 2;
    int yin = wid >> 1, xh = wid & 1;
    int bx0 = blockIdx.x * 32, by0 = blockIdx.y * 4, b = blockIdx.z;

    if (tid < COUT) {
        float sA = __uint_as_float(sa[b]);
        sAB[tid] = sA * sb[b * COUT + tid] * (1.f / 16129.f);
    }

    int acch[NT][4], accc[NT][4];
#pragma unroll
    for (int nt = 0; nt < NT; nt++)
#pragma unroll
        for (int k = 0; k < 4; k++) {
            acch[nt][k] = 0;
            accc[nt][k] = 0;
        }

    for (int ch = 0; ch < NCH; ch++) {
        __syncthreads();
        for (int p = tid; p < NPIX; p += 256) {
            int py = p / PXP, px = p - py * PXP;
            int gy = by0 - R + py, gx = bx0 - R + px;
            uint4* d4 = (uint4*)(patch + p * 8);
            if ((unsigned)gy < (unsigned)H && (unsigned)gx < (unsigned)H) {
                const uint4* s4 = qa + ((size_t)((b * NCH + ch) * H + gy) * H + gx) * 4;
                d4[0] = s4[0];
                d4[1] = s4[1];
                d4[2] = s4[2];
                d4[3] = s4[3];
            } else {
                uint4 z = make_uint4(0, 0, 0, 0);
                d4[0] = z;
                d4[1] = z;
                d4[2] = z;
                d4[3] = z;
            }
        }
        const uint2* wcb = qw + ((size_t)(b * NCH + ch) * 25 * COUT) * 8;
#pragma unroll 1
        for (int ky = 0; ky < 5; ky++) {
            __syncthreads();
            for (int i = tid; i < 5 * COUT * 8; i += 256)
                wt[i] = wcb[(size_t)ky * 5 * COUT * 8 + i];
            __syncthreads();
#pragma unroll
            for (int kx = 0; kx < 5; kx++) {
                int p = (yin + ky * DIL) * PXP + xh * 16 + gid + kx * DIL;
                uint2 Ah0 = patch[p * 8 + tg];
                uint2 Ah1 = patch[(p + 8) * 8 + tg];
                uint2 Al0 = patch[p * 8 + 4 + tg];
                uint2 Al1 = patch[(p + 8) * 8 + 4 + tg];
#pragma unroll
                for (int nt = 0; nt < NT; nt++) {
                    int co = nt * 8 + gid;
                    uint2 Bh = wt[(kx * COUT + co) * 8 + tg];
                    uint2 Bl = wt[(kx * COUT + co) * 8 + 4 + tg];
                    mma_s8(acch[nt], Ah0.x, Ah1.x, Ah0.y, Ah1.y, Bh.x, Bh.y);
                    mma_s8(accc[nt], Al0.x, Al1.x, Al0.y, Al1.y, Bh.x, Bh.y);
                    mma_s8(accc[nt], Ah0.x, Ah1.x, Ah0.y, Ah1.y, Bl.x, Bl.y);
                }
            }
        }
    }

    int gy = by0 + yin, gx = bx0 + xh * 16 + gid;
#pragma unroll
    for (int nt = 0; nt < NT; nt++) {
        int co = nt * 8 + 2 * tg;
        float s0 = sAB[co], s1 = sAB[co + 1];
        __half* o = out + ((size_t)(b * COUT + co) * H + gy) * H;
        o[gx] = __float2half(s0 * fmaf((float)accc[nt][0], 0.0078125f, (float)acch[nt][0]));
        o[(size_t)H * H + gx] =
            __float2half(s1 * fmaf((float)accc[nt][1], 0.0078125f, (float)acch[nt][1]));
        o[gx + 8] = __float2half(s0 * fmaf((float)accc[nt][2], 0.0078125f, (float)acch[nt][2]));
        o[(size_t)H * H + gx + 8] =
            __float2half(s1 * fmaf((float)accc[nt][3], 0.0078125f, (float)acch[nt][3]));
    }
}

// ---------------- avgpool (raw mean) + bn2 stats + min/max (fp16 in/out) ----------------
__global__ void avgpool_stats_kernel(const __half* __restrict__ in, __half* __restrict__ out,
                                     float* __restrict__ st, unsigned* __restrict__ mm) {
    int idx = blockIdx.x * 256 + threadIdx.x;
    int x = idx & 127;
    int y = (idx >> 7) & 127;
    int bc = idx >> 14;
    const __half* p = in + ((size_t)bc * 256 + 2 * y) * 256 + 2 * x;
    float v0 = __half2float(p[0]), v1 = __half2float(p[1]);
    float v2 = __half2float(p[256]), v3 = __half2float(p[257]);
    float m = (v0 + v1 + v2 + v3) * 0.25f;
    out[idx] = __float2half(m);
    float s = v0 + v1 + v2 + v3;
    float q = v0 * v0 + v1 * v1 + v2 * v2 + v3 * v3;
    __shared__ float ss[256], sq[256], smn[256], smx[256];
    ss[threadIdx.x] = s;
    sq[threadIdx.x] = q;
    smn[threadIdx.x] = m;
    smx[threadIdx.x] = m;
    __syncthreads();
    for (int stp = 128; stp > 0; stp >>= 1) {
        if (threadIdx.x < stp) {
            ss[threadIdx.x] += ss[threadIdx.x + stp];
            sq[threadIdx.x] += sq[threadIdx.x + stp];
            smn[threadIdx.x] = fminf(smn[threadIdx.x], smn[threadIdx.x + stp]);
            smx[threadIdx.x] = fmaxf(smx[threadIdx.x], smx[threadIdx.x + stp]);
        }
        __syncthreads();
    }
    if (threadIdx.x == 0) {
        atomicAdd(st + bc * 2, ss[0]);
        atomicAdd(st + bc * 2 + 1, sq[0]);
        atomicMin(mm + bc * 2, fkey(smn[0]));
        atomicMax(mm + bc * 2 + 1, fkey(smx[0]));
    }
}

// ---------------- 1x1 conv (fp16 in) + bilinear residual ----------------
__global__ __launch_bounds__(256) void conv1x1_kernel(const __half* __restrict__ in,
                                                      const float* __restrict__ aff,
                                                      const float* __restrict__ wts,
                                                      float* __restrict__ out) {
    int b = blockIdx.y;
    int p = blockIdx.x * 256 + threadIdx.x;
    __shared__ float wsh[4][64];
    __shared__ float sc[64], bi[64];
    int tid = threadIdx.x;
    wsh[tid >> 6][tid & 63] = wts[b * 256 + tid];
    if (tid < 64) {
        sc[tid] = aff[(b * 64 + tid) * 2];
        bi[tid] = aff[(b * 64 + tid) * 2 + 1];
    }
    __syncthreads();
    float acc[4] = {0.f, 0.f, 0.f, 0.f};
    const __half* pin = in + (size_t)b * 64 * 16384 + p;
#pragma unroll 8
    for (int ci = 0; ci < 64; ci++) {
        float v = fmaf(__half2float(pin[(size_t)ci * 16384]), sc[ci], bi[ci]);
#pragma unroll
        for (int co = 0; co < 4; co++) acc[co] = fmaf(v, wsh[co][ci], acc[co]);
    }
#pragma unroll
    for (int co = 0; co < 4; co++) out[((size_t)b * 4 + co) * 16384 + p] = acc[co];
}

__global__ void up_add_kernel(const float* __restrict__ in, const float* __restrict__ x,
                              float* __restrict__ out) {
    int idx = blockIdx.x * 256 + threadIdx.x;
    if (idx >= 16 * 4 * 256 * 256) return;
    int ox = idx & 255;
    int oy = (idx >> 8) & 255;
    int bc = idx >> 16;
    const float r = (float)(127.0 / 255.0);
    float px = ox * r, py = oy * r;
    int x0 = (int)px, y0 = (int)py;
    float fx = px - x0, fy = py - y0;
    int x1 = min(x0 + 1, 127), y1 = min(y0 + 1, 127);
    const float* p = in + (size_t)bc * 16384;
    float v00 = p[y0 * 128 + x0], v01 = p[y0 * 128 + x1];
    float v10 = p[y1 * 128 + x0], v11 = p[y1 * 128 + x1];
    float v0 = v00 * (1.f - fx) + v01 * fx;
    float v1 = v10 * (1.f - fx) + v11 * fx;
    out[idx] = v0 * (1.f - fy) + v1 * fy + x[idx];
}

// ---------------- host-side smem size mirrors ----------------
static int i8_smem(int COUT, int DIL) {
    int R = 2 * DIL;
    int NPIX = (32 + 2 * R) * (4 + 2 * R);
    return (NPIX * 8 + 5 * COUT * 8) * 8 + COUT * 4;
}
static int i8p_smem(int COUT, int DIL) {
    int R = 2 * DIL;
    int NPIX = (32 + 2 * R) * (4 + 2 * R);
    return NPIX * 32 + 13 * COUT * 64 + COUT * 4;
}

// ---------------- launch ----------------
extern "C" void kernel_launch(void* const* d_in, const int* in_sizes, int n_in,
                              void* d_out, int out_size) {
    const float* x = (const float*)d_in[0];
    const int* action = (const int*)d_in[1];
    const float* w[7];
    const float* wb[7];
    for (int i = 0; i < 7; i++) {
        w[i] = (const float*)d_in[2 + 2 * i];
        wb[i] = (const float*)d_in[3 + 2 * i];
    }
    const float* bns[7];
    const float* bnb[7];
    for (int i = 0; i < 7; i++) {
        bns[i] = (const float*)d_in[16 + 2 * i];
        bnb[i] = (const float*)d_in[17 + 2 * i];
    }

    uint2 *q1, *q2, *q3, *q4, *q5, *q6, *qa1;
    uint4 *qa2, *qa3, *qa4, *qa5, *qa6;
    float *k7, *sb1, *sb2, *sb3, *sb4, *sb5, *sb6;
    unsigned *sa1, *sa2, *sa3, *sa4, *sa5, *sa6, *mm3;
    __half *t1, *t2, *t3, *t4, *t5, *t6, *t7;
    float *t8, *aff, *st2;
    cudaGetSymbolAddress((void**)&q1, g_q1);
    cudaGetSymbolAddress((void**)&q2, g_q2);
    cudaGetSymbolAddress((void**)&q3, g_q3);
    cudaGetSymbolAddress((void**)&q4, g_q4);
    cudaGetSymbolAddress((void**)&q5, g_q5);
    cudaGetSymbolAddress((void**)&q6, g_q6);
    cudaGetSymbolAddress((void**)&qa1, g_qa1);
    cudaGetSymbolAddress((void**)&qa2, g_qa2);
    cudaGetSymbolAddress((void**)&qa3, g_qa3);
    cudaGetSymbolAddress((void**)&qa4, g_qa4);
    cudaGetSymbolAddress((void**)&qa5, g_qa5);
    cudaGetSymbolAddress((void**)&qa6, g_qa6);
    cudaGetSymbolAddress((void**)&sb1, g_sb1);
    cudaGetSymbolAddress((void**)&sb2, g_sb2);
    cudaGetSymbolAddress((void**)&sb3, g_sb3);
    cudaGetSymbolAddress((void**)&sb4, g_sb4);
    cudaGetSymbolAddress((void**)&sb5, g_sb5);
    cudaGetSymbolAddress((void**)&sb6, g_sb6);
    cudaGetSymbolAddress((void**)&sa1, g_sa1);
    cudaGetSymbolAddress((void**)&sa2, g_sa2);
    cudaGetSymbolAddress((void**)&sa3, g_sa3);
    cudaGetSymbolAddress((void**)&sa4, g_sa4);
    cudaGetSymbolAddress((void**)&sa5, g_sa5);
    cudaGetSymbolAddress((void**)&sa6, g_sa6);
    cudaGetSymbolAddress((void**)&mm3, g_mm3);
    cudaGetSymbolAddress((void**)&k7, g_k7);
    cudaGetSymbolAddress((void**)&t1, g_t1);
    cudaGetSymbolAddress((void**)&t2, g_t2);
    cudaGetSymbolAddress((void**)&t3, g_t3);
    cudaGetSymbolAddress((void**)&t4, g_t4);
    cudaGetSymbolAddress((void**)&t5, g_t5);
    cudaGetSymbolAddress((void**)&t6, g_t6);
    cudaGetSymbolAddress((void**)&t7, g_t7);
    cudaGetSymbolAddress((void**)&t8, g_t8);
    cudaGetSymbolAddress((void**)&aff, g_aff);
    cudaGetSymbolAddress((void**)&st2, g_st2);

    const int AOFF = 16 * 64 * 2;

    cudaFuncSetAttribute(conv_i8p_kernel<16, 256, 1>, cudaFuncAttributeMaxDynamicSharedMemorySize,
                         i8p_smem(16, 1));
    cudaFuncSetAttribute(conv_i8p_kernel<32, 128, 2>, cudaFuncAttributeMaxDynamicSharedMemorySize,
                         i8p_smem(32, 2));
    cudaFuncSetAttribute(conv_i8_kernel<32, 32, 128, 1>,
                         cudaFuncAttributeMaxDynamicSharedMemorySize, i8_smem(32, 1));
    cudaFuncSetAttribute(conv_i8_kernel<32, 64, 128, 2>,
                         cudaFuncAttributeMaxDynamicSharedMemorySize, i8_smem(64, 2));
    cudaFuncSetAttribute(conv_i8_kernel<64, 64, 128, 1>,
                         cudaFuncAttributeMaxDynamicSharedMemorySize, i8_smem(64, 1));

    // init + weight amax/quant
    init_kernel<<<16, 256>>>(st2, mm3, sa1, sa2, sa3, sa4, sa5, sa6, w[6], wb[6], action, k7);
    gi8_amax_kernel<<<16 * 16, 256>>>(w[0], wb[0], action, sb1, 4, 16);
    gi8_amax_kernel<<<16 * 16, 256>>>(w[1], wb[1], action, sb2, 16, 16);
    gi8_amax_kernel<<<16 * 32, 256>>>(w[2], wb[2], action, sb3, 16, 32);
    gi8_amax_kernel<<<16 * 32, 256>>>(w[3], wb[3], action, sb4, 32, 32);
    gi8_amax_kernel<<<16 * 64, 256>>>(w[4], wb[4], action, sb5, 32, 64);
    gi8_amax_kernel<<<16 * 64, 256>>>(w[5], wb[5], action, sb6, 64, 64);
    gi8c1_quant_kernel<<<32, 256>>>(w[0], wb[0], action, sb1, q1);
    gi8p_quant_kernel<<<104, 256>>>(w[1], wb[1], action, sb2, q2, 16);
    gi8p_quant_kernel<<<208, 256>>>(w[2], wb[2], action, sb3, q3, 32);
    gi8_quant_kernel<<<400, 256>>>(w[3], wb[3], action, sb4, q4, 32, 32);
    gi8_quant_kernel<<<800, 256>>>(w[4], wb[4], action, sb5, q5, 32, 64);
    gi8_quant_kernel<<<1600, 256>>>(w[5], wb[5], action, sb6, q6, 64, 64);
    // bn0 stats + amax on x, quantize x
    stats_amax_kernel<float, 65536><<<16 * 4, 256>>>(x, bns[0], bnb[0], aff + 0 * AOFF, 4, sa1, 0);
    quant_act4_kernel<<<4096, 256>>>(x, aff + 0 * AOFF, sa1, qa1);
    // conv1 (int8x2)
    conv1_i8_kernel<<<dim3(8, 32, 16), 256>>>(qa1, q1, sb1, sa1, t1);
    // bn1 stats + amax -> conv2
    stats_amax_kernel<__half, 65536>
        <<<16 * 16, 256>>>(t1, bns[1], bnb[1], aff + 1 * AOFF, 16, sa2, 1);
    quant_act16_kernel<<<4096, 256>>>(t1, aff + 1 * AOFF, sa2, qa2, 16, 1);
    conv_i8p_kernel<16, 256, 1>
        <<<dim3(8, 64, 16), 256, i8p_smem(16, 1)>>>(qa2, q2, sb2, sa2, t2);
    // avgpool + bn2 stats + min/max
    avgpool_stats_kernel<<<16384, 256>>>(t2, t3, st2, mm3);
    fin3_kernel<<<1, 256>>>(st2, mm3, bns[2], bnb[2], aff + 2 * AOFF, sa3);
    quant_act16_kernel<<<1024, 256>>>(t3, aff + 2 * AOFF, sa3, qa3, 14, 0);
    conv_i8p_kernel<32, 128, 2>
        <<<dim3(4, 32, 16), 256, i8p_smem(32, 2)>>>(qa3, q3, sb3, sa3, t4);
    // bn3 + conv4
    stats_amax_kernel<__half, 16384>
        <<<16 * 32, 256>>>(t4, bns[3], bnb[3], aff + 3 * AOFF, 32, sa4, 1);
    quant_act_kernel<<<1024, 256>>>(t4, aff + 3 * AOFF, sa4, qa4, 1, 1);
    conv_i8_kernel<32, 32, 128, 1>
        <<<dim3(4, 32, 16), 256, i8_smem(32, 1)>>>(qa4, q4, sb4, sa4, t5);
    // bn4 + conv5
    stats_amax_kernel<__half, 16384>
        <<<16 * 32, 256>>>(t5, bns[4], bnb[4], aff + 4 * AOFF, 32, sa5, 0);
    quant_act_kernel<<<1024, 256>>>(t5, aff + 4 * AOFF, sa5, qa5, 1, 0);
    conv_i8_kernel<32, 64, 128, 2>
        <<<dim3(4, 32, 16), 256, i8_smem(64, 2)>>>(qa5, q5, sb5, sa5, t6);
    // bn5 + conv6
    stats_amax_kernel<__half, 16384>
        <<<16 * 64, 256>>>(t6, bns[5], bnb[5], aff + 5 * AOFF, 64, sa6, 1);
    quant_act_kernel<<<2048, 256>>>(t6, aff + 5 * AOFF, sa6, qa6, 2, 1);
    conv_i8_kernel<64, 64, 128, 1>
        <<<dim3(4, 32, 16), 256, i8_smem(64, 1)>>>(qa6, q6, sb6, sa6, t7);
    // bn6, conv7, upsample+residual
    stats_kernel<__half, 16384><<<16 * 64, 256>>>(t7, bns[6], bnb[6], aff + 6 * AOFF, 64);
    conv1x1_kernel<<<dim3(64, 16), 256>>>(t7, aff + 6 * AOFF, k7, t8);
    up_add_kernel<<<(16 * 4 * 256 * 256 + 255) / 256, 256>>>(t8, x, (float*)d_out);
}